// round 10
// baseline (speedup 1.0000x reference)
#include <cuda_runtime.h>
#include <cuda_bf16.h>
#include <cuda_fp16.h>
#include <math.h>
#include <stdint.h>

#define NB 4
#define NN 50000
#define NT (NB*NN)
#define H4 128
#define RF 64
#define CH 98
#define CHSZ 512

#define ALPHA 0.4204482076268573f   /* 32^-0.25 */
#define RATIO 0.125f                /* 1/sqrt(64) */
#define EPSRF 1e-6f
#define EPSLN 1e-5f

/* ------------------------------ scratch ------------------------------ */
__device__ float  g_inp[(size_t)NT*32];      /* conv output (h0 cols 0..31) */
__device__ int    g_idx[NT];                 /* packed ti*8+wk per node */
__device__ float  g_h [(size_t)NT*H4];
__device__ __half g_vh[(size_t)NT*H4];
__device__ __half g_qh[(size_t)NT*RF];
__device__ float  g_dash2[(size_t)NT*RF];
__device__ float  g_diag2[NT];
__device__ __half g_kh[(size_t)NT*RF];
__device__ int    g_mx[NB];
__device__ float  g_part [(size_t)NB*CH*RF*H4];
__device__ float  g_kpart[(size_t)NB*CH*RF];
__device__ float  g_v2x[(size_t)NB*RF*H4];
__device__ float  g_ksum[NB*RF];
/* precomputed LUTs */
__device__ float  g_a1n[(size_t)NN*32], g_a2n[(size_t)NN*32];
__device__ float  g_d1n[(size_t)NN*64], g_d2n[(size_t)NN*64];
__device__ float  g_a1t[288*32], g_a2t[288*32];
__device__ float  g_d1t[288*64], g_d2t[288*64];
__device__ float  g_a1w[7*32],  g_a2w[7*32];
__device__ float  g_d1w[7*64],  g_d2w[7*64];
__device__ float  g_a1b[32],    g_a2b[32];
__device__ float  g_d1b[64],    g_d2b[64];

/* ------------------------------ helpers ------------------------------ */
__device__ __forceinline__ float warpSum(float v){
    #pragma unroll
    for (int o=16;o;o>>=1) v += __shfl_xor_sync(0xffffffffu, v, o);
    return v;
}
__device__ __forceinline__ float warpMax(float v){
    #pragma unroll
    for (int o=16;o;o>>=1) v = fmaxf(v, __shfl_xor_sync(0xffffffffu, v, o));
    return v;
}
__device__ __forceinline__ int f2ord(float f){
    int i = __float_as_int(f);
    return (i >= 0) ? i : (i ^ 0x7FFFFFFF);
}
__device__ __forceinline__ float ord2f(int i){
    return __int_as_float((i >= 0) ? i : (i ^ 0x7FFFFFFF));
}

/* --------------------- mma.sync helpers ------------------------------ */
__device__ __forceinline__ uint32_t smem_u32(const void* p){
    uint32_t a;
    asm("{ .reg .u64 t; cvta.to.shared.u64 t, %1; cvt.u32.u64 %0, t; }"
        : "=r"(a) : "l"(p));
    return a;
}
__device__ __forceinline__ void ldsm_x4(uint32_t* r, uint32_t addr){
    asm volatile("ldmatrix.sync.aligned.m8n8.x4.shared.b16 {%0,%1,%2,%3}, [%4];"
        : "=r"(r[0]), "=r"(r[1]), "=r"(r[2]), "=r"(r[3]) : "r"(addr));
}
__device__ __forceinline__ void mma16816h(float* d, const uint32_t* a, const uint32_t* b){
    asm volatile("mma.sync.aligned.m16n8k16.row.col.f32.f16.f16.f32 "
        "{%0,%1,%2,%3}, {%4,%5,%6,%7}, {%8,%9}, {%0,%1,%2,%3};"
        : "+f"(d[0]), "+f"(d[1]), "+f"(d[2]), "+f"(d[3])
        : "r"(a[0]), "r"(a[1]), "r"(a[2]), "r"(a[3]), "r"(b[0]), "r"(b[1]));
}
__device__ __forceinline__ uint4 pack8_f16(const float* src){
    float4 a = ((const float4*)src)[0];
    float4 b = ((const float4*)src)[1];
    __half2 p0 = __floats2half2_rn(a.x, a.y);
    __half2 p1 = __floats2half2_rn(a.z, a.w);
    __half2 p2 = __floats2half2_rn(b.x, b.y);
    __half2 p3 = __floats2half2_rn(b.z, b.w);
    uint4 w;
    w.x = *reinterpret_cast<uint32_t*>(&p0);
    w.y = *reinterpret_cast<uint32_t*>(&p1);
    w.z = *reinterpret_cast<uint32_t*>(&p2);
    w.w = *reinterpret_cast<uint32_t*>(&p3);
    return w;
}

/* ------------------------------ init --------------------------------- */
__global__ void initmx_k(){
    if (threadIdx.x < NB) g_mx[threadIdx.x] = (int)0x80000000;
}

/* ------------- LUT precompute: time/week/bias (296 entries) ---------- */
__global__ void pre_small_k(const float* __restrict__ time_emb,
                            const float* __restrict__ week_emb,
                            const float* __restrict__ W1, const float* __restrict__ b1,
                            const float* __restrict__ W2, const float* __restrict__ b2,
                            const float* __restrict__ proj)
{
    __shared__ float sT1[32*32], sU1[32*32], sT2[32*32], sU2[32*32];
    __shared__ float sprojT[32*64];
    __shared__ float sv[8][32], snv[8][32];
    int tid = threadIdx.x;
    for (int t=tid; t<1024; t+=256){
        int h=t>>5, d=t&31;
        sT1[d*32+h] = W1[h*96 + 32 + d];
        sU1[d*32+h] = W1[h*96 + 64 + d];
        sT2[d*32+h] = W2[h*96 + 32 + d];
        sU2[d*32+h] = W2[h*96 + 64 + d];
    }
    for (int t=tid; t<2048; t+=256){ int m=t>>5, d=t&31; sprojT[d*64+m] = proj[m*32+d]; }
    __syncthreads();

    int w = tid>>5, l = tid&31;
    int e = blockIdx.x*8 + w;
    if (e >= 296) return;

    float a1, a2;
    float *A1, *A2, *D1, *D2;
    if (e < 288){
        sv[w][l] = time_emb[e*32 + l]; __syncwarp();
        a1 = 0.f; a2 = 0.f;
        #pragma unroll
        for (int d=0; d<32; d++){
            float v = sv[w][d];
            a1 = fmaf(sT1[d*32+l], v, a1);
            a2 = fmaf(sT2[d*32+l], v, a2);
        }
        A1 = g_a1t + e*32; A2 = g_a2t + e*32;
        D1 = g_d1t + e*64; D2 = g_d2t + e*64;
    } else if (e < 295){
        int k = e - 288;
        sv[w][l] = week_emb[k*32 + l]; __syncwarp();
        a1 = 0.f; a2 = 0.f;
        #pragma unroll
        for (int d=0; d<32; d++){
            float v = sv[w][d];
            a1 = fmaf(sU1[d*32+l], v, a1);
            a2 = fmaf(sU2[d*32+l], v, a2);
        }
        A1 = g_a1w + k*32; A2 = g_a2w + k*32;
        D1 = g_d1w + k*64; D2 = g_d2w + k*64;
    } else {
        a1 = b1[l]; a2 = b2[l];
        A1 = g_a1b; A2 = g_a2b; D1 = g_d1b; D2 = g_d2b;
    }
    a1 *= ALPHA; a2 *= ALPHA;
    A1[l] = a1; A2[l] = a2;

    snv[w][l] = a1; __syncwarp();
    float d0=0.f, d1=0.f;
    #pragma unroll
    for (int dd=0; dd<32; dd++){
        float f = snv[w][dd];
        d0 = fmaf(f, sprojT[dd*64+l],    d0);
        d1 = fmaf(f, sprojT[dd*64+32+l], d1);
    }
    D1[l] = d0; D1[32+l] = d1;
    __syncwarp();
    snv[w][l] = a2; __syncwarp();
    d0=0.f; d1=0.f;
    #pragma unroll
    for (int dd=0; dd<32; dd++){
        float f = snv[w][dd];
        d0 = fmaf(f, sprojT[dd*64+l],    d0);
        d1 = fmaf(f, sprojT[dd*64+32+l], d1);
    }
    D2[l] = d0; D2[32+l] = d1;
}

/* ------------- LUT precompute: per-node (50000 entries) -------------- */
__global__ void pre_node_k(const float* __restrict__ node_emb,
                           const float* __restrict__ W1, const float* __restrict__ W2,
                           const float* __restrict__ proj)
{
    __shared__ float sW1T[32*32], sW2T[32*32];
    __shared__ float sprojT[32*64];
    __shared__ float sne[8][32], snv[8][32];
    int tid = threadIdx.x;
    for (int t=tid; t<1024; t+=256){
        int h=t>>5, d=t&31;
        sW1T[d*32+h] = W1[h*96 + d];
        sW2T[d*32+h] = W2[h*96 + d];
    }
    for (int t=tid; t<2048; t+=256){ int m=t>>5, d=t&31; sprojT[d*64+m] = proj[m*32+d]; }
    __syncthreads();

    int w = tid>>5, l = tid&31;
    int n = blockIdx.x*8 + w;

    sne[w][l] = node_emb[n*32 + l]; __syncwarp();
    float a1 = 0.f, a2 = 0.f;
    #pragma unroll
    for (int d=0; d<32; d++){
        float v = sne[w][d];
        a1 = fmaf(sW1T[d*32+l], v, a1);
        a2 = fmaf(sW2T[d*32+l], v, a2);
    }
    a1 *= ALPHA; a2 *= ALPHA;
    g_a1n[(size_t)n*32 + l] = a1;
    g_a2n[(size_t)n*32 + l] = a2;

    snv[w][l] = a1; __syncwarp();
    float d0=0.f, d1=0.f;
    #pragma unroll
    for (int dd=0; dd<32; dd++){
        float f = snv[w][dd];
        d0 = fmaf(f, sprojT[dd*64+l],    d0);
        d1 = fmaf(f, sprojT[dd*64+32+l], d1);
    }
    g_d1n[(size_t)n*64 + l] = d0;
    g_d1n[(size_t)n*64 + 32 + l] = d1;
    __syncwarp();
    snv[w][l] = a2; __syncwarp();
    d0=0.f; d1=0.f;
    #pragma unroll
    for (int dd=0; dd<32; dd++){
        float f = snv[w][dd];
        d0 = fmaf(f, sprojT[dd*64+l],    d0);
        d1 = fmaf(f, sprojT[dd*64+32+l], d1);
    }
    g_d2n[(size_t)n*64 + l] = d0;
    g_d2n[(size_t)n*64 + 32 + l] = d1;
}

/* --------------------------- phase 1 (LUT-based) ---------------------
 * Writes g_inp (32 f32), g_idx, g_qh (fp16), g_dash2, g_diag2, g_mx.
 * NO h0 materialization: ne/te/we reconstructed by consumers.
 */
__global__ void phase1_k(const float* __restrict__ x,
                         const float* __restrict__ Win, const float* __restrict__ bin)
{
    __shared__ float sWinT[36*32];
    __shared__ float sbin[32];
    __shared__ float sxv[8][40];
    __shared__ int   sbmax[NB];

    int tid = threadIdx.x;
    for (int t=tid; t<32*36; t+=256){ int h=t/36, j=t%36; sWinT[j*32+h]=Win[t]; }
    if (tid<32) sbin[tid]=bin[tid];
    if (tid<NB) sbmax[tid] = (int)0x80000000;
    __syncthreads();

    int w = tid>>5, l = tid&31;
    int i = blockIdx.x*8 + w;
    int b = i / NN;
    int n = i - b*NN;

    const float* xr = x + (size_t)i*36;
    sxv[w][l] = xr[l];
    if (l < 4) sxv[w][32+l] = xr[32+l];
    __syncwarp();

    int ti = (int)(sxv[w][34]*288.0f); ti = min(max(ti,0),287);
    int wk = (int)(sxv[w][35]);        wk = min(max(wk,0),6);

    float inp = sbin[l];
    #pragma unroll
    for (int j=0;j<36;j++) inp = fmaf(sWinT[j*32+l], sxv[w][j], inp);

    g_inp[(size_t)i*32 + l] = inp;
    if (l == 0) g_idx[i] = ti*8 + wk;

    /* ---- map 1 (q, fp16 out) ---- */
    float a1 = g_a1n[(size_t)n*32+l] + g_a1t[ti*32+l] + g_a1w[wk*32+l] + g_a1b[l];
    float diag1 = 0.5f * warpSum(a1*a1);
    float d0 = g_d1n[(size_t)n*64+l]    + g_d1t[ti*64+l]    + g_d1w[wk*64+l]    + g_d1b[l];
    float d1 = g_d1n[(size_t)n*64+32+l] + g_d1t[ti*64+32+l] + g_d1w[wk*64+32+l] + g_d1b[32+l];
    float mx1 = warpMax(fmaxf(d0,d1));
    g_qh[(size_t)i*64 + l]      = __float2half(RATIO*(expf(d0 - diag1 - mx1) + EPSRF));
    g_qh[(size_t)i*64 + 32 + l] = __float2half(RATIO*(expf(d1 - diag1 - mx1) + EPSRF));

    /* ---- map 2 (k: needs batch-global max) ---- */
    float a2 = g_a2n[(size_t)n*32+l] + g_a2t[ti*32+l] + g_a2w[wk*32+l] + g_a2b[l];
    float diag2 = 0.5f * warpSum(a2*a2);
    d0 = g_d2n[(size_t)n*64+l]    + g_d2t[ti*64+l]    + g_d2w[wk*64+l]    + g_d2b[l];
    d1 = g_d2n[(size_t)n*64+32+l] + g_d2t[ti*64+32+l] + g_d2w[wk*64+32+l] + g_d2b[32+l];
    g_dash2[(size_t)i*64 + l]      = d0;
    g_dash2[(size_t)i*64 + 32 + l] = d1;
    if (l==0) g_diag2[i] = diag2;
    float mx2 = warpMax(fmaxf(d0,d1));
    if (l==0) atomicMax(&sbmax[b], f2ord(mx2));

    __syncthreads();
    if (tid < NB && sbmax[tid] != (int)0x80000000)
        atomicMax(&g_mx[tid], sbmax[tid]);
}

/* --------------------------- k features (fp16 out) ------------------- */
__global__ void computek_k(){
    int idx = blockIdx.x*256 + threadIdx.x;
    int i = idx >> 6;
    int b = i / NN;
    float mx = ord2f(g_mx[b]);
    float val = RATIO*(expf(g_dash2[idx] - g_diag2[i] - mx) + EPSRF);
    g_kh[idx] = __float2half(val);
}

/* ------------------- ksum partial + final (hoisted) ------------------ */
__global__ void ksump_k(){
    __shared__ float red[4][64];
    int b = blockIdx.y, ch = blockIdx.x;
    int tid = threadIdx.x;
    int m = tid & 63, part = tid >> 6;
    float s = 0.f;
    int nb = ch*CHSZ + part*128;
    #pragma unroll 4
    for (int nn=0; nn<128; nn++){
        int n = nb + nn;
        if (n < NN) s += __half2float(g_kh[((size_t)(b*NN+n))*64 + m]);
    }
    red[part][m] = s;
    __syncthreads();
    if (part == 0){
        float t = red[0][m] + red[1][m] + red[2][m] + red[3][m];
        g_kpart[(size_t)(b*CH+ch)*64 + m] = t;
    }
}

__global__ void ksumr_k(){
    int tid = threadIdx.x;
    int b = tid >> 6, m = tid & 63;
    float s = 0.f;
    for (int ch=0; ch<CH; ch++)
        s += g_kpart[(size_t)(b*CH+ch)*64 + m];
    g_ksum[b*64 + m] = s;
}

/* ------------------------- GLU via mma.sync (fp16) ------------------- */
#define GT_TILES ((NT + 255)/256)
#define G3_SA   0
#define G3_SB   65536
#define G3_SBI  131072
#define G3_SBO  131584
#define G3_TOT  132096

extern __shared__ char gsm2[];

__global__ void __launch_bounds__(512,1)
glu3_k(int lay0,
       const float* __restrict__ node_emb,
       const float* __restrict__ time_emb,
       const float* __restrict__ week_emb,
       const float* __restrict__ wi, const float* __restrict__ bi,
       const float* __restrict__ wo, const float* __restrict__ bo)
{
    char* SA = gsm2 + G3_SA;
    char* SB = gsm2 + G3_SB;
    float* sbi = (float*)(gsm2 + G3_SBI);
    float* sbo = (float*)(gsm2 + G3_SBO);
    int tid = threadIdx.x;

    for (int c = tid; c < 4096; c += 512){
        int n = c >> 4, ch = c & 15;
        const float* src = (n < 128) ? (wi + (size_t)n*128 + ch*8)
                                     : (wo + (size_t)(n-128)*128 + ch*8);
        *reinterpret_cast<uint4*>(SB + n*256 + ((ch ^ (n&7))<<4)) = pack8_f16(src);
    }
    if (tid < 128){ sbi[tid] = bi[tid]; sbo[tid] = bo[tid]; }

    int w = tid>>5, l = tid&31;
    uint32_t saB = smem_u32(SA);
    uint32_t sbB = smem_u32(SB);

    int a_row = (w<<4) + (l & 15);
    int er    = (w<<4) + (l>>2);

    for (int tile = blockIdx.x; tile < GT_TILES; tile += gridDim.x){
        int base = tile << 8;

        for (int c = tid; c < 4096; c += 512){
            int r = c >> 4, ch = c & 15;
            int node = base + r;
            uint4 pw = make_uint4(0,0,0,0);
            if (node < NT){
                const float* src;
                if (lay0){
                    int seg = ch >> 2, off = (ch & 3)*8;
                    if (seg == 0)      src = g_inp + (size_t)node*32 + off;
                    else if (seg == 1){ int nn = node % NN;
                                        src = node_emb + (size_t)nn*32 + off; }
                    else { int iv = g_idx[node];
                           src = (seg == 2) ? time_emb + (iv>>3)*32 + off
                                            : week_emb + (iv&7)*32 + off; }
                } else {
                    src = g_h + (size_t)node*128 + ch*8;
                }
                pw = pack8_f16(src);
            }
            *reinterpret_cast<uint4*>(SA + r*256 + ((ch ^ (r&7))<<4)) = pw;
        }
        __syncthreads();

        uint32_t Af[8][4];
        #pragma unroll
        for (int ks=0; ks<8; ks++){
            int kc = (ks<<1) + (l>>4);
            ldsm_x4(Af[ks], saB + a_row*256 + ((kc ^ (a_row&7))<<4));
        }

        #pragma unroll 1
        for (int nb=0; nb<16; nb++){
            int nrI = (nb<<3) + (l&7);
            int nrO = nrI + 128;
            uint32_t BI[16], BO[16];
            #pragma unroll
            for (int j=0;j<4;j++){
                int kc = (j<<2) + (l>>3);
                ldsm_x4(&BI[j<<2], sbB + nrI*256 + ((kc ^ (nrI&7))<<4));
                ldsm_x4(&BO[j<<2], sbB + nrO*256 + ((kc ^ (nrO&7))<<4));
            }
            float dI[4] = {0.f,0.f,0.f,0.f};
            float dO[4] = {0.f,0.f,0.f,0.f};
            #pragma unroll
            for (int ks=0; ks<8; ks++){
                mma16816h(dI, Af[ks], &BI[ks<<1]);
                mma16816h(dO, Af[ks], &BO[ks<<1]);
            }

            int c0 = (nb<<3) + ((l&3)<<1);
            float bi0 = sbi[c0], bi1 = sbi[c0+1];
            float bo0 = sbo[c0], bo1 = sbo[c0+1];
            int n0 = base + er;
            int n1 = n0 + 8;
            if (n0 < NT){
                float aI0 = dI[0] + bi0, aI1 = dI[1] + bi1;
                float ox = (dO[0] + bo0) / (1.f + expf(-aI0));
                float oy = (dO[1] + bo1) / (1.f + expf(-aI1));
                *reinterpret_cast<__half2*>(g_vh + (size_t)n0*128 + c0) = __floats2half2_rn(ox, oy);
            }
            if (n1 < NT){
                float aI2 = dI[2] + bi0, aI3 = dI[3] + bi1;
                float ox = (dO[2] + bo0) / (1.f + expf(-aI2));
                float oy = (dO[3] + bo1) / (1.f + expf(-aI3));
                *reinterpret_cast<__half2*>(g_vh + (size_t)n1*128 + c0) = __floats2half2_rn(ox, oy);
            }
        }
        __syncthreads();
    }
}

/* --------------- K^T V partials via mma.sync (deterministic) --------- */
#define KT_PAD 40
__global__ void __launch_bounds__(256,1)
kvredmma_k(){
    __shared__ __align__(16) __half SKt[64*KT_PAD];
    __shared__ __align__(16) __half SVt[128*KT_PAD];
    int b = blockIdx.y, ch = blockIdx.x;
    int tid = threadIdx.x, w = tid>>5, l = tid&31;
    uint32_t skB = smem_u32(SKt), svB = smem_u32(SVt);

    float acc[4][2][4];
    #pragma unroll
    for (int mt=0;mt<4;mt++)
        #pragma unroll
        for (int nb=0;nb<2;nb++)
            #pragma unroll
            for (int r=0;r<4;r++) acc[mt][nb][r] = 0.f;

    int nb0 = ch*CHSZ;
    #pragma unroll 1
    for (int c0=0; c0<CHSZ; c0+=32){
        int nbase = nb0 + c0;
        {
            int node = tid & 31, rg = tid >> 5;
            int n = nbase + node;
            if (n < NN){
                const __half2* s2 = (const __half2*)(g_kh + ((size_t)(b*NN+n))*64 + rg*8);
                #pragma unroll
                for (int j=0;j<4;j++){
                    __half2 p = s2[j];
                    SKt[(rg*8 + 2*j  )*KT_PAD + node] = __low2half(p);
                    SKt[(rg*8 + 2*j+1)*KT_PAD + node] = __high2half(p);
                }
            } else {
                #pragma unroll
                for (int j=0;j<4;j++){
                    SKt[(rg*8 + 2*j  )*KT_PAD + node] = __float2half(0.f);
                    SKt[(rg*8 + 2*j+1)*KT_PAD + node] = __float2half(0.f);
                }
            }
        }
        {
            int node = tid & 31, hg = tid >> 5;
            int n = nbase + node;
            if (n < NN){
                const __half2* s2 = (const __half2*)(g_vh + ((size_t)(b*NN+n))*128 + hg*16);
                #pragma unroll
                for (int j=0;j<8;j++){
                    __half2 p = s2[j];
                    SVt[(hg*16 + 2*j  )*KT_PAD + node] = __low2half(p);
                    SVt[(hg*16 + 2*j+1)*KT_PAD + node] = __high2half(p);
                }
            } else {
                #pragma unroll
                for (int j=0;j<8;j++){
                    SVt[(hg*16 + 2*j  )*KT_PAD + node] = __float2half(0.f);
                    SVt[(hg*16 + 2*j+1)*KT_PAD + node] = __float2half(0.f);
                }
            }
        }
        __syncthreads();

        uint32_t Bv[2][4];
        #pragma unroll
        for (int nb=0;nb<2;nb++){
            int row = w*16 + nb*8 + (l&7);
            ldsm_x4(Bv[nb], svB + row*(KT_PAD*2) + ((l>>3)<<4));
        }
        #pragma unroll
        for (int ks=0; ks<2; ks++){
            uint32_t Af[4][4];
            #pragma unroll
            for (int mt=0;mt<4;mt++){
                int row = mt*16 + (l&15);
                ldsm_x4(Af[mt], skB + row*(KT_PAD*2) + (((ks<<1) + (l>>4))<<4));
            }
            #pragma unroll
            for (int mt=0;mt<4;mt++){
                mma16816h(acc[mt][0], Af[mt], &Bv[0][ks<<1]);
                mma16816h(acc[mt][1], Af[mt], &Bv[1][ks<<1]);
            }
        }
        __syncthreads();
    }

    size_t pb = (size_t)(b*CH+ch);
    #pragma unroll
    for (int mt=0;mt<4;mt++){
        #pragma unroll
        for (int nb=0;nb<2;nb++){
            int rf0 = mt*16 + (l>>2);
            int hd = w*16 + nb*8 + 2*(l&3);
            float2 v0 = make_float2(acc[mt][nb][0], acc[mt][nb][1]);
            float2 v1 = make_float2(acc[mt][nb][2], acc[mt][nb][3]);
            *reinterpret_cast<float2*>(&g_part[(pb*64 + rf0    )*128 + hd]) = v0;
            *reinterpret_cast<float2*>(&g_part[(pb*64 + rf0 + 8)*128 + hd]) = v1;
        }
    }
}

__global__ void vred_k(){
    int idx = blockIdx.x*256 + threadIdx.x;
    int b = idx >> 13;
    int rem = idx & 8191;
    int m = rem >> 7, d = rem & 127;
    float s = 0.f;
    for (int ch=0; ch<CH; ch++)
        s += g_part[((size_t)(b*CH+ch)*64 + m)*128 + d];
    g_v2x[((size_t)b*64 + m)*128 + d] = s;
}

/* ------------- attention out + residual + layernorm ------------------ */
__global__ void attn_k(int lay0,
                       const float* __restrict__ node_emb,
                       const float* __restrict__ time_emb,
                       const float* __restrict__ week_emb,
                       const float* __restrict__ lg, const float* __restrict__ lb){
    __shared__ float sv2x[64*128];
    __shared__ float sks[64];
    __shared__ float sg[128], sb[128];

    int b = blockIdx.y;
    int tid = threadIdx.x, w = tid>>5, l = tid&31;
    for (int t=tid; t<8192; t+=256) sv2x[t] = g_v2x[(size_t)b*8192 + t];
    if (tid<64)  sks[tid] = g_ksum[b*64 + tid];
    if (tid<128){ sg[tid] = lg[tid]; sb[tid] = lb[tid]; }
    __syncthreads();

    int nb0 = (blockIdx.x*8 + w)*8;
    float q0[8], q1[8];
    #pragma unroll
    for (int nd=0; nd<8; nd++){
        int n = nb0 + nd;
        if (n < NN){
            size_t i = (size_t)b*NN + n;
            q0[nd] = __half2float(g_qh[i*64 + l]);
            q1[nd] = __half2float(g_qh[i*64 + 32 + l]);
        } else { q0[nd] = 0.f; q1[nd] = 0.f; }
    }

    float4 acc[8]; float o2[8];
    #pragma unroll
    for (int nd=0; nd<8; nd++){ acc[nd]=make_float4(0.f,0.f,0.f,0.f); o2[nd]=0.f; }

    #pragma unroll 4
    for (int m=0; m<32; m++){
        float4 vx = ((float4*)(sv2x + m*128))[l];
        float km = sks[m];
        #pragma unroll
        for (int nd=0; nd<8; nd++){
            float qm = __shfl_sync(0xffffffffu, q0[nd], m);
            acc[nd].x = fmaf(qm, vx.x, acc[nd].x);
            acc[nd].y = fmaf(qm, vx.y, acc[nd].y);
            acc[nd].z = fmaf(qm, vx.z, acc[nd].z);
            acc[nd].w = fmaf(qm, vx.w, acc[nd].w);
            o2[nd]    = fmaf(qm, km, o2[nd]);
        }
    }
    #pragma unroll 4
    for (int m=0; m<32; m++){
        float4 vx = ((float4*)(sv2x + (m+32)*128))[l];
        float km = sks[m+32];
        #pragma unroll
        for (int nd=0; nd<8; nd++){
            float qm = __shfl_sync(0xffffffffu, q1[nd], m);
            acc[nd].x = fmaf(qm, vx.x, acc[nd].x);
            acc[nd].y = fmaf(qm, vx.y, acc[nd].y);
            acc[nd].z = fmaf(qm, vx.z, acc[nd].z);
            acc[nd].w = fmaf(qm, vx.w, acc[nd].w);
            o2[nd]    = fmaf(qm, km, o2[nd]);
        }
    }

    float4 g4 = ((float4*)sg)[l];
    float4 b4 = ((float4*)sb)[l];
    #pragma unroll 1
    for (int nd=0; nd<8; nd++){
        int n = nb0 + nd;
        if (n >= NN) continue;
        size_t i = (size_t)b*NN + n;
        float inv = 1.f / o2[nd];
        float4 res;
        if (lay0){
            int iv = g_idx[i];
            int off = l & 7;
            const float4* p;
            if (l < 8)       p = (const float4*)(g_inp + i*32);
            else if (l < 16) p = (const float4*)(node_emb + (size_t)n*32);
            else if (l < 24) p = (const float4*)(time_emb + (size_t)(iv>>3)*32);
            else             p = (const float4*)(week_emb + (size_t)(iv&7)*32);
            res = p[off];
        } else {
            res = ((const float4*)g_h)[i*32 + l];
        }
        float4 t;
        t.x = fmaf(acc[nd].x, inv, res.x);
        t.y = fmaf(acc[nd].y, inv, res.y);
        t.z = fmaf(acc[nd].z, inv, res.z);
        t.w = fmaf(acc[nd].w, inv, res.w);
        float mu = warpSum(t.x+t.y+t.z+t.w) * (1.f/128.f);
        float dx=t.x-mu, dy=t.y-mu, dz=t.z-mu, dw=t.w-mu;
        float var = warpSum(dx*dx+dy*dy+dz*dz+dw*dw) * (1.f/128.f);
        float rs = rsqrtf(var + EPSLN);
        float4 o;
        o.x = dx*rs*g4.x + b4.x;
        o.y = dy*rs*g4.y + b4.y;
        o.z = dz*rs*g4.z + b4.z;
        o.w = dw*rs*g4.w + b4.w;
        ((float4*)g_h)[i*32 + l] = o;
    }
}

/* -------- relu(concat(h0,h)) @ W_reg.T + b_reg, transposed out ------- */
__global__ void final_k(const float* __restrict__ node_emb,
                        const float* __restrict__ time_emb,
                        const float* __restrict__ week_emb,
                        const float* __restrict__ Wreg, const float* __restrict__ breg,
                        float* __restrict__ out)
{
    __shared__ float sWrT[256*12];
    __shared__ float sbr[12];
    int tid = threadIdx.x;
    for (int t=tid; t<3072; t+=256){ int to=t>>8, j=t&255; sWrT[j*12+to] = Wreg[t]; }
    if (tid<12) sbr[tid] = breg[tid];
    __syncthreads();

    int w = tid>>5, l = tid&31;
    int i = blockIdx.x*8 + w;
    int b = i / NN;
    int n = i - b*NN;
    int iv = g_idx[i];

    float acc[12];
    #pragma unroll
    for (int t=0;t<12;t++) acc[t]=0.f;

    #pragma unroll
    for (int c=0;c<8;c++){
        int j = c*32 + l;
        float vIn;
        if      (c == 0) vIn = g_inp[(size_t)i*32 + l];
        else if (c == 1) vIn = node_emb[(size_t)n*32 + l];
        else if (c == 2) vIn = time_emb[(size_t)(iv>>3)*32 + l];
        else if (c == 3) vIn = week_emb[(size_t)(iv&7)*32 + l];
        else             vIn = g_h[(size_t)i*128 + (j - 128)];
        vIn = fmaxf(vIn, 0.f);
        #pragma unroll
        for (int t=0;t<12;t++) acc[t] = fmaf(vIn, sWrT[j*12+t], acc[t]);
    }
    #pragma unroll
    for (int t=0;t<12;t++) acc[t] = warpSum(acc[t]);
    if (l < 12) out[((size_t)b*12 + l)*NN + n] = acc[l] + sbr[l];
}

/* ------------------------------ launch ------------------------------- */
extern "C" void kernel_launch(void* const* d_in, const int* in_sizes, int n_in,
                              void* d_out, int out_size)
{
    const float* x        = (const float*)d_in[0];
    const float* node_emb = (const float*)d_in[1];
    const float* time_emb = (const float*)d_in[2];
    const float* week_emb = (const float*)d_in[3];
    const float* Win      = (const float*)d_in[4];
    const float* bin      = (const float*)d_in[5];
    const float* W1       = (const float*)d_in[6];
    const float* b1       = (const float*)d_in[7];
    const float* W2       = (const float*)d_in[8];
    const float* b2       = (const float*)d_in[9];
    const float* Wreg     = (const float*)d_in[10];
    const float* breg     = (const float*)d_in[11];
    const float* proj     = (const float*)d_in[12];

    cudaFuncSetAttribute(glu3_k, cudaFuncAttributeMaxDynamicSharedMemorySize, G3_TOT);

    initmx_k<<<1,32>>>();
    pre_small_k<<<37,256>>>(time_emb, week_emb, W1, b1, W2, b2, proj);
    pre_node_k<<<NN/8,256>>>(node_emb, W1, W2, proj);
    phase1_k<<<NT/8,256>>>(x, Win, bin);
    computek_k<<<(NT*64)/256,256>>>();
    ksump_k<<<dim3(CH,NB),256>>>();
    ksumr_k<<<1,256>>>();

    for (int layer=0; layer<2; layer++){
        const float* wi = (const float*)d_in[13 + layer*6 + 0];
        const float* bi = (const float*)d_in[13 + layer*6 + 1];
        const float* wo = (const float*)d_in[13 + layer*6 + 2];
        const float* bo = (const float*)d_in[13 + layer*6 + 3];
        const float* lg = (const float*)d_in[13 + layer*6 + 4];
        const float* lb = (const float*)d_in[13 + layer*6 + 5];

        int lay0 = (layer == 0) ? 1 : 0;

        glu3_k<<<148,512,G3_TOT>>>(lay0, node_emb, time_emb, week_emb,
                                   wi, bi, wo, bo);
        kvredmma_k<<<dim3(CH,NB),256>>>();
        vred_k<<<128,256>>>();
        attn_k<<<dim3((NN+63)/64,NB),256>>>(lay0, node_emb, time_emb, week_emb, lg, lb);
    }

    final_k<<<NT/8,256>>>(node_emb, time_emb, week_emb, Wreg, breg, (float*)d_out);
}

// round 11
// speedup vs baseline: 1.0558x; 1.0558x over previous
#include <cuda_runtime.h>
#include <cuda_bf16.h>
#include <cuda_fp16.h>
#include <math.h>
#include <stdint.h>

#define NB 4
#define NN 50000
#define NT (NB*NN)
#define H4 128
#define RF 64
#define CH 98
#define CHSZ 512

#define ALPHA 0.4204482076268573f   /* 32^-0.25 */
#define RATIO 0.125f                /* 1/sqrt(64) */
#define EPSRF 1e-6f
#define EPSLN 1e-5f

/* ------------------------------ scratch ------------------------------ */
__device__ float  g_h0[(size_t)NT*H4];
__device__ float  g_h [(size_t)NT*H4];
__device__ __half g_vh[(size_t)NT*H4];
__device__ __half g_qh[(size_t)NT*RF];
__device__ float  g_dash2[(size_t)NT*RF];
__device__ float  g_diag2[NT];
__device__ __half g_kh[(size_t)NT*RF];
__device__ int    g_mx[NB];
__device__ float  g_part [(size_t)NB*CH*RF*H4];
__device__ float  g_kpart[(size_t)NB*CH*RF];
__device__ float  g_v2x[(size_t)NB*RF*H4];
__device__ float  g_ksum[NB*RF];
/* precomputed LUTs */
__device__ float  g_a1n[(size_t)NN*32], g_a2n[(size_t)NN*32];
__device__ float  g_d1n[(size_t)NN*64], g_d2n[(size_t)NN*64];
__device__ float  g_a1t[288*32], g_a2t[288*32];
__device__ float  g_d1t[288*64], g_d2t[288*64];
__device__ float  g_a1w[7*32],  g_a2w[7*32];
__device__ float  g_d1w[7*64],  g_d2w[7*64];
__device__ float  g_a1b[32],    g_a2b[32];
__device__ float  g_d1b[64],    g_d2b[64];

/* ------------------------------ helpers ------------------------------ */
__device__ __forceinline__ float warpSum(float v){
    #pragma unroll
    for (int o=16;o;o>>=1) v += __shfl_xor_sync(0xffffffffu, v, o);
    return v;
}
__device__ __forceinline__ float warpMax(float v){
    #pragma unroll
    for (int o=16;o;o>>=1) v = fmaxf(v, __shfl_xor_sync(0xffffffffu, v, o));
    return v;
}
__device__ __forceinline__ int f2ord(float f){
    int i = __float_as_int(f);
    return (i >= 0) ? i : (i ^ 0x7FFFFFFF);
}
__device__ __forceinline__ float ord2f(int i){
    return __int_as_float((i >= 0) ? i : (i ^ 0x7FFFFFFF));
}

/* --------------------- mma.sync helpers ------------------------------ */
__device__ __forceinline__ uint32_t smem_u32(const void* p){
    uint32_t a;
    asm("{ .reg .u64 t; cvta.to.shared.u64 t, %1; cvt.u32.u64 %0, t; }"
        : "=r"(a) : "l"(p));
    return a;
}
__device__ __forceinline__ void ldsm_x4(uint32_t* r, uint32_t addr){
    asm volatile("ldmatrix.sync.aligned.m8n8.x4.shared.b16 {%0,%1,%2,%3}, [%4];"
        : "=r"(r[0]), "=r"(r[1]), "=r"(r[2]), "=r"(r[3]) : "r"(addr));
}
__device__ __forceinline__ void mma16816h(float* d, const uint32_t* a, const uint32_t* b){
    asm volatile("mma.sync.aligned.m16n8k16.row.col.f32.f16.f16.f32 "
        "{%0,%1,%2,%3}, {%4,%5,%6,%7}, {%8,%9}, {%0,%1,%2,%3};"
        : "+f"(d[0]), "+f"(d[1]), "+f"(d[2]), "+f"(d[3])
        : "r"(a[0]), "r"(a[1]), "r"(a[2]), "r"(a[3]), "r"(b[0]), "r"(b[1]));
}
__device__ __forceinline__ uint4 pack8_f16(const float* src){
    float4 a = ((const float4*)src)[0];
    float4 b = ((const float4*)src)[1];
    __half2 p0 = __floats2half2_rn(a.x, a.y);
    __half2 p1 = __floats2half2_rn(a.z, a.w);
    __half2 p2 = __floats2half2_rn(b.x, b.y);
    __half2 p3 = __floats2half2_rn(b.z, b.w);
    uint4 w;
    w.x = *reinterpret_cast<uint32_t*>(&p0);
    w.y = *reinterpret_cast<uint32_t*>(&p1);
    w.z = *reinterpret_cast<uint32_t*>(&p2);
    w.w = *reinterpret_cast<uint32_t*>(&p3);
    return w;
}

/* ------------------------------ init --------------------------------- */
__global__ void initmx_k(){
    if (threadIdx.x < NB) g_mx[threadIdx.x] = (int)0x80000000;
}

/* ------------- LUT precompute: time/week/bias (296 entries) ---------- */
__global__ void pre_small_k(const float* __restrict__ time_emb,
                            const float* __restrict__ week_emb,
                            const float* __restrict__ W1, const float* __restrict__ b1,
                            const float* __restrict__ W2, const float* __restrict__ b2,
                            const float* __restrict__ proj)
{
    __shared__ float sT1[32*32], sU1[32*32], sT2[32*32], sU2[32*32];
    __shared__ float sprojT[32*64];
    __shared__ float sv[8][32], snv[8][32];
    int tid = threadIdx.x;
    for (int t=tid; t<1024; t+=256){
        int h=t>>5, d=t&31;
        sT1[d*32+h] = W1[h*96 + 32 + d];
        sU1[d*32+h] = W1[h*96 + 64 + d];
        sT2[d*32+h] = W2[h*96 + 32 + d];
        sU2[d*32+h] = W2[h*96 + 64 + d];
    }
    for (int t=tid; t<2048; t+=256){ int m=t>>5, d=t&31; sprojT[d*64+m] = proj[m*32+d]; }
    __syncthreads();

    int w = tid>>5, l = tid&31;
    int e = blockIdx.x*8 + w;
    if (e >= 296) return;

    float a1, a2;
    float *A1, *A2, *D1, *D2;
    if (e < 288){
        sv[w][l] = time_emb[e*32 + l]; __syncwarp();
        a1 = 0.f; a2 = 0.f;
        #pragma unroll
        for (int d=0; d<32; d++){
            float v = sv[w][d];
            a1 = fmaf(sT1[d*32+l], v, a1);
            a2 = fmaf(sT2[d*32+l], v, a2);
        }
        A1 = g_a1t + e*32; A2 = g_a2t + e*32;
        D1 = g_d1t + e*64; D2 = g_d2t + e*64;
    } else if (e < 295){
        int k = e - 288;
        sv[w][l] = week_emb[k*32 + l]; __syncwarp();
        a1 = 0.f; a2 = 0.f;
        #pragma unroll
        for (int d=0; d<32; d++){
            float v = sv[w][d];
            a1 = fmaf(sU1[d*32+l], v, a1);
            a2 = fmaf(sU2[d*32+l], v, a2);
        }
        A1 = g_a1w + k*32; A2 = g_a2w + k*32;
        D1 = g_d1w + k*64; D2 = g_d2w + k*64;
    } else {
        a1 = b1[l]; a2 = b2[l];
        A1 = g_a1b; A2 = g_a2b; D1 = g_d1b; D2 = g_d2b;
    }
    a1 *= ALPHA; a2 *= ALPHA;
    A1[l] = a1; A2[l] = a2;

    snv[w][l] = a1; __syncwarp();
    float d0=0.f, d1=0.f;
    #pragma unroll
    for (int dd=0; dd<32; dd++){
        float f = snv[w][dd];
        d0 = fmaf(f, sprojT[dd*64+l],    d0);
        d1 = fmaf(f, sprojT[dd*64+32+l], d1);
    }
    D1[l] = d0; D1[32+l] = d1;
    __syncwarp();
    snv[w][l] = a2; __syncwarp();
    d0=0.f; d1=0.f;
    #pragma unroll
    for (int dd=0; dd<32; dd++){
        float f = snv[w][dd];
        d0 = fmaf(f, sprojT[dd*64+l],    d0);
        d1 = fmaf(f, sprojT[dd*64+32+l], d1);
    }
    D2[l] = d0; D2[32+l] = d1;
}

/* ------------- LUT precompute: per-node (50000 entries) -------------- */
__global__ void pre_node_k(const float* __restrict__ node_emb,
                           const float* __restrict__ W1, const float* __restrict__ W2,
                           const float* __restrict__ proj)
{
    __shared__ float sW1T[32*32], sW2T[32*32];
    __shared__ float sprojT[32*64];
    __shared__ float sne[8][32], snv[8][32];
    int tid = threadIdx.x;
    for (int t=tid; t<1024; t+=256){
        int h=t>>5, d=t&31;
        sW1T[d*32+h] = W1[h*96 + d];
        sW2T[d*32+h] = W2[h*96 + d];
    }
    for (int t=tid; t<2048; t+=256){ int m=t>>5, d=t&31; sprojT[d*64+m] = proj[m*32+d]; }
    __syncthreads();

    int w = tid>>5, l = tid&31;
    int n = blockIdx.x*8 + w;

    sne[w][l] = node_emb[n*32 + l]; __syncwarp();
    float a1 = 0.f, a2 = 0.f;
    #pragma unroll
    for (int d=0; d<32; d++){
        float v = sne[w][d];
        a1 = fmaf(sW1T[d*32+l], v, a1);
        a2 = fmaf(sW2T[d*32+l], v, a2);
    }
    a1 *= ALPHA; a2 *= ALPHA;
    g_a1n[(size_t)n*32 + l] = a1;
    g_a2n[(size_t)n*32 + l] = a2;

    snv[w][l] = a1; __syncwarp();
    float d0=0.f, d1=0.f;
    #pragma unroll
    for (int dd=0; dd<32; dd++){
        float f = snv[w][dd];
        d0 = fmaf(f, sprojT[dd*64+l],    d0);
        d1 = fmaf(f, sprojT[dd*64+32+l], d1);
    }
    g_d1n[(size_t)n*64 + l] = d0;
    g_d1n[(size_t)n*64 + 32 + l] = d1;
    __syncwarp();
    snv[w][l] = a2; __syncwarp();
    d0=0.f; d1=0.f;
    #pragma unroll
    for (int dd=0; dd<32; dd++){
        float f = snv[w][dd];
        d0 = fmaf(f, sprojT[dd*64+l],    d0);
        d1 = fmaf(f, sprojT[dd*64+32+l], d1);
    }
    g_d2n[(size_t)n*64 + l] = d0;
    g_d2n[(size_t)n*64 + 32 + l] = d1;
}

/* --------------------------- phase 1 (LUT, 4 nodes/warp) -------------
 * float4-packed Win GEMV shared across 4 nodes; writes full h0,
 * q (fp16), dash2, diag2, batch max.
 */
__global__ void phase1_k(const float* __restrict__ x,
                         const float* __restrict__ node_emb,
                         const float* __restrict__ time_emb,
                         const float* __restrict__ week_emb,
                         const float* __restrict__ Win, const float* __restrict__ bin)
{
    __shared__ float sW4[9*128];       /* float4-packed: [(j/4)*32+l] = Win[l][4j4..] */
    __shared__ float sbin[32];
    __shared__ float sxv[8][160];      /* 4 nodes x 40 floats per warp */
    __shared__ int   sbmax[NB];

    int tid = threadIdx.x;
    for (int t=tid; t<1152; t+=256){
        int h=t/36, j=t%36;
        sW4[(j>>2)*128 + h*4 + (j&3)] = Win[t];
    }
    if (tid<32) sbin[tid]=bin[tid];
    if (tid<NB) sbmax[tid] = (int)0x80000000;
    __syncthreads();

    int w = tid>>5, l = tid&31;
    int i0 = (blockIdx.x*8 + w)*4;     /* 4 consecutive nodes; NN%4==0 -> same batch */
    int b = i0 / NN;

    /* stage x for 4 nodes: 144 contiguous floats, coalesced */
    const float* xr = x + (size_t)i0*36;
    for (int idx=l; idx<144; idx+=32){
        int nd = idx/36, j = idx - nd*36;
        sxv[w][nd*40 + j] = xr[idx];
    }
    __syncwarp();

    /* GEMV: weights loaded once, shared across 4 nodes */
    float inp[4];
    #pragma unroll
    for (int nd=0; nd<4; nd++) inp[nd] = sbin[l];
    #pragma unroll
    for (int j4=0; j4<9; j4++){
        float4 w4 = ((float4*)sW4)[j4*32 + l];
        #pragma unroll
        for (int nd=0; nd<4; nd++){
            float4 x4 = *reinterpret_cast<float4*>(&sxv[w][nd*40 + j4*4]);
            inp[nd] = fmaf(w4.x, x4.x,
                      fmaf(w4.y, x4.y,
                      fmaf(w4.z, x4.z,
                      fmaf(w4.w, x4.w, inp[nd]))));
        }
    }

    float wmax = -1e30f;
    #pragma unroll 1
    for (int nd=0; nd<4; nd++){
        int i = i0 + nd;
        int n = i - b*NN;
        int ti = (int)(sxv[w][nd*40+34]*288.0f); ti = min(max(ti,0),287);
        int wk = (int)(sxv[w][nd*40+35]);        wk = min(max(wk,0),6);

        float ne = node_emb[n*32+l];
        float te = time_emb[ti*32+l];
        float we = week_emb[wk*32+l];
        size_t hb = (size_t)i*128;
        g_h0[hb+l]=inp[nd]; g_h0[hb+32+l]=ne; g_h0[hb+64+l]=te; g_h0[hb+96+l]=we;

        float a1 = g_a1n[(size_t)n*32+l] + g_a1t[ti*32+l] + g_a1w[wk*32+l] + g_a1b[l];
        float diag1 = 0.5f * warpSum(a1*a1);
        float d0 = g_d1n[(size_t)n*64+l]    + g_d1t[ti*64+l]    + g_d1w[wk*64+l]    + g_d1b[l];
        float d1 = g_d1n[(size_t)n*64+32+l] + g_d1t[ti*64+32+l] + g_d1w[wk*64+32+l] + g_d1b[32+l];
        float mx1 = warpMax(fmaxf(d0,d1));
        g_qh[(size_t)i*64 + l]      = __float2half(RATIO*(expf(d0 - diag1 - mx1) + EPSRF));
        g_qh[(size_t)i*64 + 32 + l] = __float2half(RATIO*(expf(d1 - diag1 - mx1) + EPSRF));

        float a2 = g_a2n[(size_t)n*32+l] + g_a2t[ti*32+l] + g_a2w[wk*32+l] + g_a2b[l];
        float diag2 = 0.5f * warpSum(a2*a2);
        d0 = g_d2n[(size_t)n*64+l]    + g_d2t[ti*64+l]    + g_d2w[wk*64+l]    + g_d2b[l];
        d1 = g_d2n[(size_t)n*64+32+l] + g_d2t[ti*64+32+l] + g_d2w[wk*64+32+l] + g_d2b[32+l];
        g_dash2[(size_t)i*64 + l]      = d0;
        g_dash2[(size_t)i*64 + 32 + l] = d1;
        if (l==0) g_diag2[i] = diag2;
        wmax = fmaxf(wmax, fmaxf(d0,d1));
    }

    float m = warpMax(wmax);
    if (l==0) atomicMax(&sbmax[b], f2ord(m));

    __syncthreads();
    if (tid < NB && sbmax[tid] != (int)0x80000000)
        atomicMax(&g_mx[tid], sbmax[tid]);
}

/* --------------------------- k features (fp16 out) ------------------- */
__global__ void computek_k(){
    int idx = blockIdx.x*256 + threadIdx.x;
    int i = idx >> 6;
    int b = i / NN;
    float mx = ord2f(g_mx[b]);
    float val = RATIO*(expf(g_dash2[idx] - g_diag2[i] - mx) + EPSRF);
    g_kh[idx] = __float2half(val);
}

/* ------------------- ksum partial + final (hoisted) ------------------ */
__global__ void ksump_k(){
    __shared__ float red[4][64];
    int b = blockIdx.y, ch = blockIdx.x;
    int tid = threadIdx.x;
    int m = tid & 63, part = tid >> 6;
    float s = 0.f;
    int nb = ch*CHSZ + part*128;
    #pragma unroll 4
    for (int nn=0; nn<128; nn++){
        int n = nb + nn;
        if (n < NN) s += __half2float(g_kh[((size_t)(b*NN+n))*64 + m]);
    }
    red[part][m] = s;
    __syncthreads();
    if (part == 0){
        float t = red[0][m] + red[1][m] + red[2][m] + red[3][m];
        g_kpart[(size_t)(b*CH+ch)*64 + m] = t;
    }
}

__global__ void ksumr_k(){
    int tid = threadIdx.x;
    int b = tid >> 6, m = tid & 63;
    float s = 0.f;
    for (int ch=0; ch<CH; ch++)
        s += g_kpart[(size_t)(b*CH+ch)*64 + m];
    g_ksum[b*64 + m] = s;
}

/* ------------------------- GLU via mma.sync (fp16) ------------------- */
#define GT_TILES ((NT + 255)/256)
#define G3_SA   0
#define G3_SB   65536
#define G3_SBI  131072
#define G3_SBO  131584
#define G3_TOT  132096

extern __shared__ char gsm2[];

__global__ void __launch_bounds__(512,1)
glu3_k(const float* __restrict__ hin,
       const float* __restrict__ wi, const float* __restrict__ bi,
       const float* __restrict__ wo, const float* __restrict__ bo)
{
    char* SA = gsm2 + G3_SA;
    char* SB = gsm2 + G3_SB;
    float* sbi = (float*)(gsm2 + G3_SBI);
    float* sbo = (float*)(gsm2 + G3_SBO);
    int tid = threadIdx.x;

    for (int c = tid; c < 4096; c += 512){
        int n = c >> 4, ch = c & 15;
        const float* src = (n < 128) ? (wi + (size_t)n*128 + ch*8)
                                     : (wo + (size_t)(n-128)*128 + ch*8);
        *reinterpret_cast<uint4*>(SB + n*256 + ((ch ^ (n&7))<<4)) = pack8_f16(src);
    }
    if (tid < 128){ sbi[tid] = bi[tid]; sbo[tid] = bo[tid]; }

    int w = tid>>5, l = tid&31;
    uint32_t saB = smem_u32(SA);
    uint32_t sbB = smem_u32(SB);

    int a_row = (w<<4) + (l & 15);
    int er    = (w<<4) + (l>>2);

    for (int tile = blockIdx.x; tile < GT_TILES; tile += gridDim.x){
        int base = tile << 8;

        for (int c = tid; c < 4096; c += 512){
            int r = c >> 4, ch = c & 15;
            uint4 pw = make_uint4(0,0,0,0);
            if (base + r < NT)
                pw = pack8_f16(hin + (size_t)(base + r)*128 + ch*8);
            *reinterpret_cast<uint4*>(SA + r*256 + ((ch ^ (r&7))<<4)) = pw;
        }
        __syncthreads();

        uint32_t Af[8][4];
        #pragma unroll
        for (int ks=0; ks<8; ks++){
            int kc = (ks<<1) + (l>>4);
            ldsm_x4(Af[ks], saB + a_row*256 + ((kc ^ (a_row&7))<<4));
        }

        #pragma unroll 1
        for (int nb=0; nb<16; nb++){
            int nrI = (nb<<3) + (l&7);
            int nrO = nrI + 128;
            uint32_t BI[16], BO[16];
            #pragma unroll
            for (int j=0;j<4;j++){
                int kc = (j<<2) + (l>>3);
                ldsm_x4(&BI[j<<2], sbB + nrI*256 + ((kc ^ (nrI&7))<<4));
                ldsm_x4(&BO[j<<2], sbB + nrO*256 + ((kc ^ (nrO&7))<<4));
            }
            float dI[4] = {0.f,0.f,0.f,0.f};
            float dO[4] = {0.f,0.f,0.f,0.f};
            #pragma unroll
            for (int ks=0; ks<8; ks++){
                mma16816h(dI, Af[ks], &BI[ks<<1]);
                mma16816h(dO, Af[ks], &BO[ks<<1]);
            }

            int c0 = (nb<<3) + ((l&3)<<1);
            float bi0 = sbi[c0], bi1 = sbi[c0+1];
            float bo0 = sbo[c0], bo1 = sbo[c0+1];
            int n0 = base + er;
            int n1 = n0 + 8;
            if (n0 < NT){
                float aI0 = dI[0] + bi0, aI1 = dI[1] + bi1;
                float ox = (dO[0] + bo0) / (1.f + expf(-aI0));
                float oy = (dO[1] + bo1) / (1.f + expf(-aI1));
                *reinterpret_cast<__half2*>(g_vh + (size_t)n0*128 + c0) = __floats2half2_rn(ox, oy);
            }
            if (n1 < NT){
                float aI2 = dI[2] + bi0, aI3 = dI[3] + bi1;
                float ox = (dO[2] + bo0) / (1.f + expf(-aI2));
                float oy = (dO[3] + bo1) / (1.f + expf(-aI3));
                *reinterpret_cast<__half2*>(g_vh + (size_t)n1*128 + c0) = __floats2half2_rn(ox, oy);
            }
        }
        __syncthreads();
    }
}

/* --------------- K^T V partials via mma.sync (deterministic) --------- */
#define KT_PAD 40
__global__ void __launch_bounds__(256,1)
kvredmma_k(){
    __shared__ __align__(16) __half SKt[64*KT_PAD];
    __shared__ __align__(16) __half SVt[128*KT_PAD];
    int b = blockIdx.y, ch = blockIdx.x;
    int tid = threadIdx.x, w = tid>>5, l = tid&31;
    uint32_t skB = smem_u32(SKt), svB = smem_u32(SVt);

    float acc[4][2][4];
    #pragma unroll
    for (int mt=0;mt<4;mt++)
        #pragma unroll
        for (int nb=0;nb<2;nb++)
            #pragma unroll
            for (int r=0;r<4;r++) acc[mt][nb][r] = 0.f;

    int nb0 = ch*CHSZ;
    #pragma unroll 1
    for (int c0=0; c0<CHSZ; c0+=32){
        int nbase = nb0 + c0;
        {
            int node = tid & 31, rg = tid >> 5;
            int n = nbase + node;
            if (n < NN){
                const __half2* s2 = (const __half2*)(g_kh + ((size_t)(b*NN+n))*64 + rg*8);
                #pragma unroll
                for (int j=0;j<4;j++){
                    __half2 p = s2[j];
                    SKt[(rg*8 + 2*j  )*KT_PAD + node] = __low2half(p);
                    SKt[(rg*8 + 2*j+1)*KT_PAD + node] = __high2half(p);
                }
            } else {
                #pragma unroll
                for (int j=0;j<4;j++){
                    SKt[(rg*8 + 2*j  )*KT_PAD + node] = __float2half(0.f);
                    SKt[(rg*8 + 2*j+1)*KT_PAD + node] = __float2half(0.f);
                }
            }
        }
        {
            int node = tid & 31, hg = tid >> 5;
            int n = nbase + node;
            if (n < NN){
                const __half2* s2 = (const __half2*)(g_vh + ((size_t)(b*NN+n))*128 + hg*16);
                #pragma unroll
                for (int j=0;j<8;j++){
                    __half2 p = s2[j];
                    SVt[(hg*16 + 2*j  )*KT_PAD + node] = __low2half(p);
                    SVt[(hg*16 + 2*j+1)*KT_PAD + node] = __high2half(p);
                }
            } else {
                #pragma unroll
                for (int j=0;j<8;j++){
                    SVt[(hg*16 + 2*j  )*KT_PAD + node] = __float2half(0.f);
                    SVt[(hg*16 + 2*j+1)*KT_PAD + node] = __float2half(0.f);
                }
            }
        }
        __syncthreads();

        uint32_t Bv[2][4];
        #pragma unroll
        for (int nb=0;nb<2;nb++){
            int row = w*16 + nb*8 + (l&7);
            ldsm_x4(Bv[nb], svB + row*(KT_PAD*2) + ((l>>3)<<4));
        }
        #pragma unroll
        for (int ks=0; ks<2; ks++){
            uint32_t Af[4][4];
            #pragma unroll
            for (int mt=0;mt<4;mt++){
                int row = mt*16 + (l&15);
                ldsm_x4(Af[mt], skB + row*(KT_PAD*2) + (((ks<<1) + (l>>4))<<4));
            }
            #pragma unroll
            for (int mt=0;mt<4;mt++){
                mma16816h(acc[mt][0], Af[mt], &Bv[0][ks<<1]);
                mma16816h(acc[mt][1], Af[mt], &Bv[1][ks<<1]);
            }
        }
        __syncthreads();
    }

    size_t pb = (size_t)(b*CH+ch);
    #pragma unroll
    for (int mt=0;mt<4;mt++){
        #pragma unroll
        for (int nb=0;nb<2;nb++){
            int rf0 = mt*16 + (l>>2);
            int hd = w*16 + nb*8 + 2*(l&3);
            float2 v0 = make_float2(acc[mt][nb][0], acc[mt][nb][1]);
            float2 v1 = make_float2(acc[mt][nb][2], acc[mt][nb][3]);
            *reinterpret_cast<float2*>(&g_part[(pb*64 + rf0    )*128 + hd]) = v0;
            *reinterpret_cast<float2*>(&g_part[(pb*64 + rf0 + 8)*128 + hd]) = v1;
        }
    }
}

__global__ void vred_k(){
    int idx = blockIdx.x*256 + threadIdx.x;
    int b = idx >> 13;
    int rem = idx & 8191;
    int m = rem >> 7, d = rem & 127;
    float s = 0.f;
    for (int ch=0; ch<CH; ch++)
        s += g_part[((size_t)(b*CH+ch)*64 + m)*128 + d];
    g_v2x[((size_t)b*64 + m)*128 + d] = s;
}

/* ------------- attention out + residual + layernorm ------------------ */
__global__ void attn_k(const float* __restrict__ res_in,
                       const float* __restrict__ lg, const float* __restrict__ lb){
    __shared__ float sv2x[64*128];
    __shared__ float sks[64];
    __shared__ float sg[128], sb[128];

    int b = blockIdx.y;
    int tid = threadIdx.x, w = tid>>5, l = tid&31;
    for (int t=tid; t<8192; t+=256) sv2x[t] = g_v2x[(size_t)b*8192 + t];
    if (tid<64)  sks[tid] = g_ksum[b*64 + tid];
    if (tid<128){ sg[tid] = lg[tid]; sb[tid] = lb[tid]; }
    __syncthreads();

    int nb0 = (blockIdx.x*8 + w)*8;
    float q0[8], q1[8];
    #pragma unroll
    for (int nd=0; nd<8; nd++){
        int n = nb0 + nd;
        if (n < NN){
            size_t i = (size_t)b*NN + n;
            q0[nd] = __half2float(g_qh[i*64 + l]);
            q1[nd] = __half2float(g_qh[i*64 + 32 + l]);
        } else { q0[nd] = 0.f; q1[nd] = 0.f; }
    }

    float4 acc[8]; float o2[8];
    #pragma unroll
    for (int nd=0; nd<8; nd++){ acc[nd]=make_float4(0.f,0.f,0.f,0.f); o2[nd]=0.f; }

    #pragma unroll 4
    for (int m=0; m<32; m++){
        float4 vx = ((float4*)(sv2x + m*128))[l];
        float km = sks[m];
        #pragma unroll
        for (int nd=0; nd<8; nd++){
            float qm = __shfl_sync(0xffffffffu, q0[nd], m);
            acc[nd].x = fmaf(qm, vx.x, acc[nd].x);
            acc[nd].y = fmaf(qm, vx.y, acc[nd].y);
            acc[nd].z = fmaf(qm, vx.z, acc[nd].z);
            acc[nd].w = fmaf(qm, vx.w, acc[nd].w);
            o2[nd]    = fmaf(qm, km, o2[nd]);
        }
    }
    #pragma unroll 4
    for (int m=0; m<32; m++){
        float4 vx = ((float4*)(sv2x + (m+32)*128))[l];
        float km = sks[m+32];
        #pragma unroll
        for (int nd=0; nd<8; nd++){
            float qm = __shfl_sync(0xffffffffu, q1[nd], m);
            acc[nd].x = fmaf(qm, vx.x, acc[nd].x);
            acc[nd].y = fmaf(qm, vx.y, acc[nd].y);
            acc[nd].z = fmaf(qm, vx.z, acc[nd].z);
            acc[nd].w = fmaf(qm, vx.w, acc[nd].w);
            o2[nd]    = fmaf(qm, km, o2[nd]);
        }
    }

    float4 g4 = ((float4*)sg)[l];
    float4 b4 = ((float4*)sb)[l];
    #pragma unroll 1
    for (int nd=0; nd<8; nd++){
        int n = nb0 + nd;
        if (n >= NN) continue;
        size_t i = (size_t)b*NN + n;
        float inv = 1.f / o2[nd];
        float4 res = ((const float4*)res_in)[i*32 + l];
        float4 t;
        t.x = fmaf(acc[nd].x, inv, res.x);
        t.y = fmaf(acc[nd].y, inv, res.y);
        t.z = fmaf(acc[nd].z, inv, res.z);
        t.w = fmaf(acc[nd].w, inv, res.w);
        float mu = warpSum(t.x+t.y+t.z+t.w) * (1.f/128.f);
        float dx=t.x-mu, dy=t.y-mu, dz=t.z-mu, dw=t.w-mu;
        float var = warpSum(dx*dx+dy*dy+dz*dz+dw*dw) * (1.f/128.f);
        float rs = rsqrtf(var + EPSLN);
        float4 o;
        o.x = dx*rs*g4.x + b4.x;
        o.y = dy*rs*g4.y + b4.y;
        o.z = dz*rs*g4.z + b4.z;
        o.w = dw*rs*g4.w + b4.w;
        ((float4*)g_h)[i*32 + l] = o;
    }
}

/* -------- relu(concat(h0,h)) @ W_reg.T + b_reg, transposed out ------- */
__global__ void final_k(const float* __restrict__ Wreg, const float* __restrict__ breg,
                        float* __restrict__ out)
{
    __shared__ float sWrT[256*12];
    __shared__ float sbr[12];
    int tid = threadIdx.x;
    for (int t=tid; t<3072; t+=256){ int to=t>>8, j=t&255; sWrT[j*12+to] = Wreg[t]; }
    if (tid<12) sbr[tid] = breg[tid];
    __syncthreads();

    int w = tid>>5, l = tid&31;
    int i = blockIdx.x*8 + w;
    int b = i / NN;
    int n = i - b*NN;
    size_t hb = (size_t)i*128;

    float acc[12];
    #pragma unroll
    for (int t=0;t<12;t++) acc[t]=0.f;

    #pragma unroll
    for (int c=0;c<8;c++){
        int j = c*32 + l;
        float vIn = (j < 128) ? g_h0[hb + j] : g_h[hb + j - 128];
        vIn = fmaxf(vIn, 0.f);
        #pragma unroll
        for (int t=0;t<12;t++) acc[t] = fmaf(vIn, sWrT[j*12+t], acc[t]);
    }
    #pragma unroll
    for (int t=0;t<12;t++) acc[t] = warpSum(acc[t]);
    if (l < 12) out[((size_t)b*12 + l)*NN + n] = acc[l] + sbr[l];
}

/* ------------------------------ launch ------------------------------- */
extern "C" void kernel_launch(void* const* d_in, const int* in_sizes, int n_in,
                              void* d_out, int out_size)
{
    const float* x        = (const float*)d_in[0];
    const float* node_emb = (const float*)d_in[1];
    const float* time_emb = (const float*)d_in[2];
    const float* week_emb = (const float*)d_in[3];
    const float* Win      = (const float*)d_in[4];
    const float* bin      = (const float*)d_in[5];
    const float* W1       = (const float*)d_in[6];
    const float* b1       = (const float*)d_in[7];
    const float* W2       = (const float*)d_in[8];
    const float* b2       = (const float*)d_in[9];
    const float* Wreg     = (const float*)d_in[10];
    const float* breg     = (const float*)d_in[11];
    const float* proj     = (const float*)d_in[12];

    cudaFuncSetAttribute(glu3_k, cudaFuncAttributeMaxDynamicSharedMemorySize, G3_TOT);

    float* g_h_ptr;  cudaGetSymbolAddress((void**)&g_h_ptr,  g_h);
    float* g_h0_ptr; cudaGetSymbolAddress((void**)&g_h0_ptr, g_h0);

    initmx_k<<<1,32>>>();
    pre_small_k<<<37,256>>>(time_emb, week_emb, W1, b1, W2, b2, proj);
    pre_node_k<<<NN/8,256>>>(node_emb, W1, W2, proj);
    phase1_k<<<NT/32,256>>>(x, node_emb, time_emb, week_emb, Win, bin);
    computek_k<<<(NT*64)/256,256>>>();
    ksump_k<<<dim3(CH,NB),256>>>();
    ksumr_k<<<1,256>>>();

    for (int layer=0; layer<2; layer++){
        const float* wi = (const float*)d_in[13 + layer*6 + 0];
        const float* bi = (const float*)d_in[13 + layer*6 + 1];
        const float* wo = (const float*)d_in[13 + layer*6 + 2];
        const float* bo = (const float*)d_in[13 + layer*6 + 3];
        const float* lg = (const float*)d_in[13 + layer*6 + 4];
        const float* lb = (const float*)d_in[13 + layer*6 + 5];

        const float* hin = (layer == 0) ? g_h0_ptr : g_h_ptr;

        glu3_k<<<148,512,G3_TOT>>>(hin, wi, bi, wo, bo);
        kvredmma_k<<<dim3(CH,NB),256>>>();
        vred_k<<<128,256>>>();
        attn_k<<<dim3((NN+63)/64,NB),256>>>(hin, lg, lb);
    }

    final_k<<<NT/8,256>>>(Wreg, breg, (float*)d_out);
}

// round 12
// speedup vs baseline: 1.0773x; 1.0203x over previous
#include <cuda_runtime.h>
#include <cuda_bf16.h>
#include <cuda_fp16.h>
#include <math.h>
#include <stdint.h>

#define NB 4
#define NN 50000
#define NT (NB*NN)
#define H4 128
#define RF 64
#define CH 98
#define CHSZ 512

#define ALPHA 0.4204482076268573f   /* 32^-0.25 */
#define RATIO 0.125f                /* 1/sqrt(64) */
#define EPSRF 1e-6f
#define EPSLN 1e-5f

/* ------------------------------ scratch ------------------------------ */
__device__ float  g_h0[(size_t)NT*H4];
__device__ float  g_h [(size_t)NT*H4];
__device__ __half g_vh[(size_t)NT*H4];
__device__ __half g_qh[(size_t)NT*RF];
__device__ float  g_diag2[NT];
__device__ int    g_idx[NT];
__device__ __half g_kh[(size_t)NT*RF];
__device__ int    g_mx[NB];
__device__ float  g_part [(size_t)NB*CH*RF*H4];
__device__ float  g_kpart[(size_t)NB*CH*RF];
__device__ float  g_v2x[(size_t)NB*RF*H4];
__device__ float  g_ksum[NB*RF];
/* precomputed LUTs */
__device__ float  g_a1n[(size_t)NN*32], g_a2n[(size_t)NN*32];
__device__ float  g_d1n[(size_t)NN*64], g_d2n[(size_t)NN*64];
__device__ float  g_a1t[288*32], g_a2t[288*32];
__device__ float  g_d1t[288*64], g_d2t[288*64];
__device__ float  g_a1w[7*32],  g_a2w[7*32];
__device__ float  g_d1w[7*64],  g_d2w[7*64];
__device__ float  g_a1b[32],    g_a2b[32];
__device__ float  g_d1b[64],    g_d2b[64];

/* ------------------------------ helpers ------------------------------ */
__device__ __forceinline__ float warpSum(float v){
    #pragma unroll
    for (int o=16;o;o>>=1) v += __shfl_xor_sync(0xffffffffu, v, o);
    return v;
}
__device__ __forceinline__ float warpMax(float v){
    #pragma unroll
    for (int o=16;o;o>>=1) v = fmaxf(v, __shfl_xor_sync(0xffffffffu, v, o));
    return v;
}
__device__ __forceinline__ int f2ord(float f){
    int i = __float_as_int(f);
    return (i >= 0) ? i : (i ^ 0x7FFFFFFF);
}
__device__ __forceinline__ float ord2f(int i){
    return __int_as_float((i >= 0) ? i : (i ^ 0x7FFFFFFF));
}

/* --------------------- mma.sync helpers ------------------------------ */
__device__ __forceinline__ uint32_t smem_u32(const void* p){
    uint32_t a;
    asm("{ .reg .u64 t; cvta.to.shared.u64 t, %1; cvt.u32.u64 %0, t; }"
        : "=r"(a) : "l"(p));
    return a;
}
__device__ __forceinline__ void ldsm_x4(uint32_t* r, uint32_t addr){
    asm volatile("ldmatrix.sync.aligned.m8n8.x4.shared.b16 {%0,%1,%2,%3}, [%4];"
        : "=r"(r[0]), "=r"(r[1]), "=r"(r[2]), "=r"(r[3]) : "r"(addr));
}
__device__ __forceinline__ void mma16816h(float* d, const uint32_t* a, const uint32_t* b){
    asm volatile("mma.sync.aligned.m16n8k16.row.col.f32.f16.f16.f32 "
        "{%0,%1,%2,%3}, {%4,%5,%6,%7}, {%8,%9}, {%0,%1,%2,%3};"
        : "+f"(d[0]), "+f"(d[1]), "+f"(d[2]), "+f"(d[3])
        : "r"(a[0]), "r"(a[1]), "r"(a[2]), "r"(a[3]), "r"(b[0]), "r"(b[1]));
}
__device__ __forceinline__ uint4 pack8_f16(const float* src){
    float4 a = ((const float4*)src)[0];
    float4 b = ((const float4*)src)[1];
    __half2 p0 = __floats2half2_rn(a.x, a.y);
    __half2 p1 = __floats2half2_rn(a.z, a.w);
    __half2 p2 = __floats2half2_rn(b.x, b.y);
    __half2 p3 = __floats2half2_rn(b.z, b.w);
    uint4 w;
    w.x = *reinterpret_cast<uint32_t*>(&p0);
    w.y = *reinterpret_cast<uint32_t*>(&p1);
    w.z = *reinterpret_cast<uint32_t*>(&p2);
    w.w = *reinterpret_cast<uint32_t*>(&p3);
    return w;
}

/* ------------------------------ init --------------------------------- */
__global__ void initmx_k(){
    if (threadIdx.x < NB) g_mx[threadIdx.x] = (int)0x80000000;
}

/* ------------- LUT precompute: time/week/bias (296 entries) ---------- */
__global__ void pre_small_k(const float* __restrict__ time_emb,
                            const float* __restrict__ week_emb,
                            const float* __restrict__ W1, const float* __restrict__ b1,
                            const float* __restrict__ W2, const float* __restrict__ b2,
                            const float* __restrict__ proj)
{
    __shared__ float sT1[32*32], sU1[32*32], sT2[32*32], sU2[32*32];
    __shared__ float sprojT[32*64];
    __shared__ float sv[8][32], snv[8][32];
    int tid = threadIdx.x;
    for (int t=tid; t<1024; t+=256){
        int h=t>>5, d=t&31;
        sT1[d*32+h] = W1[h*96 + 32 + d];
        sU1[d*32+h] = W1[h*96 + 64 + d];
        sT2[d*32+h] = W2[h*96 + 32 + d];
        sU2[d*32+h] = W2[h*96 + 64 + d];
    }
    for (int t=tid; t<2048; t+=256){ int m=t>>5, d=t&31; sprojT[d*64+m] = proj[m*32+d]; }
    __syncthreads();

    int w = tid>>5, l = tid&31;
    int e = blockIdx.x*8 + w;
    if (e >= 296) return;

    float a1, a2;
    float *A1, *A2, *D1, *D2;
    if (e < 288){
        sv[w][l] = time_emb[e*32 + l]; __syncwarp();
        a1 = 0.f; a2 = 0.f;
        #pragma unroll
        for (int d=0; d<32; d++){
            float v = sv[w][d];
            a1 = fmaf(sT1[d*32+l], v, a1);
            a2 = fmaf(sT2[d*32+l], v, a2);
        }
        A1 = g_a1t + e*32; A2 = g_a2t + e*32;
        D1 = g_d1t + e*64; D2 = g_d2t + e*64;
    } else if (e < 295){
        int k = e - 288;
        sv[w][l] = week_emb[k*32 + l]; __syncwarp();
        a1 = 0.f; a2 = 0.f;
        #pragma unroll
        for (int d=0; d<32; d++){
            float v = sv[w][d];
            a1 = fmaf(sU1[d*32+l], v, a1);
            a2 = fmaf(sU2[d*32+l], v, a2);
        }
        A1 = g_a1w + k*32; A2 = g_a2w + k*32;
        D1 = g_d1w + k*64; D2 = g_d2w + k*64;
    } else {
        a1 = b1[l]; a2 = b2[l];
        A1 = g_a1b; A2 = g_a2b; D1 = g_d1b; D2 = g_d2b;
    }
    a1 *= ALPHA; a2 *= ALPHA;
    A1[l] = a1; A2[l] = a2;

    snv[w][l] = a1; __syncwarp();
    float d0=0.f, d1=0.f;
    #pragma unroll
    for (int dd=0; dd<32; dd++){
        float f = snv[w][dd];
        d0 = fmaf(f, sprojT[dd*64+l],    d0);
        d1 = fmaf(f, sprojT[dd*64+32+l], d1);
    }
    D1[l] = d0; D1[32+l] = d1;
    __syncwarp();
    snv[w][l] = a2; __syncwarp();
    d0=0.f; d1=0.f;
    #pragma unroll
    for (int dd=0; dd<32; dd++){
        float f = snv[w][dd];
        d0 = fmaf(f, sprojT[dd*64+l],    d0);
        d1 = fmaf(f, sprojT[dd*64+32+l], d1);
    }
    D2[l] = d0; D2[32+l] = d1;
}

/* ------------- LUT precompute: per-node (50000 entries) -------------- */
__global__ void pre_node_k(const float* __restrict__ node_emb,
                           const float* __restrict__ W1, const float* __restrict__ W2,
                           const float* __restrict__ proj)
{
    __shared__ float sW1T[32*32], sW2T[32*32];
    __shared__ float sprojT[32*64];
    __shared__ float sne[8][32], snv[8][32];
    int tid = threadIdx.x;
    for (int t=tid; t<1024; t+=256){
        int h=t>>5, d=t&31;
        sW1T[d*32+h] = W1[h*96 + d];
        sW2T[d*32+h] = W2[h*96 + d];
    }
    for (int t=tid; t<2048; t+=256){ int m=t>>5, d=t&31; sprojT[d*64+m] = proj[m*32+d]; }
    __syncthreads();

    int w = tid>>5, l = tid&31;
    int n = blockIdx.x*8 + w;

    sne[w][l] = node_emb[n*32 + l]; __syncwarp();
    float a1 = 0.f, a2 = 0.f;
    #pragma unroll
    for (int d=0; d<32; d++){
        float v = sne[w][d];
        a1 = fmaf(sW1T[d*32+l], v, a1);
        a2 = fmaf(sW2T[d*32+l], v, a2);
    }
    a1 *= ALPHA; a2 *= ALPHA;
    g_a1n[(size_t)n*32 + l] = a1;
    g_a2n[(size_t)n*32 + l] = a2;

    snv[w][l] = a1; __syncwarp();
    float d0=0.f, d1=0.f;
    #pragma unroll
    for (int dd=0; dd<32; dd++){
        float f = snv[w][dd];
        d0 = fmaf(f, sprojT[dd*64+l],    d0);
        d1 = fmaf(f, sprojT[dd*64+32+l], d1);
    }
    g_d1n[(size_t)n*64 + l] = d0;
    g_d1n[(size_t)n*64 + 32 + l] = d1;
    __syncwarp();
    snv[w][l] = a2; __syncwarp();
    d0=0.f; d1=0.f;
    #pragma unroll
    for (int dd=0; dd<32; dd++){
        float f = snv[w][dd];
        d0 = fmaf(f, sprojT[dd*64+l],    d0);
        d1 = fmaf(f, sprojT[dd*64+32+l], d1);
    }
    g_d2n[(size_t)n*64 + l] = d0;
    g_d2n[(size_t)n*64 + 32 + l] = d1;
}

/* --------------------------- phase 1 (LUT, 4 nodes/warp) -------------
 * Writes h0, q (fp16), diag2, idx, batch max.  NO dash2 store.
 */
__global__ void phase1_k(const float* __restrict__ x,
                         const float* __restrict__ node_emb,
                         const float* __restrict__ time_emb,
                         const float* __restrict__ week_emb,
                         const float* __restrict__ Win, const float* __restrict__ bin)
{
    __shared__ float sW4[9*128];
    __shared__ float sbin[32];
    __shared__ float sxv[8][160];
    __shared__ int   sbmax[NB];

    int tid = threadIdx.x;
    for (int t=tid; t<1152; t+=256){
        int h=t/36, j=t%36;
        sW4[(j>>2)*128 + h*4 + (j&3)] = Win[t];
    }
    if (tid<32) sbin[tid]=bin[tid];
    if (tid<NB) sbmax[tid] = (int)0x80000000;
    __syncthreads();

    int w = tid>>5, l = tid&31;
    int i0 = (blockIdx.x*8 + w)*4;
    int b = i0 / NN;

    const float* xr = x + (size_t)i0*36;
    for (int idx=l; idx<144; idx+=32){
        int nd = idx/36, j = idx - nd*36;
        sxv[w][nd*40 + j] = xr[idx];
    }
    __syncwarp();

    float inp[4];
    #pragma unroll
    for (int nd=0; nd<4; nd++) inp[nd] = sbin[l];
    #pragma unroll
    for (int j4=0; j4<9; j4++){
        float4 w4 = ((float4*)sW4)[j4*32 + l];
        #pragma unroll
        for (int nd=0; nd<4; nd++){
            float4 x4 = *reinterpret_cast<float4*>(&sxv[w][nd*40 + j4*4]);
            inp[nd] = fmaf(w4.x, x4.x,
                      fmaf(w4.y, x4.y,
                      fmaf(w4.z, x4.z,
                      fmaf(w4.w, x4.w, inp[nd]))));
        }
    }

    float wmax = -1e30f;
    #pragma unroll 1
    for (int nd=0; nd<4; nd++){
        int i = i0 + nd;
        int n = i - b*NN;
        int ti = (int)(sxv[w][nd*40+34]*288.0f); ti = min(max(ti,0),287);
        int wk = (int)(sxv[w][nd*40+35]);        wk = min(max(wk,0),6);

        float ne = node_emb[n*32+l];
        float te = time_emb[ti*32+l];
        float we = week_emb[wk*32+l];
        size_t hb = (size_t)i*128;
        g_h0[hb+l]=inp[nd]; g_h0[hb+32+l]=ne; g_h0[hb+64+l]=te; g_h0[hb+96+l]=we;

        float a1 = g_a1n[(size_t)n*32+l] + g_a1t[ti*32+l] + g_a1w[wk*32+l] + g_a1b[l];
        float diag1 = 0.5f * warpSum(a1*a1);
        float d0 = g_d1n[(size_t)n*64+l]    + g_d1t[ti*64+l]    + g_d1w[wk*64+l]    + g_d1b[l];
        float d1 = g_d1n[(size_t)n*64+32+l] + g_d1t[ti*64+32+l] + g_d1w[wk*64+32+l] + g_d1b[32+l];
        float mx1 = warpMax(fmaxf(d0,d1));
        g_qh[(size_t)i*64 + l]      = __float2half(RATIO*(expf(d0 - diag1 - mx1) + EPSRF));
        g_qh[(size_t)i*64 + 32 + l] = __float2half(RATIO*(expf(d1 - diag1 - mx1) + EPSRF));

        float a2 = g_a2n[(size_t)n*32+l] + g_a2t[ti*32+l] + g_a2w[wk*32+l] + g_a2b[l];
        float diag2 = 0.5f * warpSum(a2*a2);
        d0 = g_d2n[(size_t)n*64+l]    + g_d2t[ti*64+l]    + g_d2w[wk*64+l]    + g_d2b[l];
        d1 = g_d2n[(size_t)n*64+32+l] + g_d2t[ti*64+32+l] + g_d2w[wk*64+32+l] + g_d2b[32+l];
        if (l==0){
            g_diag2[i] = diag2;
            g_idx[i]   = ti*8 + wk;
        }
        wmax = fmaxf(wmax, fmaxf(d0,d1));
    }

    float m = warpMax(wmax);
    if (l==0) atomicMax(&sbmax[b], f2ord(m));

    __syncthreads();
    if (tid < NB && sbmax[tid] != (int)0x80000000)
        atomicMax(&g_mx[tid], sbmax[tid]);
}

/* ---------- fused k features + ksum partials (LUT recompute) --------- */
__global__ void __launch_bounds__(256,1)
computek2_k(){
    __shared__ float sd2b[64];
    __shared__ int   sidx[CHSZ];
    __shared__ float sdiag[CHSZ];
    __shared__ float red[4][64];

    int b = blockIdx.y, ch = blockIdx.x;
    int tid = threadIdx.x;
    int m = tid & 63, part = tid >> 6;
    int nb0 = ch*CHSZ;

    if (tid < 64) sd2b[tid] = g_d2b[tid];
    for (int t=tid; t<CHSZ; t+=256){
        int n = nb0 + t;
        if (n < NN){
            sidx[t]  = g_idx[b*NN + n];
            sdiag[t] = g_diag2[b*NN + n];
        } else { sidx[t] = 0; sdiag[t] = 0.f; }
    }
    __syncthreads();

    float mx = ord2f(g_mx[b]);
    float s = 0.f;
    int tb = part*128;
    #pragma unroll 2
    for (int nn=0; nn<128; nn++){
        int t = tb + nn;
        int n = nb0 + t;
        if (n < NN){
            int iv = sidx[t];
            int ti = iv >> 3, wk = iv & 7;
            float dv = g_d2n[(size_t)n*64 + m] + g_d2t[ti*64 + m]
                     + g_d2w[wk*64 + m] + sd2b[m];
            float val = RATIO*(expf(dv - sdiag[t] - mx) + EPSRF);
            g_kh[((size_t)(b*NN+n))*64 + m] = __float2half(val);
            s += val;
        }
    }
    red[part][m] = s;
    __syncthreads();
    if (part == 0){
        float t = red[0][m] + red[1][m] + red[2][m] + red[3][m];
        g_kpart[(size_t)(b*CH+ch)*64 + m] = t;
    }
}

__global__ void ksumr_k(){
    int tid = threadIdx.x;
    int b = tid >> 6, m = tid & 63;
    float s = 0.f;
    for (int ch=0; ch<CH; ch++)
        s += g_kpart[(size_t)(b*CH+ch)*64 + m];
    g_ksum[b*64 + m] = s;
}

/* ------------------------- GLU via mma.sync (fp16) ------------------- */
#define GT_TILES ((NT + 255)/256)
#define G3_SA   0
#define G3_SB   65536
#define G3_SBI  131072
#define G3_SBO  131584
#define G3_TOT  132096

extern __shared__ char gsm2[];

__global__ void __launch_bounds__(512,1)
glu3_k(const float* __restrict__ hin,
       const float* __restrict__ wi, const float* __restrict__ bi,
       const float* __restrict__ wo, const float* __restrict__ bo)
{
    char* SA = gsm2 + G3_SA;
    char* SB = gsm2 + G3_SB;
    float* sbi = (float*)(gsm2 + G3_SBI);
    float* sbo = (float*)(gsm2 + G3_SBO);
    int tid = threadIdx.x;

    for (int c = tid; c < 4096; c += 512){
        int n = c >> 4, ch = c & 15;
        const float* src = (n < 128) ? (wi + (size_t)n*128 + ch*8)
                                     : (wo + (size_t)(n-128)*128 + ch*8);
        *reinterpret_cast<uint4*>(SB + n*256 + ((ch ^ (n&7))<<4)) = pack8_f16(src);
    }
    if (tid < 128){ sbi[tid] = bi[tid]; sbo[tid] = bo[tid]; }

    int w = tid>>5, l = tid&31;
    uint32_t saB = smem_u32(SA);
    uint32_t sbB = smem_u32(SB);

    int a_row = (w<<4) + (l & 15);
    int er    = (w<<4) + (l>>2);

    for (int tile = blockIdx.x; tile < GT_TILES; tile += gridDim.x){
        int base = tile << 8;

        for (int c = tid; c < 4096; c += 512){
            int r = c >> 4, ch = c & 15;
            uint4 pw = make_uint4(0,0,0,0);
            if (base + r < NT)
                pw = pack8_f16(hin + (size_t)(base + r)*128 + ch*8);
            *reinterpret_cast<uint4*>(SA + r*256 + ((ch ^ (r&7))<<4)) = pw;
        }
        __syncthreads();

        uint32_t Af[8][4];
        #pragma unroll
        for (int ks=0; ks<8; ks++){
            int kc = (ks<<1) + (l>>4);
            ldsm_x4(Af[ks], saB + a_row*256 + ((kc ^ (a_row&7))<<4));
        }

        #pragma unroll 1
        for (int nb=0; nb<16; nb++){
            int nrI = (nb<<3) + (l&7);
            int nrO = nrI + 128;
            uint32_t BI[16], BO[16];
            #pragma unroll
            for (int j=0;j<4;j++){
                int kc = (j<<2) + (l>>3);
                ldsm_x4(&BI[j<<2], sbB + nrI*256 + ((kc ^ (nrI&7))<<4));
                ldsm_x4(&BO[j<<2], sbB + nrO*256 + ((kc ^ (nrO&7))<<4));
            }
            float dI[4] = {0.f,0.f,0.f,0.f};
            float dO[4] = {0.f,0.f,0.f,0.f};
            #pragma unroll
            for (int ks=0; ks<8; ks++){
                mma16816h(dI, Af[ks], &BI[ks<<1]);
                mma16816h(dO, Af[ks], &BO[ks<<1]);
            }

            int c0 = (nb<<3) + ((l&3)<<1);
            float bi0 = sbi[c0], bi1 = sbi[c0+1];
            float bo0 = sbo[c0], bo1 = sbo[c0+1];
            int n0 = base + er;
            int n1 = n0 + 8;
            if (n0 < NT){
                float aI0 = dI[0] + bi0, aI1 = dI[1] + bi1;
                float ox = (dO[0] + bo0) / (1.f + expf(-aI0));
                float oy = (dO[1] + bo1) / (1.f + expf(-aI1));
                *reinterpret_cast<__half2*>(g_vh + (size_t)n0*128 + c0) = __floats2half2_rn(ox, oy);
            }
            if (n1 < NT){
                float aI2 = dI[2] + bi0, aI3 = dI[3] + bi1;
                float ox = (dO[2] + bo0) / (1.f + expf(-aI2));
                float oy = (dO[3] + bo1) / (1.f + expf(-aI3));
                *reinterpret_cast<__half2*>(g_vh + (size_t)n1*128 + c0) = __floats2half2_rn(ox, oy);
            }
        }
        __syncthreads();
    }
}

/* --------------- K^T V partials via mma.sync (deterministic) --------- */
#define KT_PAD 40
__global__ void __launch_bounds__(256,1)
kvredmma_k(){
    __shared__ __align__(16) __half SKt[64*KT_PAD];
    __shared__ __align__(16) __half SVt[128*KT_PAD];
    int b = blockIdx.y, ch = blockIdx.x;
    int tid = threadIdx.x, w = tid>>5, l = tid&31;
    uint32_t skB = smem_u32(SKt), svB = smem_u32(SVt);

    float acc[4][2][4];
    #pragma unroll
    for (int mt=0;mt<4;mt++)
        #pragma unroll
        for (int nb=0;nb<2;nb++)
            #pragma unroll
            for (int r=0;r<4;r++) acc[mt][nb][r] = 0.f;

    int nb0 = ch*CHSZ;
    #pragma unroll 1
    for (int c0=0; c0<CHSZ; c0+=32){
        int nbase = nb0 + c0;
        {
            int node = tid & 31, rg = tid >> 5;
            int n = nbase + node;
            if (n < NN){
                const __half2* s2 = (const __half2*)(g_kh + ((size_t)(b*NN+n))*64 + rg*8);
                #pragma unroll
                for (int j=0;j<4;j++){
                    __half2 p = s2[j];
                    SKt[(rg*8 + 2*j  )*KT_PAD + node] = __low2half(p);
                    SKt[(rg*8 + 2*j+1)*KT_PAD + node] = __high2half(p);
                }
            } else {
                #pragma unroll
                for (int j=0;j<4;j++){
                    SKt[(rg*8 + 2*j  )*KT_PAD + node] = __float2half(0.f);
                    SKt[(rg*8 + 2*j+1)*KT_PAD + node] = __float2half(0.f);
                }
            }
        }
        {
            int node = tid & 31, hg = tid >> 5;
            int n = nbase + node;
            if (n < NN){
                const __half2* s2 = (const __half2*)(g_vh + ((size_t)(b*NN+n))*128 + hg*16);
                #pragma unroll
                for (int j=0;j<8;j++){
                    __half2 p = s2[j];
                    SVt[(hg*16 + 2*j  )*KT_PAD + node] = __low2half(p);
                    SVt[(hg*16 + 2*j+1)*KT_PAD + node] = __high2half(p);
                }
            } else {
                #pragma unroll
                for (int j=0;j<8;j++){
                    SVt[(hg*16 + 2*j  )*KT_PAD + node] = __float2half(0.f);
                    SVt[(hg*16 + 2*j+1)*KT_PAD + node] = __float2half(0.f);
                }
            }
        }
        __syncthreads();

        uint32_t Bv[2][4];
        #pragma unroll
        for (int nb=0;nb<2;nb++){
            int row = w*16 + nb*8 + (l&7);
            ldsm_x4(Bv[nb], svB + row*(KT_PAD*2) + ((l>>3)<<4));
        }
        #pragma unroll
        for (int ks=0; ks<2; ks++){
            uint32_t Af[4][4];
            #pragma unroll
            for (int mt=0;mt<4;mt++){
                int row = mt*16 + (l&15);
                ldsm_x4(Af[mt], skB + row*(KT_PAD*2) + (((ks<<1) + (l>>4))<<4));
            }
            #pragma unroll
            for (int mt=0;mt<4;mt++){
                mma16816h(acc[mt][0], Af[mt], &Bv[0][ks<<1]);
                mma16816h(acc[mt][1], Af[mt], &Bv[1][ks<<1]);
            }
        }
        __syncthreads();
    }

    size_t pb = (size_t)(b*CH+ch);
    #pragma unroll
    for (int mt=0;mt<4;mt++){
        #pragma unroll
        for (int nb=0;nb<2;nb++){
            int rf0 = mt*16 + (l>>2);
            int hd = w*16 + nb*8 + 2*(l&3);
            float2 v0 = make_float2(acc[mt][nb][0], acc[mt][nb][1]);
            float2 v1 = make_float2(acc[mt][nb][2], acc[mt][nb][3]);
            *reinterpret_cast<float2*>(&g_part[(pb*64 + rf0    )*128 + hd]) = v0;
            *reinterpret_cast<float2*>(&g_part[(pb*64 + rf0 + 8)*128 + hd]) = v1;
        }
    }
}

__global__ void vred_k(){
    int idx = blockIdx.x*256 + threadIdx.x;
    int b = idx >> 13;
    int rem = idx & 8191;
    int m = rem >> 7, d = rem & 127;
    float s = 0.f;
    for (int ch=0; ch<CH; ch++)
        s += g_part[((size_t)(b*CH+ch)*64 + m)*128 + d];
    g_v2x[((size_t)b*64 + m)*128 + d] = s;
}

/* ------------- attention out + residual + layernorm ------------------ */
__global__ void attn_k(const float* __restrict__ res_in,
                       const float* __restrict__ lg, const float* __restrict__ lb){
    __shared__ float sv2x[64*128];
    __shared__ float sks[64];
    __shared__ float sg[128], sb[128];

    int b = blockIdx.y;
    int tid = threadIdx.x, w = tid>>5, l = tid&31;
    for (int t=tid; t<8192; t+=256) sv2x[t] = g_v2x[(size_t)b*8192 + t];
    if (tid<64)  sks[tid] = g_ksum[b*64 + tid];
    if (tid<128){ sg[tid] = lg[tid]; sb[tid] = lb[tid]; }
    __syncthreads();

    int nb0 = (blockIdx.x*8 + w)*8;
    float q0[8], q1[8];
    #pragma unroll
    for (int nd=0; nd<8; nd++){
        int n = nb0 + nd;
        if (n < NN){
            size_t i = (size_t)b*NN + n;
            q0[nd] = __half2float(g_qh[i*64 + l]);
            q1[nd] = __half2float(g_qh[i*64 + 32 + l]);
        } else { q0[nd] = 0.f; q1[nd] = 0.f; }
    }

    float4 acc[8]; float o2[8];
    #pragma unroll
    for (int nd=0; nd<8; nd++){ acc[nd]=make_float4(0.f,0.f,0.f,0.f); o2[nd]=0.f; }

    #pragma unroll 4
    for (int m=0; m<32; m++){
        float4 vx = ((float4*)(sv2x + m*128))[l];
        float km = sks[m];
        #pragma unroll
        for (int nd=0; nd<8; nd++){
            float qm = __shfl_sync(0xffffffffu, q0[nd], m);
            acc[nd].x = fmaf(qm, vx.x, acc[nd].x);
            acc[nd].y = fmaf(qm, vx.y, acc[nd].y);
            acc[nd].z = fmaf(qm, vx.z, acc[nd].z);
            acc[nd].w = fmaf(qm, vx.w, acc[nd].w);
            o2[nd]    = fmaf(qm, km, o2[nd]);
        }
    }
    #pragma unroll 4
    for (int m=0; m<32; m++){
        float4 vx = ((float4*)(sv2x + (m+32)*128))[l];
        float km = sks[m+32];
        #pragma unroll
        for (int nd=0; nd<8; nd++){
            float qm = __shfl_sync(0xffffffffu, q1[nd], m);
            acc[nd].x = fmaf(qm, vx.x, acc[nd].x);
            acc[nd].y = fmaf(qm, vx.y, acc[nd].y);
            acc[nd].z = fmaf(qm, vx.z, acc[nd].z);
            acc[nd].w = fmaf(qm, vx.w, acc[nd].w);
            o2[nd]    = fmaf(qm, km, o2[nd]);
        }
    }

    float4 g4 = ((float4*)sg)[l];
    float4 b4 = ((float4*)sb)[l];
    #pragma unroll 1
    for (int nd=0; nd<8; nd++){
        int n = nb0 + nd;
        if (n >= NN) continue;
        size_t i = (size_t)b*NN + n;
        float inv = 1.f / o2[nd];
        float4 res = ((const float4*)res_in)[i*32 + l];
        float4 t;
        t.x = fmaf(acc[nd].x, inv, res.x);
        t.y = fmaf(acc[nd].y, inv, res.y);
        t.z = fmaf(acc[nd].z, inv, res.z);
        t.w = fmaf(acc[nd].w, inv, res.w);
        float mu = warpSum(t.x+t.y+t.z+t.w) * (1.f/128.f);
        float dx=t.x-mu, dy=t.y-mu, dz=t.z-mu, dw=t.w-mu;
        float var = warpSum(dx*dx+dy*dy+dz*dz+dw*dw) * (1.f/128.f);
        float rs = rsqrtf(var + EPSLN);
        float4 o;
        o.x = dx*rs*g4.x + b4.x;
        o.y = dy*rs*g4.y + b4.y;
        o.z = dz*rs*g4.z + b4.z;
        o.w = dw*rs*g4.w + b4.w;
        ((float4*)g_h)[i*32 + l] = o;
    }
}

/* -------- relu(concat(h0,h)) @ W_reg.T + b_reg, transposed out ------- */
__global__ void final_k(const float* __restrict__ Wreg, const float* __restrict__ breg,
                        float* __restrict__ out)
{
    __shared__ float sWrT[256*12];
    __shared__ float sbr[12];
    int tid = threadIdx.x;
    for (int t=tid; t<3072; t+=256){ int to=t>>8, j=t&255; sWrT[j*12+to] = Wreg[t]; }
    if (tid<12) sbr[tid] = breg[tid];
    __syncthreads();

    int w = tid>>5, l = tid&31;
    int i = blockIdx.x*8 + w;
    int b = i / NN;
    int n = i - b*NN;
    size_t hb = (size_t)i*128;

    float acc[12];
    #pragma unroll
    for (int t=0;t<12;t++) acc[t]=0.f;

    #pragma unroll
    for (int c=0;c<8;c++){
        int j = c*32 + l;
        float vIn = (j < 128) ? g_h0[hb + j] : g_h[hb + j - 128];
        vIn = fmaxf(vIn, 0.f);
        #pragma unroll
        for (int t=0;t<12;t++) acc[t] = fmaf(vIn, sWrT[j*12+t], acc[t]);
    }
    #pragma unroll
    for (int t=0;t<12;t++) acc[t] = warpSum(acc[t]);
    if (l < 12) out[((size_t)b*12 + l)*NN + n] = acc[l] + sbr[l];
}

/* ------------------------------ launch ------------------------------- */
extern "C" void kernel_launch(void* const* d_in, const int* in_sizes, int n_in,
                              void* d_out, int out_size)
{
    const float* x        = (const float*)d_in[0];
    const float* node_emb = (const float*)d_in[1];
    const float* time_emb = (const float*)d_in[2];
    const float* week_emb = (const float*)d_in[3];
    const float* Win      = (const float*)d_in[4];
    const float* bin      = (const float*)d_in[5];
    const float* W1       = (const float*)d_in[6];
    const float* b1       = (const float*)d_in[7];
    const float* W2       = (const float*)d_in[8];
    const float* b2       = (const float*)d_in[9];
    const float* Wreg     = (const float*)d_in[10];
    const float* breg     = (const float*)d_in[11];
    const float* proj     = (const float*)d_in[12];

    cudaFuncSetAttribute(glu3_k, cudaFuncAttributeMaxDynamicSharedMemorySize, G3_TOT);

    float* g_h_ptr;  cudaGetSymbolAddress((void**)&g_h_ptr,  g_h);
    float* g_h0_ptr; cudaGetSymbolAddress((void**)&g_h0_ptr, g_h0);

    initmx_k<<<1,32>>>();
    pre_small_k<<<37,256>>>(time_emb, week_emb, W1, b1, W2, b2, proj);
    pre_node_k<<<NN/8,256>>>(node_emb, W1, W2, proj);
    phase1_k<<<NT/32,256>>>(x, node_emb, time_emb, week_emb, Win, bin);
    computek2_k<<<dim3(CH,NB),256>>>();
    ksumr_k<<<1,256>>>();

    for (int layer=0; layer<2; layer++){
        const float* wi = (const float*)d_in[13 + layer*6 + 0];
        const float* bi = (const float*)d_in[13 + layer*6 + 1];
        const float* wo = (const float*)d_in[13 + layer*6 + 2];
        const float* bo = (const float*)d_in[13 + layer*6 + 3];
        const float* lg = (const float*)d_in[13 + layer*6 + 4];
        const float* lb = (const float*)d_in[13 + layer*6 + 5];

        const float* hin = (layer == 0) ? g_h0_ptr : g_h_ptr;

        glu3_k<<<148,512,G3_TOT>>>(hin, wi, bi, wo, bo);
        kvredmma_k<<<dim3(CH,NB),256>>>();
        vred_k<<<128,256>>>();
        attn_k<<<dim3((NN+63)/64,NB),256>>>(hin, lg, lb);
    }

    final_k<<<NT/8,256>>>(Wreg, breg, (float*)d_out);
}

// round 14
// speedup vs baseline: 1.4115x; 1.3102x over previous
#include <cuda_runtime.h>
#include <cuda_bf16.h>
#include <cuda_fp16.h>
#include <math.h>
#include <stdint.h>

#define NB 4
#define NN 50000
#define NT (NB*NN)
#define H4 128
#define RF 64
#define CH 98
#define CHSZ 512

#define ALPHA 0.4204482076268573f   /* 32^-0.25 */
#define RATIO 0.125f                /* 1/sqrt(64) */
#define EPSRF 1e-6f
#define EPSLN 1e-5f

/* ------------------------------ scratch ------------------------------ */
__device__ float  g_h0[(size_t)NT*H4];
__device__ float  g_h [(size_t)NT*H4];
__device__ __align__(16) __half g_hh[(size_t)NT*H4];
__device__ __align__(16) __half g_vh[(size_t)NT*H4];
__device__ __align__(16) __half g_qh[(size_t)NT*RF];
__device__ float  g_diag2[NT];
__device__ int    g_idx[NT];
__device__ __align__(16) __half g_kh[(size_t)NT*RF];
__device__ int    g_mx[NB];
__device__ float  g_part [(size_t)NB*CH*RF*H4];
__device__ float  g_kpart[(size_t)NB*CH*RF];
__device__ float  g_v2x[(size_t)NB*RF*H4];
__device__ float  g_ksum[NB*RF];
/* precomputed LUTs */
__device__ float  g_a1n[(size_t)NN*32], g_a2n[(size_t)NN*32];
__device__ float  g_d1n[(size_t)NN*64], g_d2n[(size_t)NN*64];
__device__ float  g_a1t[288*32], g_a2t[288*32];
__device__ float  g_d1t[288*64], g_d2t[288*64];
__device__ float  g_a1w[7*32],  g_a2w[7*32];
__device__ float  g_d1w[7*64],  g_d2w[7*64];
__device__ float  g_a1b[32],    g_a2b[32];
__device__ float  g_d1b[64],    g_d2b[64];

/* ------------------------------ helpers ------------------------------ */
__device__ __forceinline__ float warpSum(float v){
    #pragma unroll
    for (int o=16;o;o>>=1) v += __shfl_xor_sync(0xffffffffu, v, o);
    return v;
}
__device__ __forceinline__ float warpMax(float v){
    #pragma unroll
    for (int o=16;o;o>>=1) v = fmaxf(v, __shfl_xor_sync(0xffffffffu, v, o));
    return v;
}
__device__ __forceinline__ int f2ord(float f){
    int i = __float_as_int(f);
    return (i >= 0) ? i : (i ^ 0x7FFFFFFF);
}
__device__ __forceinline__ float ord2f(int i){
    return __int_as_float((i >= 0) ? i : (i ^ 0x7FFFFFFF));
}

/* --------------------- mma.sync helpers ------------------------------ */
__device__ __forceinline__ uint32_t smem_u32(const void* p){
    uint32_t a;
    asm("{ .reg .u64 t; cvta.to.shared.u64 t, %1; cvt.u32.u64 %0, t; }"
        : "=r"(a) : "l"(p));
    return a;
}
__device__ __forceinline__ void ldsm_x4(uint32_t* r, uint32_t addr){
    asm volatile("ldmatrix.sync.aligned.m8n8.x4.shared.b16 {%0,%1,%2,%3}, [%4];"
        : "=r"(r[0]), "=r"(r[1]), "=r"(r[2]), "=r"(r[3]) : "r"(addr));
}
__device__ __forceinline__ void mma16816h(float* d, const uint32_t* a, const uint32_t* b){
    asm volatile("mma.sync.aligned.m16n8k16.row.col.f32.f16.f16.f32 "
        "{%0,%1,%2,%3}, {%4,%5,%6,%7}, {%8,%9}, {%0,%1,%2,%3};"
        : "+f"(d[0]), "+f"(d[1]), "+f"(d[2]), "+f"(d[3])
        : "r"(a[0]), "r"(a[1]), "r"(a[2]), "r"(a[3]), "r"(b[0]), "r"(b[1]));
}
__device__ __forceinline__ uint4 pack8_f16(const float* src){
    float4 a = ((const float4*)src)[0];
    float4 b = ((const float4*)src)[1];
    __half2 p0 = __floats2half2_rn(a.x, a.y);
    __half2 p1 = __floats2half2_rn(a.z, a.w);
    __half2 p2 = __floats2half2_rn(b.x, b.y);
    __half2 p3 = __floats2half2_rn(b.z, b.w);
    uint4 w;
    w.x = *reinterpret_cast<uint32_t*>(&p0);
    w.y = *reinterpret_cast<uint32_t*>(&p1);
    w.z = *reinterpret_cast<uint32_t*>(&p2);
    w.w = *reinterpret_cast<uint32_t*>(&p3);
    return w;
}

/* ------------------------------ init --------------------------------- */
__global__ void initmx_k(){
    if (threadIdx.x < NB) g_mx[threadIdx.x] = (int)0x80000000;
}

/* ------------- LUT precompute: time/week/bias (296 entries) ---------- */
__global__ void pre_small_k(const float* __restrict__ time_emb,
                            const float* __restrict__ week_emb,
                            const float* __restrict__ W1, const float* __restrict__ b1,
                            const float* __restrict__ W2, const float* __restrict__ b2,
                            const float* __restrict__ proj)
{
    __shared__ float sT1[32*32], sU1[32*32], sT2[32*32], sU2[32*32];
    __shared__ float sprojT[32*64];
    __shared__ float sv[8][32], snv[8][32];
    int tid = threadIdx.x;
    for (int t=tid; t<1024; t+=256){
        int h=t>>5, d=t&31;
        sT1[d*32+h] = W1[h*96 + 32 + d];
        sU1[d*32+h] = W1[h*96 + 64 + d];
        sT2[d*32+h] = W2[h*96 + 32 + d];
        sU2[d*32+h] = W2[h*96 + 64 + d];
    }
    for (int t=tid; t<2048; t+=256){ int m=t>>5, d=t&31; sprojT[d*64+m] = proj[m*32+d]; }
    __syncthreads();

    int w = tid>>5, l = tid&31;
    int e = blockIdx.x*8 + w;
    if (e >= 296) return;

    float a1, a2;
    float *A1, *A2, *D1, *D2;
    if (e < 288){
        sv[w][l] = time_emb[e*32 + l]; __syncwarp();
        a1 = 0.f; a2 = 0.f;
        #pragma unroll
        for (int d=0; d<32; d++){
            float v = sv[w][d];
            a1 = fmaf(sT1[d*32+l], v, a1);
            a2 = fmaf(sT2[d*32+l], v, a2);
        }
        A1 = g_a1t + e*32; A2 = g_a2t + e*32;
        D1 = g_d1t + e*64; D2 = g_d2t + e*64;
    } else if (e < 295){
        int k = e - 288;
        sv[w][l] = week_emb[k*32 + l]; __syncwarp();
        a1 = 0.f; a2 = 0.f;
        #pragma unroll
        for (int d=0; d<32; d++){
            float v = sv[w][d];
            a1 = fmaf(sU1[d*32+l], v, a1);
            a2 = fmaf(sU2[d*32+l], v, a2);
        }
        A1 = g_a1w + k*32; A2 = g_a2w + k*32;
        D1 = g_d1w + k*64; D2 = g_d2w + k*64;
    } else {
        a1 = b1[l]; a2 = b2[l];
        A1 = g_a1b; A2 = g_a2b; D1 = g_d1b; D2 = g_d2b;
    }
    a1 *= ALPHA; a2 *= ALPHA;
    A1[l] = a1; A2[l] = a2;

    snv[w][l] = a1; __syncwarp();
    float d0=0.f, d1=0.f;
    #pragma unroll
    for (int dd=0; dd<32; dd++){
        float f = snv[w][dd];
        d0 = fmaf(f, sprojT[dd*64+l],    d0);
        d1 = fmaf(f, sprojT[dd*64+32+l], d1);
    }
    D1[l] = d0; D1[32+l] = d1;
    __syncwarp();
    snv[w][l] = a2; __syncwarp();
    d0=0.f; d1=0.f;
    #pragma unroll
    for (int dd=0; dd<32; dd++){
        float f = snv[w][dd];
        d0 = fmaf(f, sprojT[dd*64+l],    d0);
        d1 = fmaf(f, sprojT[dd*64+32+l], d1);
    }
    D2[l] = d0; D2[32+l] = d1;
}

/* ------------- LUT precompute: per-node (50000 entries) -------------- */
__global__ void pre_node_k(const float* __restrict__ node_emb,
                           const float* __restrict__ W1, const float* __restrict__ W2,
                           const float* __restrict__ proj)
{
    __shared__ float sW1T[32*32], sW2T[32*32];
    __shared__ float sprojT[32*64];
    __shared__ float sne[8][32], snv[8][32];
    int tid = threadIdx.x;
    for (int t=tid; t<1024; t+=256){
        int h=t>>5, d=t&31;
        sW1T[d*32+h] = W1[h*96 + d];
        sW2T[d*32+h] = W2[h*96 + d];
    }
    for (int t=tid; t<2048; t+=256){ int m=t>>5, d=t&31; sprojT[d*64+m] = proj[m*32+d]; }
    __syncthreads();

    int w = tid>>5, l = tid&31;
    int n = blockIdx.x*8 + w;

    sne[w][l] = node_emb[n*32 + l]; __syncwarp();
    float a1 = 0.f, a2 = 0.f;
    #pragma unroll
    for (int d=0; d<32; d++){
        float v = sne[w][d];
        a1 = fmaf(sW1T[d*32+l], v, a1);
        a2 = fmaf(sW2T[d*32+l], v, a2);
    }
    a1 *= ALPHA; a2 *= ALPHA;
    g_a1n[(size_t)n*32 + l] = a1;
    g_a2n[(size_t)n*32 + l] = a2;

    snv[w][l] = a1; __syncwarp();
    float d0=0.f, d1=0.f;
    #pragma unroll
    for (int dd=0; dd<32; dd++){
        float f = snv[w][dd];
        d0 = fmaf(f, sprojT[dd*64+l],    d0);
        d1 = fmaf(f, sprojT[dd*64+32+l], d1);
    }
    g_d1n[(size_t)n*64 + l] = d0;
    g_d1n[(size_t)n*64 + 32 + l] = d1;
    __syncwarp();
    snv[w][l] = a2; __syncwarp();
    d0=0.f; d1=0.f;
    #pragma unroll
    for (int dd=0; dd<32; dd++){
        float f = snv[w][dd];
        d0 = fmaf(f, sprojT[dd*64+l],    d0);
        d1 = fmaf(f, sprojT[dd*64+32+l], d1);
    }
    g_d2n[(size_t)n*64 + l] = d0;
    g_d2n[(size_t)n*64 + 32 + l] = d1;
}

/* --------------------------- phase 1 (LUT, 4 nodes/warp) ------------- */
__global__ void phase1_k(const float* __restrict__ x,
                         const float* __restrict__ node_emb,
                         const float* __restrict__ time_emb,
                         const float* __restrict__ week_emb,
                         const float* __restrict__ Win, const float* __restrict__ bin)
{
    __shared__ float sW4[9*128];
    __shared__ float sbin[32];
    __shared__ float sxv[8][160];
    __shared__ int   sbmax[NB];

    int tid = threadIdx.x;
    for (int t=tid; t<1152; t+=256){
        int h=t/36, j=t%36;
        sW4[(j>>2)*128 + h*4 + (j&3)] = Win[t];
    }
    if (tid<32) sbin[tid]=bin[tid];
    if (tid<NB) sbmax[tid] = (int)0x80000000;
    __syncthreads();

    int w = tid>>5, l = tid&31;
    int i0 = (blockIdx.x*8 + w)*4;
    int b = i0 / NN;

    const float* xr = x + (size_t)i0*36;
    for (int idx=l; idx<144; idx+=32){
        int nd = idx/36, j = idx - nd*36;
        sxv[w][nd*40 + j] = xr[idx];
    }
    __syncwarp();

    float inp[4];
    #pragma unroll
    for (int nd=0; nd<4; nd++) inp[nd] = sbin[l];
    #pragma unroll
    for (int j4=0; j4<9; j4++){
        float4 w4 = ((float4*)sW4)[j4*32 + l];
        #pragma unroll
        for (int nd=0; nd<4; nd++){
            float4 x4 = *reinterpret_cast<float4*>(&sxv[w][nd*40 + j4*4]);
            inp[nd] = fmaf(w4.x, x4.x,
                      fmaf(w4.y, x4.y,
                      fmaf(w4.z, x4.z,
                      fmaf(w4.w, x4.w, inp[nd]))));
        }
    }

    float wmax = -1e30f;
    #pragma unroll 1
    for (int nd=0; nd<4; nd++){
        int i = i0 + nd;
        int n = i - b*NN;
        int ti = (int)(sxv[w][nd*40+34]*288.0f); ti = min(max(ti,0),287);
        int wk = (int)(sxv[w][nd*40+35]);        wk = min(max(wk,0),6);

        float ne = node_emb[n*32+l];
        float te = time_emb[ti*32+l];
        float we = week_emb[wk*32+l];
        size_t hb = (size_t)i*128;
        g_h0[hb+l]=inp[nd]; g_h0[hb+32+l]=ne; g_h0[hb+64+l]=te; g_h0[hb+96+l]=we;

        float a1 = g_a1n[(size_t)n*32+l] + g_a1t[ti*32+l] + g_a1w[wk*32+l] + g_a1b[l];
        float diag1 = 0.5f * warpSum(a1*a1);
        float d0 = g_d1n[(size_t)n*64+l]    + g_d1t[ti*64+l]    + g_d1w[wk*64+l]    + g_d1b[l];
        float d1 = g_d1n[(size_t)n*64+32+l] + g_d1t[ti*64+32+l] + g_d1w[wk*64+32+l] + g_d1b[32+l];
        float mx1 = warpMax(fmaxf(d0,d1));
        g_qh[(size_t)i*64 + l]      = __float2half(RATIO*(expf(d0 - diag1 - mx1) + EPSRF));
        g_qh[(size_t)i*64 + 32 + l] = __float2half(RATIO*(expf(d1 - diag1 - mx1) + EPSRF));

        float a2 = g_a2n[(size_t)n*32+l] + g_a2t[ti*32+l] + g_a2w[wk*32+l] + g_a2b[l];
        float diag2 = 0.5f * warpSum(a2*a2);
        d0 = g_d2n[(size_t)n*64+l]    + g_d2t[ti*64+l]    + g_d2w[wk*64+l]    + g_d2b[l];
        d1 = g_d2n[(size_t)n*64+32+l] + g_d2t[ti*64+32+l] + g_d2w[wk*64+32+l] + g_d2b[32+l];
        if (l==0){
            g_diag2[i] = diag2;
            g_idx[i]   = ti*8 + wk;
        }
        wmax = fmaxf(wmax, fmaxf(d0,d1));
    }

    float m = warpMax(wmax);
    if (l==0) atomicMax(&sbmax[b], f2ord(m));

    __syncthreads();
    if (tid < NB && sbmax[tid] != (int)0x80000000)
        atomicMax(&g_mx[tid], sbmax[tid]);
}

/* ---------- fused k features + ksum partials (LUT recompute) --------- */
__global__ void __launch_bounds__(256,1)
computek2_k(){
    __shared__ float sd2b[64];
    __shared__ int   sidx[CHSZ];
    __shared__ float sdiag[CHSZ];
    __shared__ float red[4][64];

    int b = blockIdx.y, ch = blockIdx.x;
    int tid = threadIdx.x;
    int m = tid & 63, part = tid >> 6;
    int nb0 = ch*CHSZ;

    if (tid < 64) sd2b[tid] = g_d2b[tid];
    for (int t=tid; t<CHSZ; t+=256){
        int n = nb0 + t;
        if (n < NN){
            sidx[t]  = g_idx[b*NN + n];
            sdiag[t] = g_diag2[b*NN + n];
        } else { sidx[t] = 0; sdiag[t] = 0.f; }
    }
    __syncthreads();

    float mx = ord2f(g_mx[b]);
    float s = 0.f;
    int tb = part*128;
    #pragma unroll 2
    for (int nn=0; nn<128; nn++){
        int t = tb + nn;
        int n = nb0 + t;
        if (n < NN){
            int iv = sidx[t];
            int ti = iv >> 3, wk = iv & 7;
            float dv = g_d2n[(size_t)n*64 + m] + g_d2t[ti*64 + m]
                     + g_d2w[wk*64 + m] + sd2b[m];
            float val = RATIO*(expf(dv - sdiag[t] - mx) + EPSRF);
            g_kh[((size_t)(b*NN+n))*64 + m] = __float2half(val);
            s += val;
        }
    }
    red[part][m] = s;
    __syncthreads();
    if (part == 0){
        float t = red[0][m] + red[1][m] + red[2][m] + red[3][m];
        g_kpart[(size_t)(b*CH+ch)*64 + m] = t;
    }
}

__global__ void ksumr_k(){
    int tid = threadIdx.x;
    int b = tid >> 6, m = tid & 63;
    float s = 0.f;
    for (int ch=0; ch<CH; ch++)
        s += g_kpart[(size_t)(b*CH+ch)*64 + m];
    g_ksum[b*64 + m] = s;
}

/* ------------------------- GLU via mma.sync (fp16) ------------------- */
#define GT_TILES ((NT + 255)/256)
#define G3_SA   0
#define G3_SB   65536
#define G3_SBI  131072
#define G3_SBO  131584
#define G3_TOT  132096

extern __shared__ char gsm2[];

__global__ void __launch_bounds__(512,1)
glu3_k(const float* __restrict__ hin,
       const __half* __restrict__ hin_h,     /* non-null: stage A from fp16 */
       const float* __restrict__ wi, const float* __restrict__ bi,
       const float* __restrict__ wo, const float* __restrict__ bo)
{
    char* SA = gsm2 + G3_SA;
    char* SB = gsm2 + G3_SB;
    float* sbi = (float*)(gsm2 + G3_SBI);
    float* sbo = (float*)(gsm2 + G3_SBO);
    int tid = threadIdx.x;

    for (int c = tid; c < 4096; c += 512){
        int n = c >> 4, ch = c & 15;
        const float* src = (n < 128) ? (wi + (size_t)n*128 + ch*8)
                                     : (wo + (size_t)(n-128)*128 + ch*8);
        *reinterpret_cast<uint4*>(SB + n*256 + ((ch ^ (n&7))<<4)) = pack8_f16(src);
    }
    if (tid < 128){ sbi[tid] = bi[tid]; sbo[tid] = bo[tid]; }

    int w = tid>>5, l = tid&31;
    uint32_t saB = smem_u32(SA);
    uint32_t sbB = smem_u32(SB);

    int a_row = (w<<4) + (l & 15);
    int er    = (w<<4) + (l>>2);

    for (int tile = blockIdx.x; tile < GT_TILES; tile += gridDim.x){
        int base = tile << 8;

        for (int c = tid; c < 4096; c += 512){
            int r = c >> 4, ch = c & 15;
            uint4 pw = make_uint4(0,0,0,0);
            if (base + r < NT){
                if (hin_h)
                    pw = *reinterpret_cast<const uint4*>(hin_h + (size_t)(base + r)*128 + ch*8);
                else
                    pw = pack8_f16(hin + (size_t)(base + r)*128 + ch*8);
            }
            *reinterpret_cast<uint4*>(SA + r*256 + ((ch ^ (r&7))<<4)) = pw;
        }
        __syncthreads();

        uint32_t Af[8][4];
        #pragma unroll
        for (int ks=0; ks<8; ks++){
            int kc = (ks<<1) + (l>>4);
            ldsm_x4(Af[ks], saB + a_row*256 + ((kc ^ (a_row&7))<<4));
        }

        #pragma unroll 1
        for (int nb=0; nb<16; nb++){
            int nrI = (nb<<3) + (l&7);
            int nrO = nrI + 128;
            uint32_t BI[16], BO[16];
            #pragma unroll
            for (int j=0;j<4;j++){
                int kc = (j<<2) + (l>>3);
                ldsm_x4(&BI[j<<2], sbB + nrI*256 + ((kc ^ (nrI&7))<<4));
                ldsm_x4(&BO[j<<2], sbB + nrO*256 + ((kc ^ (nrO&7))<<4));
            }
            float dI[4] = {0.f,0.f,0.f,0.f};
            float dO[4] = {0.f,0.f,0.f,0.f};
            #pragma unroll
            for (int ks=0; ks<8; ks++){
                mma16816h(dI, Af[ks], &BI[ks<<1]);
                mma16816h(dO, Af[ks], &BO[ks<<1]);
            }

            int c0 = (nb<<3) + ((l&3)<<1);
            float bi0 = sbi[c0], bi1 = sbi[c0+1];
            float bo0 = sbo[c0], bo1 = sbo[c0+1];
            int n0 = base + er;
            int n1 = n0 + 8;
            if (n0 < NT){
                float aI0 = dI[0] + bi0, aI1 = dI[1] + bi1;
                float ox = (dO[0] + bo0) / (1.f + expf(-aI0));
                float oy = (dO[1] + bo1) / (1.f + expf(-aI1));
                *reinterpret_cast<__half2*>(g_vh + (size_t)n0*128 + c0) = __floats2half2_rn(ox, oy);
            }
            if (n1 < NT){
                float aI2 = dI[2] + bi0, aI3 = dI[3] + bi1;
                float ox = (dO[2] + bo0) / (1.f + expf(-aI2));
                float oy = (dO[3] + bo1) / (1.f + expf(-aI3));
                *reinterpret_cast<__half2*>(g_vh + (size_t)n1*128 + c0) = __floats2half2_rn(ox, oy);
            }
        }
        __syncthreads();
    }
}

/* --------------- K^T V partials via mma.sync (deterministic) --------- */
#define KT_PAD 40
__global__ void __launch_bounds__(256,1)
kvredmma_k(){
    __shared__ __align__(16) __half SKt[64*KT_PAD];
    __shared__ __align__(16) __half SVt[128*KT_PAD];
    int b = blockIdx.y, ch = blockIdx.x;
    int tid = threadIdx.x, w = tid>>5, l = tid&31;
    uint32_t skB = smem_u32(SKt), svB = smem_u32(SVt);

    float acc[4][2][4];
    #pragma unroll
    for (int mt=0;mt<4;mt++)
        #pragma unroll
        for (int nb=0;nb<2;nb++)
            #pragma unroll
            for (int r=0;r<4;r++) acc[mt][nb][r] = 0.f;

    int nb0 = ch*CHSZ;
    #pragma unroll 1
    for (int c0=0; c0<CHSZ; c0+=32){
        int nbase = nb0 + c0;
        {
            int node = tid & 31, rg = tid >> 5;
            int n = nbase + node;
            if (n < NN){
                const __half2* s2 = (const __half2*)(g_kh + ((size_t)(b*NN+n))*64 + rg*8);
                #pragma unroll
                for (int j=0;j<4;j++){
                    __half2 p = s2[j];
                    SKt[(rg*8 + 2*j  )*KT_PAD + node] = __low2half(p);
                    SKt[(rg*8 + 2*j+1)*KT_PAD + node] = __high2half(p);
                }
            } else {
                #pragma unroll
                for (int j=0;j<4;j++){
                    SKt[(rg*8 + 2*j  )*KT_PAD + node] = __float2half(0.f);
                    SKt[(rg*8 + 2*j+1)*KT_PAD + node] = __float2half(0.f);
                }
            }
        }
        {
            int node = tid & 31, hg = tid >> 5;
            int n = nbase + node;
            if (n < NN){
                const __half2* s2 = (const __half2*)(g_vh + ((size_t)(b*NN+n))*128 + hg*16);
                #pragma unroll
                for (int j=0;j<8;j++){
                    __half2 p = s2[j];
                    SVt[(hg*16 + 2*j  )*KT_PAD + node] = __low2half(p);
                    SVt[(hg*16 + 2*j+1)*KT_PAD + node] = __high2half(p);
                }
            } else {
                #pragma unroll
                for (int j=0;j<8;j++){
                    SVt[(hg*16 + 2*j  )*KT_PAD + node] = __float2half(0.f);
                    SVt[(hg*16 + 2*j+1)*KT_PAD + node] = __float2half(0.f);
                }
            }
        }
        __syncthreads();

        uint32_t Bv[2][4];
        #pragma unroll
        for (int nb=0;nb<2;nb++){
            int row = w*16 + nb*8 + (l&7);
            ldsm_x4(Bv[nb], svB + row*(KT_PAD*2) + ((l>>3)<<4));
        }
        #pragma unroll
        for (int ks=0; ks<2; ks++){
            uint32_t Af[4][4];
            #pragma unroll
            for (int mt=0;mt<4;mt++){
                int row = mt*16 + (l&15);
                ldsm_x4(Af[mt], skB + row*(KT_PAD*2) + (((ks<<1) + (l>>4))<<4));
            }
            #pragma unroll
            for (int mt=0;mt<4;mt++){
                mma16816h(acc[mt][0], Af[mt], &Bv[0][ks<<1]);
                mma16816h(acc[mt][1], Af[mt], &Bv[1][ks<<1]);
            }
        }
        __syncthreads();
    }

    size_t pb = (size_t)(b*CH+ch);
    #pragma unroll
    for (int mt=0;mt<4;mt++){
        #pragma unroll
        for (int nb=0;nb<2;nb++){
            int rf0 = mt*16 + (l>>2);
            int hd = w*16 + nb*8 + 2*(l&3);
            float2 v0 = make_float2(acc[mt][nb][0], acc[mt][nb][1]);
            float2 v1 = make_float2(acc[mt][nb][2], acc[mt][nb][3]);
            *reinterpret_cast<float2*>(&g_part[(pb*64 + rf0    )*128 + hd]) = v0;
            *reinterpret_cast<float2*>(&g_part[(pb*64 + rf0 + 8)*128 + hd]) = v1;
        }
    }
}

__global__ void vred_k(){
    int idx = blockIdx.x*256 + threadIdx.x;
    int b = idx >> 13;
    int rem = idx & 8191;
    int m = rem >> 7, d = rem & 127;
    float s = 0.f;
    for (int ch=0; ch<CH; ch++)
        s += g_part[((size_t)(b*CH+ch)*64 + m)*128 + d];
    g_v2x[((size_t)b*64 + m)*128 + d] = s;
}

/* ---------- attention out via mma + residual + layernorm -------------
 * Per block: 64 nodes.  D[64x136] = qh[64x64] . v2xT[136x64]^T where
 * v2xT rows 0..127 = hd (x1/16), row 128 = ksum (x1/16), 129..135 = 0.
 * Scale cancels in out1/out2 ratio.  D staged to smem for LN epilogue.
 */
#define AT_TOT (36864 + 1024)
extern __shared__ char gsm3[];

__global__ void __launch_bounds__(256,1)
attn2_k(int store_h16, const float* __restrict__ res_in,
        const float* __restrict__ lg, const float* __restrict__ lb)
{
    char* SQ = gsm3;               /* 64 rows x 128 B  = 8192  */
    char* SV = gsm3 + 8192;        /* 136 rows x 128 B = 17408 */
    float* sD = (float*)gsm3;      /* reuse: 64 x 144 f32 = 36864 */
    float* sg = (float*)(gsm3 + 36864);
    float* sb = sg + 128;

    int b = blockIdx.y;
    int tid = threadIdx.x, w = tid>>5, l = tid&31;
    int nb0 = blockIdx.x*64;

    if (tid < 128) sg[tid] = lg[tid];
    else           sb[tid-128] = lb[tid-128];

    /* stage q (fp16 direct copy) */
    for (int c = tid; c < 512; c += 256){
        int nd = c>>3, ch = c&7;
        int n = nb0 + nd;
        uint4 v = make_uint4(0,0,0,0);
        if (n < NN)
            v = *reinterpret_cast<const uint4*>(g_qh + ((size_t)(b*NN+n))*64 + ch*8);
        *reinterpret_cast<uint4*>(SQ + nd*128 + ((ch ^ (nd&7))<<4)) = v;
    }
    /* stage v2xT (fp16, x1/16): row=hd (0..127), 128=ksum, 129..135=0 */
    for (int c = tid; c < 1088; c += 256){
        int row = c>>3, ch = c&7;
        __half hv[8];
        if (row < 128){
            #pragma unroll
            for (int j=0;j<8;j++)
                hv[j] = __float2half(g_v2x[(size_t)b*8192 + (ch*8+j)*128 + row] * 0.0625f);
        } else if (row == 128){
            #pragma unroll
            for (int j=0;j<8;j++)
                hv[j] = __float2half(g_ksum[b*64 + ch*8 + j] * 0.0625f);
        } else {
            #pragma unroll
            for (int j=0;j<8;j++) hv[j] = __float2half(0.f);
        }
        *reinterpret_cast<uint4*>(SV + row*128 + ((ch ^ (row&7))<<4)) =
            *reinterpret_cast<uint4*>(hv);
    }
    __syncthreads();

    uint32_t sqB = smem_u32(SQ), svB = smem_u32(SV);
    int mt = w & 3, nh = w >> 2;
    int nblocks = nh ? 9 : 8;

    uint32_t Af[4][4];
    #pragma unroll
    for (int ks=0; ks<4; ks++){
        int ar = mt*16 + (l&15);
        int kc = ks*2 + (l>>4);
        ldsm_x4(Af[ks], sqB + ar*128 + ((kc ^ (ar&7))<<4));
    }

    float d[9][4];
    #pragma unroll
    for (int nb=0;nb<9;nb++){ d[nb][0]=0.f; d[nb][1]=0.f; d[nb][2]=0.f; d[nb][3]=0.f; }

    #pragma unroll 1
    for (int nb=0; nb<nblocks; nb++){
        int br = nh*64 + nb*8 + (l&7);
        uint32_t Bv[2][4];
        #pragma unroll
        for (int h=0; h<2; h++){
            int kc = h*4 + (l>>3);
            ldsm_x4(Bv[h], svB + br*128 + ((kc ^ (br&7))<<4));
        }
        #pragma unroll
        for (int ks=0; ks<4; ks++)
            mma16816h(d[nb], Af[ks], &Bv[ks>>1][(ks&1)<<1]);
    }
    __syncthreads();            /* all SQ/SV reads done; sD overlays */

    #pragma unroll 1
    for (int nb=0; nb<nblocks; nb++){
        int col = nh*64 + nb*8 + 2*(l&3);
        int row0 = mt*16 + (l>>2);
        *reinterpret_cast<float2*>(&sD[row0*144 + col])     = make_float2(d[nb][0], d[nb][1]);
        *reinterpret_cast<float2*>(&sD[(row0+8)*144 + col]) = make_float2(d[nb][2], d[nb][3]);
    }
    __syncthreads();

    float4 g4 = ((float4*)sg)[l];
    float4 b4 = ((float4*)sb)[l];
    #pragma unroll 1
    for (int nd=0; nd<8; nd++){
        int ln = w*8 + nd;
        int n = nb0 + ln;
        if (n >= NN) continue;          /* warp-uniform */
        size_t i = (size_t)b*NN + n;
        float inv = 1.f / sD[ln*144 + 128];
        float4 acc = *reinterpret_cast<float4*>(&sD[ln*144 + l*4]);
        float4 res = ((const float4*)res_in)[i*32 + l];
        float4 t;
        t.x = fmaf(acc.x, inv, res.x);
        t.y = fmaf(acc.y, inv, res.y);
        t.z = fmaf(acc.z, inv, res.z);
        t.w = fmaf(acc.w, inv, res.w);
        float mu = warpSum(t.x+t.y+t.z+t.w) * (1.f/128.f);
        float dx=t.x-mu, dy=t.y-mu, dz=t.z-mu, dw=t.w-mu;
        float var = warpSum(dx*dx+dy*dy+dz*dz+dw*dw) * (1.f/128.f);
        float rs = rsqrtf(var + EPSLN);
        float4 o;
        o.x = dx*rs*g4.x + b4.x;
        o.y = dy*rs*g4.y + b4.y;
        o.z = dz*rs*g4.z + b4.z;
        o.w = dw*rs*g4.w + b4.w;
        ((float4*)g_h)[i*32 + l] = o;
        if (store_h16){
            __half2 p0 = __floats2half2_rn(o.x, o.y);
            __half2 p1 = __floats2half2_rn(o.z, o.w);
            uint2 u;
            u.x = *reinterpret_cast<uint32_t*>(&p0);
            u.y = *reinterpret_cast<uint32_t*>(&p1);
            *reinterpret_cast<uint2*>(g_hh + i*128 + l*4) = u;
        }
    }
}

/* -------- relu(concat(h0,h)) @ W_reg.T + b_reg, transposed out ------- */
__global__ void final_k(const float* __restrict__ Wreg, const float* __restrict__ breg,
                        float* __restrict__ out)
{
    __shared__ float sWrT[256*12];
    __shared__ float sbr[12];
    int tid = threadIdx.x;
    for (int t=tid; t<3072; t+=256){ int to=t>>8, j=t&255; sWrT[j*12+to] = Wreg[t]; }
    if (tid<12) sbr[tid] = breg[tid];
    __syncthreads();

    int w = tid>>5, l = tid&31;
    int i = blockIdx.x*8 + w;
    int b = i / NN;
    int n = i - b*NN;
    size_t hb = (size_t)i*128;

    float acc[12];
    #pragma unroll
    for (int t=0;t<12;t++) acc[t]=0.f;

    #pragma unroll
    for (int c=0;c<8;c++){
        int j = c*32 + l;
        float vIn = (j < 128) ? g_h0[hb + j] : g_h[hb + j - 128];
        vIn = fmaxf(vIn, 0.f);
        #pragma unroll
        for (int t=0;t<12;t++) acc[t] = fmaf(vIn, sWrT[j*12+t], acc[t]);
    }
    #pragma unroll
    for (int t=0;t<12;t++) acc[t] = warpSum(acc[t]);
    if (l < 12) out[((size_t)b*12 + l)*NN + n] = acc[l] + sbr[l];
}

/* ------------------------------ launch ------------------------------- */
extern "C" void kernel_launch(void* const* d_in, const int* in_sizes, int n_in,
                              void* d_out, int out_size)
{
    const float* x        = (const float*)d_in[0];
    const float* node_emb = (const float*)d_in[1];
    const float* time_emb = (const float*)d_in[2];
    const float* week_emb = (const float*)d_in[3];
    const float* Win      = (const float*)d_in[4];
    const float* bin      = (const float*)d_in[5];
    const float* W1       = (const float*)d_in[6];
    const float* b1       = (const float*)d_in[7];
    const float* W2       = (const float*)d_in[8];
    const float* b2       = (const float*)d_in[9];
    const float* Wreg     = (const float*)d_in[10];
    const float* breg     = (const float*)d_in[11];
    const float* proj     = (const float*)d_in[12];

    cudaFuncSetAttribute(glu3_k, cudaFuncAttributeMaxDynamicSharedMemorySize, G3_TOT);

    float*  g_h_ptr;  cudaGetSymbolAddress((void**)&g_h_ptr,  g_h);
    float*  g_h0_ptr; cudaGetSymbolAddress((void**)&g_h0_ptr, g_h0);
    __half* g_hh_ptr; cudaGetSymbolAddress((void**)&g_hh_ptr, g_hh);

    initmx_k<<<1,32>>>();
    pre_small_k<<<37,256>>>(time_emb, week_emb, W1, b1, W2, b2, proj);
    pre_node_k<<<NN/8,256>>>(node_emb, W1, W2, proj);
    phase1_k<<<NT/32,256>>>(x, node_emb, time_emb, week_emb, Win, bin);
    computek2_k<<<dim3(CH,NB),256>>>();
    ksumr_k<<<1,256>>>();

    for (int layer=0; layer<2; layer++){
        const float* wi = (const float*)d_in[13 + layer*6 + 0];
        const float* bi = (const float*)d_in[13 + layer*6 + 1];
        const float* wo = (const float*)d_in[13 + layer*6 + 2];
        const float* bo = (const float*)d_in[13 + layer*6 + 3];
        const float* lg = (const float*)d_in[13 + layer*6 + 4];
        const float* lb = (const float*)d_in[13 + layer*6 + 5];

        const float*  hin   = (layer == 0) ? g_h0_ptr : g_h_ptr;
        const __half* hin_h = (layer == 0) ? (const __half*)0 : g_hh_ptr;

        glu3_k<<<148,512,G3_TOT>>>(hin, hin_h, wi, bi, wo, bo);
        kvredmma_k<<<dim3(CH,NB),256>>>();
        vred_k<<<128,256>>>();
        attn2_k<<<dim3((NN+63)/64,NB),256,AT_TOT>>>((layer==0)?1:0, hin, lg, lb);
    }

    final_k<<<NT/8,256>>>(Wreg, breg, (float*)d_out);
}

// round 15
// speedup vs baseline: 1.5016x; 1.0639x over previous
#include <cuda_runtime.h>
#include <cuda_bf16.h>
#include <cuda_fp16.h>
#include <math.h>
#include <stdint.h>

#define NB 4
#define NN 50000
#define NT (NB*NN)
#define H4 128
#define RF 64
#define CH 98
#define CHSZ 512

#define ALPHA 0.4204482076268573f   /* 32^-0.25 */
#define RATIO 0.125f                /* 1/sqrt(64) */
#define EPSRF 1e-6f
#define EPSLN 1e-5f

/* ------------------------------ scratch ------------------------------ */
__device__ float  g_h0[(size_t)NT*H4];
__device__ __align__(16) __half g_hh[(size_t)NT*H4];
__device__ __align__(16) __half g_vh[(size_t)NT*H4];
__device__ __align__(16) __half g_qh[(size_t)NT*RF];
__device__ float  g_diag2[NT];
__device__ int    g_idx[NT];
__device__ __align__(16) __half g_kh[(size_t)NT*RF];
__device__ int    g_mx[NB];
__device__ float  g_part [(size_t)NB*CH*RF*H4];
__device__ float  g_kpart[(size_t)NB*CH*RF];
__device__ __align__(16) __half g_v2xh[(size_t)NB*136*RF];
__device__ float  g_ksum[NB*RF];
/* precomputed LUTs */
__device__ float  g_a1n[(size_t)NN*32], g_a2n[(size_t)NN*32];
__device__ float  g_d1n[(size_t)NN*64], g_d2n[(size_t)NN*64];
__device__ float  g_a1t[288*32], g_a2t[288*32];
__device__ float  g_d1t[288*64], g_d2t[288*64];
__device__ float  g_a1w[7*32],  g_a2w[7*32];
__device__ float  g_d1w[7*64],  g_d2w[7*64];
__device__ float  g_a1b[32],    g_a2b[32];
__device__ float  g_d1b[64],    g_d2b[64];

/* ------------------------------ helpers ------------------------------ */
__device__ __forceinline__ float warpSum(float v){
    #pragma unroll
    for (int o=16;o;o>>=1) v += __shfl_xor_sync(0xffffffffu, v, o);
    return v;
}
__device__ __forceinline__ float warpMax(float v){
    #pragma unroll
    for (int o=16;o;o>>=1) v = fmaxf(v, __shfl_xor_sync(0xffffffffu, v, o));
    return v;
}
__device__ __forceinline__ int f2ord(float f){
    int i = __float_as_int(f);
    return (i >= 0) ? i : (i ^ 0x7FFFFFFF);
}
__device__ __forceinline__ float ord2f(int i){
    return __int_as_float((i >= 0) ? i : (i ^ 0x7FFFFFFF));
}

/* --------------------- mma.sync helpers ------------------------------ */
__device__ __forceinline__ uint32_t smem_u32(const void* p){
    uint32_t a;
    asm("{ .reg .u64 t; cvta.to.shared.u64 t, %1; cvt.u32.u64 %0, t; }"
        : "=r"(a) : "l"(p));
    return a;
}
__device__ __forceinline__ void ldsm_x4(uint32_t* r, uint32_t addr){
    asm volatile("ldmatrix.sync.aligned.m8n8.x4.shared.b16 {%0,%1,%2,%3}, [%4];"
        : "=r"(r[0]), "=r"(r[1]), "=r"(r[2]), "=r"(r[3]) : "r"(addr));
}
__device__ __forceinline__ void mma16816h(float* d, const uint32_t* a, const uint32_t* b){
    asm volatile("mma.sync.aligned.m16n8k16.row.col.f32.f16.f16.f32 "
        "{%0,%1,%2,%3}, {%4,%5,%6,%7}, {%8,%9}, {%0,%1,%2,%3};"
        : "+f"(d[0]), "+f"(d[1]), "+f"(d[2]), "+f"(d[3])
        : "r"(a[0]), "r"(a[1]), "r"(a[2]), "r"(a[3]), "r"(b[0]), "r"(b[1]));
}
__device__ __forceinline__ uint4 pack8_f16(const float* src){
    float4 a = ((const float4*)src)[0];
    float4 b = ((const float4*)src)[1];
    __half2 p0 = __floats2half2_rn(a.x, a.y);
    __half2 p1 = __floats2half2_rn(a.z, a.w);
    __half2 p2 = __floats2half2_rn(b.x, b.y);
    __half2 p3 = __floats2half2_rn(b.z, b.w);
    uint4 w;
    w.x = *reinterpret_cast<uint32_t*>(&p0);
    w.y = *reinterpret_cast<uint32_t*>(&p1);
    w.z = *reinterpret_cast<uint32_t*>(&p2);
    w.w = *reinterpret_cast<uint32_t*>(&p3);
    return w;
}

/* ------------------------------ init --------------------------------- */
__global__ void initmx_k(){
    if (threadIdx.x < NB) g_mx[threadIdx.x] = (int)0x80000000;
}

/* ------------- LUT precompute: time/week/bias (296 entries) ---------- */
__global__ void pre_small_k(const float* __restrict__ time_emb,
                            const float* __restrict__ week_emb,
                            const float* __restrict__ W1, const float* __restrict__ b1,
                            const float* __restrict__ W2, const float* __restrict__ b2,
                            const float* __restrict__ proj)
{
    __shared__ float sT1[32*32], sU1[32*32], sT2[32*32], sU2[32*32];
    __shared__ float sprojT[32*64];
    __shared__ float sv[8][32], snv[8][32];
    int tid = threadIdx.x;
    for (int t=tid; t<1024; t+=256){
        int h=t>>5, d=t&31;
        sT1[d*32+h] = W1[h*96 + 32 + d];
        sU1[d*32+h] = W1[h*96 + 64 + d];
        sT2[d*32+h] = W2[h*96 + 32 + d];
        sU2[d*32+h] = W2[h*96 + 64 + d];
    }
    for (int t=tid; t<2048; t+=256){ int m=t>>5, d=t&31; sprojT[d*64+m] = proj[m*32+d]; }
    __syncthreads();

    int w = tid>>5, l = tid&31;
    int e = blockIdx.x*8 + w;
    if (e >= 296) return;

    float a1, a2;
    float *A1, *A2, *D1, *D2;
    if (e < 288){
        sv[w][l] = time_emb[e*32 + l]; __syncwarp();
        a1 = 0.f; a2 = 0.f;
        #pragma unroll
        for (int d=0; d<32; d++){
            float v = sv[w][d];
            a1 = fmaf(sT1[d*32+l], v, a1);
            a2 = fmaf(sT2[d*32+l], v, a2);
        }
        A1 = g_a1t + e*32; A2 = g_a2t + e*32;
        D1 = g_d1t + e*64; D2 = g_d2t + e*64;
    } else if (e < 295){
        int k = e - 288;
        sv[w][l] = week_emb[k*32 + l]; __syncwarp();
        a1 = 0.f; a2 = 0.f;
        #pragma unroll
        for (int d=0; d<32; d++){
            float v = sv[w][d];
            a1 = fmaf(sU1[d*32+l], v, a1);
            a2 = fmaf(sU2[d*32+l], v, a2);
        }
        A1 = g_a1w + k*32; A2 = g_a2w + k*32;
        D1 = g_d1w + k*64; D2 = g_d2w + k*64;
    } else {
        a1 = b1[l]; a2 = b2[l];
        A1 = g_a1b; A2 = g_a2b; D1 = g_d1b; D2 = g_d2b;
    }
    a1 *= ALPHA; a2 *= ALPHA;
    A1[l] = a1; A2[l] = a2;

    snv[w][l] = a1; __syncwarp();
    float d0=0.f, d1=0.f;
    #pragma unroll
    for (int dd=0; dd<32; dd++){
        float f = snv[w][dd];
        d0 = fmaf(f, sprojT[dd*64+l],    d0);
        d1 = fmaf(f, sprojT[dd*64+32+l], d1);
    }
    D1[l] = d0; D1[32+l] = d1;
    __syncwarp();
    snv[w][l] = a2; __syncwarp();
    d0=0.f; d1=0.f;
    #pragma unroll
    for (int dd=0; dd<32; dd++){
        float f = snv[w][dd];
        d0 = fmaf(f, sprojT[dd*64+l],    d0);
        d1 = fmaf(f, sprojT[dd*64+32+l], d1);
    }
    D2[l] = d0; D2[32+l] = d1;
}

/* ------------- LUT precompute: per-node (50000 entries) -------------- */
__global__ void pre_node_k(const float* __restrict__ node_emb,
                           const float* __restrict__ W1, const float* __restrict__ W2,
                           const float* __restrict__ proj)
{
    __shared__ float sW1T[32*32], sW2T[32*32];
    __shared__ float sprojT[32*64];
    __shared__ float sne[8][32], snv[8][32];
    int tid = threadIdx.x;
    for (int t=tid; t<1024; t+=256){
        int h=t>>5, d=t&31;
        sW1T[d*32+h] = W1[h*96 + d];
        sW2T[d*32+h] = W2[h*96 + d];
    }
    for (int t=tid; t<2048; t+=256){ int m=t>>5, d=t&31; sprojT[d*64+m] = proj[m*32+d]; }
    __syncthreads();

    int w = tid>>5, l = tid&31;
    int n = blockIdx.x*8 + w;

    sne[w][l] = node_emb[n*32 + l]; __syncwarp();
    float a1 = 0.f, a2 = 0.f;
    #pragma unroll
    for (int d=0; d<32; d++){
        float v = sne[w][d];
        a1 = fmaf(sW1T[d*32+l], v, a1);
        a2 = fmaf(sW2T[d*32+l], v, a2);
    }
    a1 *= ALPHA; a2 *= ALPHA;
    g_a1n[(size_t)n*32 + l] = a1;
    g_a2n[(size_t)n*32 + l] = a2;

    snv[w][l] = a1; __syncwarp();
    float d0=0.f, d1=0.f;
    #pragma unroll
    for (int dd=0; dd<32; dd++){
        float f = snv[w][dd];
        d0 = fmaf(f, sprojT[dd*64+l],    d0);
        d1 = fmaf(f, sprojT[dd*64+32+l], d1);
    }
    g_d1n[(size_t)n*64 + l] = d0;
    g_d1n[(size_t)n*64 + 32 + l] = d1;
    __syncwarp();
    snv[w][l] = a2; __syncwarp();
    d0=0.f; d1=0.f;
    #pragma unroll
    for (int dd=0; dd<32; dd++){
        float f = snv[w][dd];
        d0 = fmaf(f, sprojT[dd*64+l],    d0);
        d1 = fmaf(f, sprojT[dd*64+32+l], d1);
    }
    g_d2n[(size_t)n*64 + l] = d0;
    g_d2n[(size_t)n*64 + 32 + l] = d1;
}

/* --------------------------- phase 1 (LUT, 4 nodes/warp) ------------- */
__global__ void phase1_k(const float* __restrict__ x,
                         const float* __restrict__ node_emb,
                         const float* __restrict__ time_emb,
                         const float* __restrict__ week_emb,
                         const float* __restrict__ Win, const float* __restrict__ bin)
{
    __shared__ float sW4[9*128];
    __shared__ float sbin[32];
    __shared__ float sxv[8][160];
    __shared__ int   sbmax[NB];

    int tid = threadIdx.x;
    for (int t=tid; t<1152; t+=256){
        int h=t/36, j=t%36;
        sW4[(j>>2)*128 + h*4 + (j&3)] = Win[t];
    }
    if (tid<32) sbin[tid]=bin[tid];
    if (tid<NB) sbmax[tid] = (int)0x80000000;
    __syncthreads();

    int w = tid>>5, l = tid&31;
    int i0 = (blockIdx.x*8 + w)*4;
    int b = i0 / NN;

    const float* xr = x + (size_t)i0*36;
    for (int idx=l; idx<144; idx+=32){
        int nd = idx/36, j = idx - nd*36;
        sxv[w][nd*40 + j] = xr[idx];
    }
    __syncwarp();

    float inp[4];
    #pragma unroll
    for (int nd=0; nd<4; nd++) inp[nd] = sbin[l];
    #pragma unroll
    for (int j4=0; j4<9; j4++){
        float4 w4 = ((float4*)sW4)[j4*32 + l];
        #pragma unroll
        for (int nd=0; nd<4; nd++){
            float4 x4 = *reinterpret_cast<float4*>(&sxv[w][nd*40 + j4*4]);
            inp[nd] = fmaf(w4.x, x4.x,
                      fmaf(w4.y, x4.y,
                      fmaf(w4.z, x4.z,
                      fmaf(w4.w, x4.w, inp[nd]))));
        }
    }

    float wmax = -1e30f;
    #pragma unroll 1
    for (int nd=0; nd<4; nd++){
        int i = i0 + nd;
        int n = i - b*NN;
        int ti = (int)(sxv[w][nd*40+34]*288.0f); ti = min(max(ti,0),287);
        int wk = (int)(sxv[w][nd*40+35]);        wk = min(max(wk,0),6);

        float ne = node_emb[n*32+l];
        float te = time_emb[ti*32+l];
        float we = week_emb[wk*32+l];
        size_t hb = (size_t)i*128;
        g_h0[hb+l]=inp[nd]; g_h0[hb+32+l]=ne; g_h0[hb+64+l]=te; g_h0[hb+96+l]=we;

        float a1 = g_a1n[(size_t)n*32+l] + g_a1t[ti*32+l] + g_a1w[wk*32+l] + g_a1b[l];
        float diag1 = 0.5f * warpSum(a1*a1);
        float d0 = g_d1n[(size_t)n*64+l]    + g_d1t[ti*64+l]    + g_d1w[wk*64+l]    + g_d1b[l];
        float d1 = g_d1n[(size_t)n*64+32+l] + g_d1t[ti*64+32+l] + g_d1w[wk*64+32+l] + g_d1b[32+l];
        float mx1 = warpMax(fmaxf(d0,d1));
        g_qh[(size_t)i*64 + l]      = __float2half(RATIO*(expf(d0 - diag1 - mx1) + EPSRF));
        g_qh[(size_t)i*64 + 32 + l] = __float2half(RATIO*(expf(d1 - diag1 - mx1) + EPSRF));

        float a2 = g_a2n[(size_t)n*32+l] + g_a2t[ti*32+l] + g_a2w[wk*32+l] + g_a2b[l];
        float diag2 = 0.5f * warpSum(a2*a2);
        d0 = g_d2n[(size_t)n*64+l]    + g_d2t[ti*64+l]    + g_d2w[wk*64+l]    + g_d2b[l];
        d1 = g_d2n[(size_t)n*64+32+l] + g_d2t[ti*64+32+l] + g_d2w[wk*64+32+l] + g_d2b[32+l];
        if (l==0){
            g_diag2[i] = diag2;
            g_idx[i]   = ti*8 + wk;
        }
        wmax = fmaxf(wmax, fmaxf(d0,d1));
    }

    float m = warpMax(wmax);
    if (l==0) atomicMax(&sbmax[b], f2ord(m));

    __syncthreads();
    if (tid < NB && sbmax[tid] != (int)0x80000000)
        atomicMax(&g_mx[tid], sbmax[tid]);
}

/* ---------- fused k features + ksum partials (LUT recompute) --------- */
__global__ void __launch_bounds__(256,1)
computek2_k(){
    __shared__ float sd2b[64];
    __shared__ int   sidx[CHSZ];
    __shared__ float sdiag[CHSZ];
    __shared__ float red[4][64];

    int b = blockIdx.y, ch = blockIdx.x;
    int tid = threadIdx.x;
    int m = tid & 63, part = tid >> 6;
    int nb0 = ch*CHSZ;

    if (tid < 64) sd2b[tid] = g_d2b[tid];
    for (int t=tid; t<CHSZ; t+=256){
        int n = nb0 + t;
        if (n < NN){
            sidx[t]  = g_idx[b*NN + n];
            sdiag[t] = g_diag2[b*NN + n];
        } else { sidx[t] = 0; sdiag[t] = 0.f; }
    }
    __syncthreads();

    float mx = ord2f(g_mx[b]);
    float s = 0.f;
    int tb = part*128;
    #pragma unroll 2
    for (int nn=0; nn<128; nn++){
        int t = tb + nn;
        int n = nb0 + t;
        if (n < NN){
            int iv = sidx[t];
            int ti = iv >> 3, wk = iv & 7;
            float dv = g_d2n[(size_t)n*64 + m] + g_d2t[ti*64 + m]
                     + g_d2w[wk*64 + m] + sd2b[m];
            float val = RATIO*(expf(dv - sdiag[t] - mx) + EPSRF);
            g_kh[((size_t)(b*NN+n))*64 + m] = __float2half(val);
            s += val;
        }
    }
    red[part][m] = s;
    __syncthreads();
    if (part == 0){
        float t = red[0][m] + red[1][m] + red[2][m] + red[3][m];
        g_kpart[(size_t)(b*CH+ch)*64 + m] = t;
    }
}

__global__ void ksumr_k(){
    int tid = threadIdx.x;
    int b = tid >> 6, m = tid & 63;
    float s = 0.f;
    for (int ch=0; ch<CH; ch++)
        s += g_kpart[(size_t)(b*CH+ch)*64 + m];
    g_ksum[b*64 + m] = s;
}

/* ------------------------- GLU via mma.sync (fp16) ------------------- */
#define GT_TILES ((NT + 255)/256)
#define G3_SA   0
#define G3_SB   65536
#define G3_SBI  131072
#define G3_SBO  131584
#define G3_TOT  132096

extern __shared__ char gsm2[];

__global__ void __launch_bounds__(512,1)
glu3_k(const float* __restrict__ hin,
       const __half* __restrict__ hin_h,     /* non-null: stage A from fp16 */
       const float* __restrict__ wi, const float* __restrict__ bi,
       const float* __restrict__ wo, const float* __restrict__ bo)
{
    char* SA = gsm2 + G3_SA;
    char* SB = gsm2 + G3_SB;
    float* sbi = (float*)(gsm2 + G3_SBI);
    float* sbo = (float*)(gsm2 + G3_SBO);
    int tid = threadIdx.x;

    for (int c = tid; c < 4096; c += 512){
        int n = c >> 4, ch = c & 15;
        const float* src = (n < 128) ? (wi + (size_t)n*128 + ch*8)
                                     : (wo + (size_t)(n-128)*128 + ch*8);
        *reinterpret_cast<uint4*>(SB + n*256 + ((ch ^ (n&7))<<4)) = pack8_f16(src);
    }
    if (tid < 128){ sbi[tid] = bi[tid]; sbo[tid] = bo[tid]; }

    int w = tid>>5, l = tid&31;
    uint32_t saB = smem_u32(SA);
    uint32_t sbB = smem_u32(SB);

    int a_row = (w<<4) + (l & 15);
    int er    = (w<<4) + (l>>2);

    for (int tile = blockIdx.x; tile < GT_TILES; tile += gridDim.x){
        int base = tile << 8;

        for (int c = tid; c < 4096; c += 512){
            int r = c >> 4, ch = c & 15;
            uint4 pw = make_uint4(0,0,0,0);
            if (base + r < NT){
                if (hin_h)
                    pw = *reinterpret_cast<const uint4*>(hin_h + (size_t)(base + r)*128 + ch*8);
                else
                    pw = pack8_f16(hin + (size_t)(base + r)*128 + ch*8);
            }
            *reinterpret_cast<uint4*>(SA + r*256 + ((ch ^ (r&7))<<4)) = pw;
        }
        __syncthreads();

        uint32_t Af[8][4];
        #pragma unroll
        for (int ks=0; ks<8; ks++){
            int kc = (ks<<1) + (l>>4);
            ldsm_x4(Af[ks], saB + a_row*256 + ((kc ^ (a_row&7))<<4));
        }

        #pragma unroll 1
        for (int nb=0; nb<16; nb++){
            int nrI = (nb<<3) + (l&7);
            int nrO = nrI + 128;
            uint32_t BI[16], BO[16];
            #pragma unroll
            for (int j=0;j<4;j++){
                int kc = (j<<2) + (l>>3);
                ldsm_x4(&BI[j<<2], sbB + nrI*256 + ((kc ^ (nrI&7))<<4));
                ldsm_x4(&BO[j<<2], sbB + nrO*256 + ((kc ^ (nrO&7))<<4));
            }
            float dI[4] = {0.f,0.f,0.f,0.f};
            float dO[4] = {0.f,0.f,0.f,0.f};
            #pragma unroll
            for (int ks=0; ks<8; ks++){
                mma16816h(dI, Af[ks], &BI[ks<<1]);
                mma16816h(dO, Af[ks], &BO[ks<<1]);
            }

            int c0 = (nb<<3) + ((l&3)<<1);
            float bi0 = sbi[c0], bi1 = sbi[c0+1];
            float bo0 = sbo[c0], bo1 = sbo[c0+1];
            int n0 = base + er;
            int n1 = n0 + 8;
            if (n0 < NT){
                float aI0 = dI[0] + bi0, aI1 = dI[1] + bi1;
                float ox = (dO[0] + bo0) / (1.f + expf(-aI0));
                float oy = (dO[1] + bo1) / (1.f + expf(-aI1));
                *reinterpret_cast<__half2*>(g_vh + (size_t)n0*128 + c0) = __floats2half2_rn(ox, oy);
            }
            if (n1 < NT){
                float aI2 = dI[2] + bi0, aI3 = dI[3] + bi1;
                float ox = (dO[2] + bo0) / (1.f + expf(-aI2));
                float oy = (dO[3] + bo1) / (1.f + expf(-aI3));
                *reinterpret_cast<__half2*>(g_vh + (size_t)n1*128 + c0) = __floats2half2_rn(ox, oy);
            }
        }
        __syncthreads();
    }
}

/* --------------- K^T V partials via mma.sync (deterministic) --------- */
#define KT_PAD 40
__global__ void __launch_bounds__(256,1)
kvredmma_k(){
    __shared__ __align__(16) __half SKt[64*KT_PAD];
    __shared__ __align__(16) __half SVt[128*KT_PAD];
    int b = blockIdx.y, ch = blockIdx.x;
    int tid = threadIdx.x, w = tid>>5, l = tid&31;
    uint32_t skB = smem_u32(SKt), svB = smem_u32(SVt);

    float acc[4][2][4];
    #pragma unroll
    for (int mt=0;mt<4;mt++)
        #pragma unroll
        for (int nb=0;nb<2;nb++)
            #pragma unroll
            for (int r=0;r<4;r++) acc[mt][nb][r] = 0.f;

    int nb0 = ch*CHSZ;
    #pragma unroll 1
    for (int c0=0; c0<CHSZ; c0+=32){
        int nbase = nb0 + c0;
        {
            int node = tid & 31, rg = tid >> 5;
            int n = nbase + node;
            if (n < NN){
                const __half2* s2 = (const __half2*)(g_kh + ((size_t)(b*NN+n))*64 + rg*8);
                #pragma unroll
                for (int j=0;j<4;j++){
                    __half2 p = s2[j];
                    SKt[(rg*8 + 2*j  )*KT_PAD + node] = __low2half(p);
                    SKt[(rg*8 + 2*j+1)*KT_PAD + node] = __high2half(p);
                }
            } else {
                #pragma unroll
                for (int j=0;j<4;j++){
                    SKt[(rg*8 + 2*j  )*KT_PAD + node] = __float2half(0.f);
                    SKt[(rg*8 + 2*j+1)*KT_PAD + node] = __float2half(0.f);
                }
            }
        }
        {
            int node = tid & 31, hg = tid >> 5;
            int n = nbase + node;
            if (n < NN){
                const __half2* s2 = (const __half2*)(g_vh + ((size_t)(b*NN+n))*128 + hg*16);
                #pragma unroll
                for (int j=0;j<8;j++){
                    __half2 p = s2[j];
                    SVt[(hg*16 + 2*j  )*KT_PAD + node] = __low2half(p);
                    SVt[(hg*16 + 2*j+1)*KT_PAD + node] = __high2half(p);
                }
            } else {
                #pragma unroll
                for (int j=0;j<8;j++){
                    SVt[(hg*16 + 2*j  )*KT_PAD + node] = __float2half(0.f);
                    SVt[(hg*16 + 2*j+1)*KT_PAD + node] = __float2half(0.f);
                }
            }
        }
        __syncthreads();

        uint32_t Bv[2][4];
        #pragma unroll
        for (int nb=0;nb<2;nb++){
            int row = w*16 + nb*8 + (l&7);
            ldsm_x4(Bv[nb], svB + row*(KT_PAD*2) + ((l>>3)<<4));
        }
        #pragma unroll
        for (int ks=0; ks<2; ks++){
            uint32_t Af[4][4];
            #pragma unroll
            for (int mt=0;mt<4;mt++){
                int row = mt*16 + (l&15);
                ldsm_x4(Af[mt], skB + row*(KT_PAD*2) + (((ks<<1) + (l>>4))<<4));
            }
            #pragma unroll
            for (int mt=0;mt<4;mt++){
                mma16816h(acc[mt][0], Af[mt], &Bv[0][ks<<1]);
                mma16816h(acc[mt][1], Af[mt], &Bv[1][ks<<1]);
            }
        }
        __syncthreads();
    }

    size_t pb = (size_t)(b*CH+ch);
    #pragma unroll
    for (int mt=0;mt<4;mt++){
        #pragma unroll
        for (int nb=0;nb<2;nb++){
            int rf0 = mt*16 + (l>>2);
            int hd = w*16 + nb*8 + 2*(l&3);
            float2 v0 = make_float2(acc[mt][nb][0], acc[mt][nb][1]);
            float2 v1 = make_float2(acc[mt][nb][2], acc[mt][nb][3]);
            *reinterpret_cast<float2*>(&g_part[(pb*64 + rf0    )*128 + hd]) = v0;
            *reinterpret_cast<float2*>(&g_part[(pb*64 + rf0 + 8)*128 + hd]) = v1;
        }
    }
}

/* ---- vred: reduce partials -> transposed fp16 v2xT (x1/16) + ksum --- */
__global__ void vred2_k(){
    int idx = blockIdx.x*256 + threadIdx.x;   /* NB*64*136 = 34816 */
    if (idx >= NB*64*136) return;
    int b = idx / (64*136);
    int rem = idx - b*64*136;
    int m = rem / 136;
    int d = rem - m*136;
    float s = 0.f;
    if (d < 128){
        for (int ch=0; ch<CH; ch++)
            s += g_part[((size_t)(b*CH+ch)*64 + m)*128 + d];
    } else if (d == 128){
        s = g_ksum[b*64 + m];
    }
    g_v2xh[((size_t)b*136 + d)*64 + m] = __float2half(s * 0.0625f);
}

/* ---------- attention out via mma + residual + layernorm -------------
 * D[64x136] = qh[64x64] . v2xT[136x64]^T ; v2xT prescaled x1/16 with
 * ksum row 128.  Residual from fp32 h0 (layer0) or fp16 g_hh (layer1).
 * Output always fp16 -> g_hh.
 */
#define AT_TOT (36864 + 1024)
extern __shared__ char gsm3[];

__global__ void __launch_bounds__(256,1)
attn2_k(int res16, const float* __restrict__ res32,
        const float* __restrict__ lg, const float* __restrict__ lb)
{
    char* SQ = gsm3;               /* 64 rows x 128 B  = 8192  */
    char* SV = gsm3 + 8192;        /* 136 rows x 128 B = 17408 */
    float* sD = (float*)gsm3;      /* reuse: 64 x 144 f32 = 36864 */
    float* sg = (float*)(gsm3 + 36864);
    float* sb = sg + 128;

    int b = blockIdx.y;
    int tid = threadIdx.x, w = tid>>5, l = tid&31;
    int nb0 = blockIdx.x*64;

    if (tid < 128) sg[tid] = lg[tid];
    else           sb[tid-128] = lb[tid-128];

    /* stage q (fp16 direct copy) */
    for (int c = tid; c < 512; c += 256){
        int nd = c>>3, ch = c&7;
        int n = nb0 + nd;
        uint4 v = make_uint4(0,0,0,0);
        if (n < NN)
            v = *reinterpret_cast<const uint4*>(g_qh + ((size_t)(b*NN+n))*64 + ch*8);
        *reinterpret_cast<uint4*>(SQ + nd*128 + ((ch ^ (nd&7))<<4)) = v;
    }
    /* stage v2xT (fp16 direct copy, prescaled) */
    for (int c = tid; c < 1088; c += 256){
        int row = c>>3, ch = c&7;
        uint4 v = *reinterpret_cast<const uint4*>(
            g_v2xh + ((size_t)b*136 + row)*64 + ch*8);
        *reinterpret_cast<uint4*>(SV + row*128 + ((ch ^ (row&7))<<4)) = v;
    }
    __syncthreads();

    uint32_t sqB = smem_u32(SQ), svB = smem_u32(SV);
    int mt = w & 3, nh = w >> 2;
    int nblocks = nh ? 9 : 8;

    uint32_t Af[4][4];
    #pragma unroll
    for (int ks=0; ks<4; ks++){
        int ar = mt*16 + (l&15);
        int kc = ks*2 + (l>>4);
        ldsm_x4(Af[ks], sqB + ar*128 + ((kc ^ (ar&7))<<4));
    }

    float d[9][4];
    #pragma unroll
    for (int nb=0;nb<9;nb++){ d[nb][0]=0.f; d[nb][1]=0.f; d[nb][2]=0.f; d[nb][3]=0.f; }

    #pragma unroll 1
    for (int nb=0; nb<nblocks; nb++){
        int br = nh*64 + nb*8 + (l&7);
        uint32_t Bv[2][4];
        #pragma unroll
        for (int h=0; h<2; h++){
            int kc = h*4 + (l>>3);
            ldsm_x4(Bv[h], svB + br*128 + ((kc ^ (br&7))<<4));
        }
        #pragma unroll
        for (int ks=0; ks<4; ks++)
            mma16816h(d[nb], Af[ks], &Bv[ks>>1][(ks&1)<<1]);
    }
    __syncthreads();            /* all SQ/SV reads done; sD overlays */

    #pragma unroll 1
    for (int nb=0; nb<nblocks; nb++){
        int col = nh*64 + nb*8 + 2*(l&3);
        int row0 = mt*16 + (l>>2);
        *reinterpret_cast<float2*>(&sD[row0*144 + col])     = make_float2(d[nb][0], d[nb][1]);
        *reinterpret_cast<float2*>(&sD[(row0+8)*144 + col]) = make_float2(d[nb][2], d[nb][3]);
    }
    __syncthreads();

    float4 g4 = ((float4*)sg)[l];
    float4 b4 = ((float4*)sb)[l];
    #pragma unroll 1
    for (int nd=0; nd<8; nd++){
        int ln = w*8 + nd;
        int n = nb0 + ln;
        if (n >= NN) continue;
        size_t i = (size_t)b*NN + n;
        float inv = 1.f / sD[ln*144 + 128];
        float4 acc = *reinterpret_cast<float4*>(&sD[ln*144 + l*4]);
        float4 res;
        if (res16){
            uint2 u = *reinterpret_cast<const uint2*>(g_hh + i*128 + l*4);
            __half2 p0 = *reinterpret_cast<__half2*>(&u.x);
            __half2 p1 = *reinterpret_cast<__half2*>(&u.y);
            res.x = __low2float(p0); res.y = __high2float(p0);
            res.z = __low2float(p1); res.w = __high2float(p1);
        } else {
            res = ((const float4*)res32)[i*32 + l];
        }
        float4 t;
        t.x = fmaf(acc.x, inv, res.x);
        t.y = fmaf(acc.y, inv, res.y);
        t.z = fmaf(acc.z, inv, res.z);
        t.w = fmaf(acc.w, inv, res.w);
        float mu = warpSum(t.x+t.y+t.z+t.w) * (1.f/128.f);
        float dx=t.x-mu, dy=t.y-mu, dz=t.z-mu, dw=t.w-mu;
        float var = warpSum(dx*dx+dy*dy+dz*dz+dw*dw) * (1.f/128.f);
        float rs = rsqrtf(var + EPSLN);
        float ox = dx*rs*g4.x + b4.x;
        float oy = dy*rs*g4.y + b4.y;
        float oz = dz*rs*g4.z + b4.z;
        float ow = dw*rs*g4.w + b4.w;
        __half2 p0 = __floats2half2_rn(ox, oy);
        __half2 p1 = __floats2half2_rn(oz, ow);
        uint2 u;
        u.x = *reinterpret_cast<uint32_t*>(&p0);
        u.y = *reinterpret_cast<uint32_t*>(&p1);
        *reinterpret_cast<uint2*>(g_hh + i*128 + l*4) = u;
    }
}

/* -------- relu(concat(h0,h)) @ W_reg.T + b_reg, transposed out ------- */
__global__ void final_k(const float* __restrict__ Wreg, const float* __restrict__ breg,
                        float* __restrict__ out)
{
    __shared__ float sWrT[256*12];
    __shared__ float sbr[12];
    int tid = threadIdx.x;
    for (int t=tid; t<3072; t+=256){ int to=t>>8, j=t&255; sWrT[j*12+to] = Wreg[t]; }
    if (tid<12) sbr[tid] = breg[tid];
    __syncthreads();

    int w = tid>>5, l = tid&31;
    int i = blockIdx.x*8 + w;
    int b = i / NN;
    int n = i - b*NN;
    size_t hb = (size_t)i*128;

    float acc[12];
    #pragma unroll
    for (int t=0;t<12;t++) acc[t]=0.f;

    #pragma unroll
    for (int c=0;c<8;c++){
        int j = c*32 + l;
        float vIn = (j < 128) ? g_h0[hb + j]
                              : __half2float(g_hh[hb + (j - 128)]);
        vIn = fmaxf(vIn, 0.f);
        #pragma unroll
        for (int t=0;t<12;t++) acc[t] = fmaf(vIn, sWrT[j*12+t], acc[t]);
    }
    #pragma unroll
    for (int t=0;t<12;t++) acc[t] = warpSum(acc[t]);
    if (l < 12) out[((size_t)b*12 + l)*NN + n] = acc[l] + sbr[l];
}

/* ------------------------------ launch ------------------------------- */
extern "C" void kernel_launch(void* const* d_in, const int* in_sizes, int n_in,
                              void* d_out, int out_size)
{
    const float* x        = (const float*)d_in[0];
    const float* node_emb = (const float*)d_in[1];
    const float* time_emb = (const float*)d_in[2];
    const float* week_emb = (const float*)d_in[3];
    const float* Win      = (const float*)d_in[4];
    const float* bin      = (const float*)d_in[5];
    const float* W1       = (const float*)d_in[6];
    const float* b1       = (const float*)d_in[7];
    const float* W2       = (const float*)d_in[8];
    const float* b2       = (const float*)d_in[9];
    const float* Wreg     = (const float*)d_in[10];
    const float* breg     = (const float*)d_in[11];
    const float* proj     = (const float*)d_in[12];

    cudaFuncSetAttribute(glu3_k, cudaFuncAttributeMaxDynamicSharedMemorySize, G3_TOT);

    float*  g_h0_ptr; cudaGetSymbolAddress((void**)&g_h0_ptr, g_h0);
    __half* g_hh_ptr; cudaGetSymbolAddress((void**)&g_hh_ptr, g_hh);

    initmx_k<<<1,32>>>();
    pre_small_k<<<37,256>>>(time_emb, week_emb, W1, b1, W2, b2, proj);
    pre_node_k<<<NN/8,256>>>(node_emb, W1, W2, proj);
    phase1_k<<<NT/32,256>>>(x, node_emb, time_emb, week_emb, Win, bin);
    computek2_k<<<dim3(CH,NB),256>>>();
    ksumr_k<<<1,256>>>();

    for (int layer=0; layer<2; layer++){
        const float* wi = (const float*)d_in[13 + layer*6 + 0];
        const float* bi = (const float*)d_in[13 + layer*6 + 1];
        const float* wo = (const float*)d_in[13 + layer*6 + 2];
        const float* bo = (const float*)d_in[13 + layer*6 + 3];
        const float* lg = (const float*)d_in[13 + layer*6 + 4];
        const float* lb = (const float*)d_in[13 + layer*6 + 5];

        const float*  hin   = (layer == 0) ? g_h0_ptr : (const float*)0;
        const __half* hin_h = (layer == 0) ? (const __half*)0 : g_hh_ptr;

        glu3_k<<<148,512,G3_TOT>>>(hin, hin_h, wi, bi, wo, bo);
        kvredmma_k<<<dim3(CH,NB),256>>>();
        vred2_k<<<136,256>>>();
        attn2_k<<<dim3((NN+63)/64,NB),256,AT_TOT>>>((layer==0)?0:1, g_h0_ptr, lg, lb);
    }

    final_k<<<NT/8,256>>>(Wreg, breg, (float*)d_out);
}

// round 16
// speedup vs baseline: 1.5055x; 1.0026x over previous
#include <cuda_runtime.h>
#include <cuda_bf16.h>
#include <cuda_fp16.h>
#include <math.h>
#include <stdint.h>

#define NB 4
#define NN 50000
#define NT (NB*NN)
#define H4 128
#define RF 64
#define CH 98
#define CHSZ 512

#define ALPHA 0.4204482076268573f   /* 32^-0.25 */
#define RATIO 0.125f                /* 1/sqrt(64) */
#define EPSRF 1e-6f
#define EPSLN 1e-5f

/* ------------------------------ scratch ------------------------------ */
__device__ float  g_h0[(size_t)NT*H4];
__device__ __align__(16) __half g_hh[(size_t)NT*H4];
__device__ __align__(16) __half g_vh[(size_t)NT*H4];
__device__ __align__(16) __half g_qh[(size_t)NT*RF];
__device__ float  g_diag2[NT];
__device__ int    g_idx[NT];
__device__ __align__(16) __half g_kh[(size_t)NT*RF];
__device__ int    g_mx[NB];
__device__ float  g_part [(size_t)NB*CH*RF*H4];
__device__ float  g_kpart[(size_t)NB*CH*RF];
__device__ __align__(16) __half g_v2xh[(size_t)NB*136*RF];
/* precomputed LUTs */
__device__ float  g_a1n[(size_t)NN*32], g_a2n[(size_t)NN*32];
__device__ float  g_d1n[(size_t)NN*64], g_d2n[(size_t)NN*64];
__device__ float  g_a1t[288*32], g_a2t[288*32];
__device__ float  g_d1t[288*64], g_d2t[288*64];
__device__ float  g_a1w[7*32],  g_a2w[7*32];
__device__ float  g_d1w[7*64],  g_d2w[7*64];
__device__ float  g_a1b[32],    g_a2b[32];
__device__ float  g_d1b[64],    g_d2b[64];

/* ------------------------------ helpers ------------------------------ */
__device__ __forceinline__ float warpSum(float v){
    #pragma unroll
    for (int o=16;o;o>>=1) v += __shfl_xor_sync(0xffffffffu, v, o);
    return v;
}
__device__ __forceinline__ float warpMax(float v){
    #pragma unroll
    for (int o=16;o;o>>=1) v = fmaxf(v, __shfl_xor_sync(0xffffffffu, v, o));
    return v;
}
__device__ __forceinline__ int f2ord(float f){
    int i = __float_as_int(f);
    return (i >= 0) ? i : (i ^ 0x7FFFFFFF);
}
__device__ __forceinline__ float ord2f(int i){
    return __int_as_float((i >= 0) ? i : (i ^ 0x7FFFFFFF));
}

/* --------------------- mma.sync helpers ------------------------------ */
__device__ __forceinline__ uint32_t smem_u32(const void* p){
    uint32_t a;
    asm("{ .reg .u64 t; cvta.to.shared.u64 t, %1; cvt.u32.u64 %0, t; }"
        : "=r"(a) : "l"(p));
    return a;
}
__device__ __forceinline__ void ldsm_x4(uint32_t* r, uint32_t addr){
    asm volatile("ldmatrix.sync.aligned.m8n8.x4.shared.b16 {%0,%1,%2,%3}, [%4];"
        : "=r"(r[0]), "=r"(r[1]), "=r"(r[2]), "=r"(r[3]) : "r"(addr));
}
__device__ __forceinline__ uint32_t movm(uint32_t s){
    uint32_t d;
    asm volatile("movmatrix.sync.aligned.m8n8.trans.b16 %0, %1;" : "=r"(d) : "r"(s));
    return d;
}
__device__ __forceinline__ void mma16816h(float* d, const uint32_t* a, const uint32_t* b){
    asm volatile("mma.sync.aligned.m16n8k16.row.col.f32.f16.f16.f32 "
        "{%0,%1,%2,%3}, {%4,%5,%6,%7}, {%8,%9}, {%0,%1,%2,%3};"
        : "+f"(d[0]), "+f"(d[1]), "+f"(d[2]), "+f"(d[3])
        : "r"(a[0]), "r"(a[1]), "r"(a[2]), "r"(a[3]), "r"(b[0]), "r"(b[1]));
}
__device__ __forceinline__ uint4 pack8_f16(const float* src){
    float4 a = ((const float4*)src)[0];
    float4 b = ((const float4*)src)[1];
    __half2 p0 = __floats2half2_rn(a.x, a.y);
    __half2 p1 = __floats2half2_rn(a.z, a.w);
    __half2 p2 = __floats2half2_rn(b.x, b.y);
    __half2 p3 = __floats2half2_rn(b.z, b.w);
    uint4 w;
    w.x = *reinterpret_cast<uint32_t*>(&p0);
    w.y = *reinterpret_cast<uint32_t*>(&p1);
    w.z = *reinterpret_cast<uint32_t*>(&p2);
    w.w = *reinterpret_cast<uint32_t*>(&p3);
    return w;
}

/* ------------------------------ init --------------------------------- */
__global__ void initmx_k(){
    if (threadIdx.x < NB) g_mx[threadIdx.x] = (int)0x80000000;
}

/* ------------- LUT precompute: time/week/bias (296 entries) ---------- */
__global__ void pre_small_k(const float* __restrict__ time_emb,
                            const float* __restrict__ week_emb,
                            const float* __restrict__ W1, const float* __restrict__ b1,
                            const float* __restrict__ W2, const float* __restrict__ b2,
                            const float* __restrict__ proj)
{
    __shared__ float sT1[32*32], sU1[32*32], sT2[32*32], sU2[32*32];
    __shared__ float sprojT[32*64];
    __shared__ float sv[8][32], snv[8][32];
    int tid = threadIdx.x;
    for (int t=tid; t<1024; t+=256){
        int h=t>>5, d=t&31;
        sT1[d*32+h] = W1[h*96 + 32 + d];
        sU1[d*32+h] = W1[h*96 + 64 + d];
        sT2[d*32+h] = W2[h*96 + 32 + d];
        sU2[d*32+h] = W2[h*96 + 64 + d];
    }
    for (int t=tid; t<2048; t+=256){ int m=t>>5, d=t&31; sprojT[d*64+m] = proj[m*32+d]; }
    __syncthreads();

    int w = tid>>5, l = tid&31;
    int e = blockIdx.x*8 + w;
    if (e >= 296) return;

    float a1, a2;
    float *A1, *A2, *D1, *D2;
    if (e < 288){
        sv[w][l] = time_emb[e*32 + l]; __syncwarp();
        a1 = 0.f; a2 = 0.f;
        #pragma unroll
        for (int d=0; d<32; d++){
            float v = sv[w][d];
            a1 = fmaf(sT1[d*32+l], v, a1);
            a2 = fmaf(sT2[d*32+l], v, a2);
        }
        A1 = g_a1t + e*32; A2 = g_a2t + e*32;
        D1 = g_d1t + e*64; D2 = g_d2t + e*64;
    } else if (e < 295){
        int k = e - 288;
        sv[w][l] = week_emb[k*32 + l]; __syncwarp();
        a1 = 0.f; a2 = 0.f;
        #pragma unroll
        for (int d=0; d<32; d++){
            float v = sv[w][d];
            a1 = fmaf(sU1[d*32+l], v, a1);
            a2 = fmaf(sU2[d*32+l], v, a2);
        }
        A1 = g_a1w + k*32; A2 = g_a2w + k*32;
        D1 = g_d1w + k*64; D2 = g_d2w + k*64;
    } else {
        a1 = b1[l]; a2 = b2[l];
        A1 = g_a1b; A2 = g_a2b; D1 = g_d1b; D2 = g_d2b;
    }
    a1 *= ALPHA; a2 *= ALPHA;
    A1[l] = a1; A2[l] = a2;

    snv[w][l] = a1; __syncwarp();
    float d0=0.f, d1=0.f;
    #pragma unroll
    for (int dd=0; dd<32; dd++){
        float f = snv[w][dd];
        d0 = fmaf(f, sprojT[dd*64+l],    d0);
        d1 = fmaf(f, sprojT[dd*64+32+l], d1);
    }
    D1[l] = d0; D1[32+l] = d1;
    __syncwarp();
    snv[w][l] = a2; __syncwarp();
    d0=0.f; d1=0.f;
    #pragma unroll
    for (int dd=0; dd<32; dd++){
        float f = snv[w][dd];
        d0 = fmaf(f, sprojT[dd*64+l],    d0);
        d1 = fmaf(f, sprojT[dd*64+32+l], d1);
    }
    D2[l] = d0; D2[32+l] = d1;
}

/* ------------- LUT precompute: per-node (50000 entries) -------------- */
__global__ void pre_node_k(const float* __restrict__ node_emb,
                           const float* __restrict__ W1, const float* __restrict__ W2,
                           const float* __restrict__ proj)
{
    __shared__ float sW1T[32*32], sW2T[32*32];
    __shared__ float sprojT[32*64];
    __shared__ float sne[8][32], snv[8][32];
    int tid = threadIdx.x;
    for (int t=tid; t<1024; t+=256){
        int h=t>>5, d=t&31;
        sW1T[d*32+h] = W1[h*96 + d];
        sW2T[d*32+h] = W2[h*96 + d];
    }
    for (int t=tid; t<2048; t+=256){ int m=t>>5, d=t&31; sprojT[d*64+m] = proj[m*32+d]; }
    __syncthreads();

    int w = tid>>5, l = tid&31;
    int n = blockIdx.x*8 + w;

    sne[w][l] = node_emb[n*32 + l]; __syncwarp();
    float a1 = 0.f, a2 = 0.f;
    #pragma unroll
    for (int d=0; d<32; d++){
        float v = sne[w][d];
        a1 = fmaf(sW1T[d*32+l], v, a1);
        a2 = fmaf(sW2T[d*32+l], v, a2);
    }
    a1 *= ALPHA; a2 *= ALPHA;
    g_a1n[(size_t)n*32 + l] = a1;
    g_a2n[(size_t)n*32 + l] = a2;

    snv[w][l] = a1; __syncwarp();
    float d0=0.f, d1=0.f;
    #pragma unroll
    for (int dd=0; dd<32; dd++){
        float f = snv[w][dd];
        d0 = fmaf(f, sprojT[dd*64+l],    d0);
        d1 = fmaf(f, sprojT[dd*64+32+l], d1);
    }
    g_d1n[(size_t)n*64 + l] = d0;
    g_d1n[(size_t)n*64 + 32 + l] = d1;
    __syncwarp();
    snv[w][l] = a2; __syncwarp();
    d0=0.f; d1=0.f;
    #pragma unroll
    for (int dd=0; dd<32; dd++){
        float f = snv[w][dd];
        d0 = fmaf(f, sprojT[dd*64+l],    d0);
        d1 = fmaf(f, sprojT[dd*64+32+l], d1);
    }
    g_d2n[(size_t)n*64 + l] = d0;
    g_d2n[(size_t)n*64 + 32 + l] = d1;
}

/* --------------------------- phase 1 (LUT, 4 nodes/warp) ------------- */
__global__ void phase1_k(const float* __restrict__ x,
                         const float* __restrict__ node_emb,
                         const float* __restrict__ time_emb,
                         const float* __restrict__ week_emb,
                         const float* __restrict__ Win, const float* __restrict__ bin)
{
    __shared__ float sW4[9*128];
    __shared__ float sbin[32];
    __shared__ float sxv[8][160];
    __shared__ int   sbmax[NB];

    int tid = threadIdx.x;
    for (int t=tid; t<1152; t+=256){
        int h=t/36, j=t%36;
        sW4[(j>>2)*128 + h*4 + (j&3)] = Win[t];
    }
    if (tid<32) sbin[tid]=bin[tid];
    if (tid<NB) sbmax[tid] = (int)0x80000000;
    __syncthreads();

    int w = tid>>5, l = tid&31;
    int i0 = (blockIdx.x*8 + w)*4;
    int b = i0 / NN;

    const float* xr = x + (size_t)i0*36;
    for (int idx=l; idx<144; idx+=32){
        int nd = idx/36, j = idx - nd*36;
        sxv[w][nd*40 + j] = xr[idx];
    }
    __syncwarp();

    float inp[4];
    #pragma unroll
    for (int nd=0; nd<4; nd++) inp[nd] = sbin[l];
    #pragma unroll
    for (int j4=0; j4<9; j4++){
        float4 w4 = ((float4*)sW4)[j4*32 + l];
        #pragma unroll
        for (int nd=0; nd<4; nd++){
            float4 x4 = *reinterpret_cast<float4*>(&sxv[w][nd*40 + j4*4]);
            inp[nd] = fmaf(w4.x, x4.x,
                      fmaf(w4.y, x4.y,
                      fmaf(w4.z, x4.z,
                      fmaf(w4.w, x4.w, inp[nd]))));
        }
    }

    float wmax = -1e30f;
    #pragma unroll 1
    for (int nd=0; nd<4; nd++){
        int i = i0 + nd;
        int n = i - b*NN;
        int ti = (int)(sxv[w][nd*40+34]*288.0f); ti = min(max(ti,0),287);
        int wk = (int)(sxv[w][nd*40+35]);        wk = min(max(wk,0),6);

        float ne = node_emb[n*32+l];
        float te = time_emb[ti*32+l];
        float we = week_emb[wk*32+l];
        size_t hb = (size_t)i*128;
        g_h0[hb+l]=inp[nd]; g_h0[hb+32+l]=ne; g_h0[hb+64+l]=te; g_h0[hb+96+l]=we;

        float a1 = g_a1n[(size_t)n*32+l] + g_a1t[ti*32+l] + g_a1w[wk*32+l] + g_a1b[l];
        float diag1 = 0.5f * warpSum(a1*a1);
        float d0 = g_d1n[(size_t)n*64+l]    + g_d1t[ti*64+l]    + g_d1w[wk*64+l]    + g_d1b[l];
        float d1 = g_d1n[(size_t)n*64+32+l] + g_d1t[ti*64+32+l] + g_d1w[wk*64+32+l] + g_d1b[32+l];
        float mx1 = warpMax(fmaxf(d0,d1));
        g_qh[(size_t)i*64 + l]      = __float2half(RATIO*(expf(d0 - diag1 - mx1) + EPSRF));
        g_qh[(size_t)i*64 + 32 + l] = __float2half(RATIO*(expf(d1 - diag1 - mx1) + EPSRF));

        float a2 = g_a2n[(size_t)n*32+l] + g_a2t[ti*32+l] + g_a2w[wk*32+l] + g_a2b[l];
        float diag2 = 0.5f * warpSum(a2*a2);
        d0 = g_d2n[(size_t)n*64+l]    + g_d2t[ti*64+l]    + g_d2w[wk*64+l]    + g_d2b[l];
        d1 = g_d2n[(size_t)n*64+32+l] + g_d2t[ti*64+32+l] + g_d2w[wk*64+32+l] + g_d2b[32+l];
        if (l==0){
            g_diag2[i] = diag2;
            g_idx[i]   = ti*8 + wk;
        }
        wmax = fmaxf(wmax, fmaxf(d0,d1));
    }

    float m = warpMax(wmax);
    if (l==0) atomicMax(&sbmax[b], f2ord(m));

    __syncthreads();
    if (tid < NB && sbmax[tid] != (int)0x80000000)
        atomicMax(&g_mx[tid], sbmax[tid]);
}

/* ---------- fused k features + ksum partials (LUT recompute) --------- */
__global__ void __launch_bounds__(256,1)
computek2_k(){
    __shared__ float sd2b[64];
    __shared__ int   sidx[CHSZ];
    __shared__ float sdiag[CHSZ];
    __shared__ float red[4][64];

    int b = blockIdx.y, ch = blockIdx.x;
    int tid = threadIdx.x;
    int m = tid & 63, part = tid >> 6;
    int nb0 = ch*CHSZ;

    if (tid < 64) sd2b[tid] = g_d2b[tid];
    for (int t=tid; t<CHSZ; t+=256){
        int n = nb0 + t;
        if (n < NN){
            sidx[t]  = g_idx[b*NN + n];
            sdiag[t] = g_diag2[b*NN + n];
        } else { sidx[t] = 0; sdiag[t] = 0.f; }
    }
    __syncthreads();

    float mx = ord2f(g_mx[b]);
    float s = 0.f;
    int tb = part*128;
    #pragma unroll 2
    for (int nn=0; nn<128; nn++){
        int t = tb + nn;
        int n = nb0 + t;
        if (n < NN){
            int iv = sidx[t];
            int ti = iv >> 3, wk = iv & 7;
            float dv = g_d2n[(size_t)n*64 + m] + g_d2t[ti*64 + m]
                     + g_d2w[wk*64 + m] + sd2b[m];
            float val = RATIO*(expf(dv - sdiag[t] - mx) + EPSRF);
            g_kh[((size_t)(b*NN+n))*64 + m] = __float2half(val);
            s += val;
        }
    }
    red[part][m] = s;
    __syncthreads();
    if (part == 0){
        float t = red[0][m] + red[1][m] + red[2][m] + red[3][m];
        g_kpart[(size_t)(b*CH+ch)*64 + m] = t;
    }
}

/* ------------------------- GLU via mma.sync (fp16) ------------------- */
#define GT_TILES ((NT + 255)/256)
#define G3_SA   0
#define G3_SB   65536
#define G3_SBI  131072
#define G3_SBO  131584
#define G3_TOT  132096

extern __shared__ char gsm2[];

__global__ void __launch_bounds__(512,1)
glu3_k(const float* __restrict__ hin,
       const __half* __restrict__ hin_h,
       const float* __restrict__ wi, const float* __restrict__ bi,
       const float* __restrict__ wo, const float* __restrict__ bo)
{
    char* SA = gsm2 + G3_SA;
    char* SB = gsm2 + G3_SB;
    float* sbi = (float*)(gsm2 + G3_SBI);
    float* sbo = (float*)(gsm2 + G3_SBO);
    int tid = threadIdx.x;

    for (int c = tid; c < 4096; c += 512){
        int n = c >> 4, ch = c & 15;
        const float* src = (n < 128) ? (wi + (size_t)n*128 + ch*8)
                                     : (wo + (size_t)(n-128)*128 + ch*8);
        *reinterpret_cast<uint4*>(SB + n*256 + ((ch ^ (n&7))<<4)) = pack8_f16(src);
    }
    if (tid < 128){ sbi[tid] = bi[tid]; sbo[tid] = bo[tid]; }

    int w = tid>>5, l = tid&31;
    uint32_t saB = smem_u32(SA);
    uint32_t sbB = smem_u32(SB);

    int a_row = (w<<4) + (l & 15);
    int er    = (w<<4) + (l>>2);

    for (int tile = blockIdx.x; tile < GT_TILES; tile += gridDim.x){
        int base = tile << 8;

        for (int c = tid; c < 4096; c += 512){
            int r = c >> 4, ch = c & 15;
            uint4 pw = make_uint4(0,0,0,0);
            if (base + r < NT){
                if (hin_h)
                    pw = *reinterpret_cast<const uint4*>(hin_h + (size_t)(base + r)*128 + ch*8);
                else
                    pw = pack8_f16(hin + (size_t)(base + r)*128 + ch*8);
            }
            *reinterpret_cast<uint4*>(SA + r*256 + ((ch ^ (r&7))<<4)) = pw;
        }
        __syncthreads();

        uint32_t Af[8][4];
        #pragma unroll
        for (int ks=0; ks<8; ks++){
            int kc = (ks<<1) + (l>>4);
            ldsm_x4(Af[ks], saB + a_row*256 + ((kc ^ (a_row&7))<<4));
        }

        #pragma unroll 1
        for (int nb=0; nb<16; nb++){
            int nrI = (nb<<3) + (l&7);
            int nrO = nrI + 128;
            uint32_t BI[16], BO[16];
            #pragma unroll
            for (int j=0;j<4;j++){
                int kc = (j<<2) + (l>>3);
                ldsm_x4(&BI[j<<2], sbB + nrI*256 + ((kc ^ (nrI&7))<<4));
                ldsm_x4(&BO[j<<2], sbB + nrO*256 + ((kc ^ (nrO&7))<<4));
            }
            float dI[4] = {0.f,0.f,0.f,0.f};
            float dO[4] = {0.f,0.f,0.f,0.f};
            #pragma unroll
            for (int ks=0; ks<8; ks++){
                mma16816h(dI, Af[ks], &BI[ks<<1]);
                mma16816h(dO, Af[ks], &BO[ks<<1]);
            }

            int c0 = (nb<<3) + ((l&3)<<1);
            float bi0 = sbi[c0], bi1 = sbi[c0+1];
            float bo0 = sbo[c0], bo1 = sbo[c0+1];
            int n0 = base + er;
            int n1 = n0 + 8;
            if (n0 < NT){
                float aI0 = dI[0] + bi0, aI1 = dI[1] + bi1;
                float ox = (dO[0] + bo0) / (1.f + expf(-aI0));
                float oy = (dO[1] + bo1) / (1.f + expf(-aI1));
                *reinterpret_cast<__half2*>(g_vh + (size_t)n0*128 + c0) = __floats2half2_rn(ox, oy);
            }
            if (n1 < NT){
                float aI2 = dI[2] + bi0, aI3 = dI[3] + bi1;
                float ox = (dO[2] + bo0) / (1.f + expf(-aI2));
                float oy = (dO[3] + bo1) / (1.f + expf(-aI3));
                *reinterpret_cast<__half2*>(g_vh + (size_t)n1*128 + c0) = __floats2half2_rn(ox, oy);
            }
        }
        __syncthreads();
    }
}

/* --------- K^T V partials via mma.sync + movmatrix (deterministic) ---
 * k,v row-staged [node][feat] with pure uint4 copies; transposes done
 * in-register with movmatrix (A = {mov(M0),mov(M2),mov(M1),mov(M3)}).
 */
__global__ void __launch_bounds__(256,1)
kvredmma_k(){
    __shared__ __align__(16) __half SKrow[32*64];    /* [node][rf], 128B rows */
    __shared__ __align__(16) __half SVrow[32*128];   /* [node][hd], 256B rows */
    int b = blockIdx.y, ch = blockIdx.x;
    int tid = threadIdx.x, w = tid>>5, l = tid&31;
    uint32_t skB = smem_u32(SKrow), svB = smem_u32(SVrow);

    float acc[4][2][4];
    #pragma unroll
    for (int mt=0;mt<4;mt++)
        #pragma unroll
        for (int nb=0;nb<2;nb++)
            #pragma unroll
            for (int r=0;r<4;r++) acc[mt][nb][r] = 0.f;

    int nb0 = ch*CHSZ;
    #pragma unroll 1
    for (int c0=0; c0<CHSZ; c0+=32){
        int nbase = nb0 + c0;
        /* stage K rows: 256 uint4 units (node=c>>3, chunk=c&7) */
        {
            int node = tid >> 3, chk = tid & 7;
            int n = nbase + node;
            uint4 v = make_uint4(0,0,0,0);
            if (n < NN)
                v = *reinterpret_cast<const uint4*>(g_kh + ((size_t)(b*NN+n))*64 + chk*8);
            *reinterpret_cast<uint4*>((char*)SKrow + node*128 + ((chk ^ (node&7))<<4)) = v;
        }
        /* stage V rows: 512 uint4 units */
        for (int c = tid; c < 512; c += 256){
            int node = c >> 4, chk = c & 15;
            int n = nbase + node;
            uint4 v = make_uint4(0,0,0,0);
            if (n < NN)
                v = *reinterpret_cast<const uint4*>(g_vh + ((size_t)(b*NN+n))*128 + chk*8);
            *reinterpret_cast<uint4*>((char*)SVrow + node*256 + ((chk ^ (node&7))<<4)) = v;
        }
        __syncthreads();

        #pragma unroll
        for (int ks=0; ks<2; ks++){
            int row = ks*16 + (l&15);
            /* B: warp w covers hd [w*16, +16) */
            uint32_t Mv[4];
            {
                int kc = w*2 + (l>>4);
                ldsm_x4(Mv, svB + row*256 + ((kc ^ (row&7))<<4));
            }
            uint32_t B0[2], B1[2];
            B0[0] = movm(Mv[0]); B0[1] = movm(Mv[1]);
            B1[0] = movm(Mv[2]); B1[1] = movm(Mv[3]);

            #pragma unroll
            for (int mt=0; mt<4; mt++){
                uint32_t Mk[4], Afr[4];
                int kc = mt*2 + (l>>4);
                ldsm_x4(Mk, skB + row*128 + ((kc ^ (row&7))<<4));
                Afr[0] = movm(Mk[0]); Afr[1] = movm(Mk[2]);
                Afr[2] = movm(Mk[1]); Afr[3] = movm(Mk[3]);
                mma16816h(acc[mt][0], Afr, B0);
                mma16816h(acc[mt][1], Afr, B1);
            }
        }
        __syncthreads();
    }

    size_t pb = (size_t)(b*CH+ch);
    #pragma unroll
    for (int mt=0;mt<4;mt++){
        #pragma unroll
        for (int nb=0;nb<2;nb++){
            int rf0 = mt*16 + (l>>2);
            int hd = w*16 + nb*8 + 2*(l&3);
            float2 v0 = make_float2(acc[mt][nb][0], acc[mt][nb][1]);
            float2 v1 = make_float2(acc[mt][nb][2], acc[mt][nb][3]);
            *reinterpret_cast<float2*>(&g_part[(pb*64 + rf0    )*128 + hd]) = v0;
            *reinterpret_cast<float2*>(&g_part[(pb*64 + rf0 + 8)*128 + hd]) = v1;
        }
    }
}

/* ---- vred: reduce partials -> transposed fp16 v2xT (x1/16) + ksum --- */
__global__ void vred2_k(){
    int idx = blockIdx.x*256 + threadIdx.x;   /* NB*64*136 = 34816 */
    if (idx >= NB*64*136) return;
    int b = idx / (64*136);
    int rem = idx - b*64*136;
    int m = rem / 136;
    int d = rem - m*136;
    float s = 0.f;
    if (d < 128){
        for (int ch=0; ch<CH; ch++)
            s += g_part[((size_t)(b*CH+ch)*64 + m)*128 + d];
    } else if (d == 128){
        for (int ch=0; ch<CH; ch++)
            s += g_kpart[(size_t)(b*CH+ch)*64 + m];
    }
    g_v2xh[((size_t)b*136 + d)*64 + m] = __float2half(s * 0.0625f);
}

/* ---------- attention out via mma + residual + layernorm ------------- */
#define AT_TOT (36864 + 1024)
extern __shared__ char gsm3[];

__global__ void __launch_bounds__(256,1)
attn2_k(int res16, const float* __restrict__ res32,
        const float* __restrict__ lg, const float* __restrict__ lb)
{
    char* SQ = gsm3;
    char* SV = gsm3 + 8192;
    float* sD = (float*)gsm3;
    float* sg = (float*)(gsm3 + 36864);
    float* sb = sg + 128;

    int b = blockIdx.y;
    int tid = threadIdx.x, w = tid>>5, l = tid&31;
    int nb0 = blockIdx.x*64;

    if (tid < 128) sg[tid] = lg[tid];
    else           sb[tid-128] = lb[tid-128];

    for (int c = tid; c < 512; c += 256){
        int nd = c>>3, ch = c&7;
        int n = nb0 + nd;
        uint4 v = make_uint4(0,0,0,0);
        if (n < NN)
            v = *reinterpret_cast<const uint4*>(g_qh + ((size_t)(b*NN+n))*64 + ch*8);
        *reinterpret_cast<uint4*>(SQ + nd*128 + ((ch ^ (nd&7))<<4)) = v;
    }
    for (int c = tid; c < 1088; c += 256){
        int row = c>>3, ch = c&7;
        uint4 v = *reinterpret_cast<const uint4*>(
            g_v2xh + ((size_t)b*136 + row)*64 + ch*8);
        *reinterpret_cast<uint4*>(SV + row*128 + ((ch ^ (row&7))<<4)) = v;
    }
    __syncthreads();

    uint32_t sqB = smem_u32(SQ), svB = smem_u32(SV);
    int mt = w & 3, nh = w >> 2;
    int nblocks = nh ? 9 : 8;

    uint32_t Af[4][4];
    #pragma unroll
    for (int ks=0; ks<4; ks++){
        int ar = mt*16 + (l&15);
        int kc = ks*2 + (l>>4);
        ldsm_x4(Af[ks], sqB + ar*128 + ((kc ^ (ar&7))<<4));
    }

    float d[9][4];
    #pragma unroll
    for (int nb=0;nb<9;nb++){ d[nb][0]=0.f; d[nb][1]=0.f; d[nb][2]=0.f; d[nb][3]=0.f; }

    #pragma unroll 1
    for (int nb=0; nb<nblocks; nb++){
        int br = nh*64 + nb*8 + (l&7);
        uint32_t Bv[2][4];
        #pragma unroll
        for (int h=0; h<2; h++){
            int kc = h*4 + (l>>3);
            ldsm_x4(Bv[h], svB + br*128 + ((kc ^ (br&7))<<4));
        }
        #pragma unroll
        for (int ks=0; ks<4; ks++)
            mma16816h(d[nb], Af[ks], &Bv[ks>>1][(ks&1)<<1]);
    }
    __syncthreads();

    #pragma unroll 1
    for (int nb=0; nb<nblocks; nb++){
        int col = nh*64 + nb*8 + 2*(l&3);
        int row0 = mt*16 + (l>>2);
        *reinterpret_cast<float2*>(&sD[row0*144 + col])     = make_float2(d[nb][0], d[nb][1]);
        *reinterpret_cast<float2*>(&sD[(row0+8)*144 + col]) = make_float2(d[nb][2], d[nb][3]);
    }
    __syncthreads();

    float4 g4 = ((float4*)sg)[l];
    float4 b4 = ((float4*)sb)[l];
    #pragma unroll 1
    for (int nd=0; nd<8; nd++){
        int ln = w*8 + nd;
        int n = nb0 + ln;
        if (n >= NN) continue;
        size_t i = (size_t)b*NN + n;
        float inv = 1.f / sD[ln*144 + 128];
        float4 acc = *reinterpret_cast<float4*>(&sD[ln*144 + l*4]);
        float4 res;
        if (res16){
            uint2 u = *reinterpret_cast<const uint2*>(g_hh + i*128 + l*4);
            __half2 p0 = *reinterpret_cast<__half2*>(&u.x);
            __half2 p1 = *reinterpret_cast<__half2*>(&u.y);
            res.x = __low2float(p0); res.y = __high2float(p0);
            res.z = __low2float(p1); res.w = __high2float(p1);
        } else {
            res = ((const float4*)res32)[i*32 + l];
        }
        float4 t;
        t.x = fmaf(acc.x, inv, res.x);
        t.y = fmaf(acc.y, inv, res.y);
        t.z = fmaf(acc.z, inv, res.z);
        t.w = fmaf(acc.w, inv, res.w);
        float mu = warpSum(t.x+t.y+t.z+t.w) * (1.f/128.f);
        float dx=t.x-mu, dy=t.y-mu, dz=t.z-mu, dw=t.w-mu;
        float var = warpSum(dx*dx+dy*dy+dz*dz+dw*dw) * (1.f/128.f);
        float rs = rsqrtf(var + EPSLN);
        float ox = dx*rs*g4.x + b4.x;
        float oy = dy*rs*g4.y + b4.y;
        float oz = dz*rs*g4.z + b4.z;
        float ow = dw*rs*g4.w + b4.w;
        __half2 p0 = __floats2half2_rn(ox, oy);
        __half2 p1 = __floats2half2_rn(oz, ow);
        uint2 u;
        u.x = *reinterpret_cast<uint32_t*>(&p0);
        u.y = *reinterpret_cast<uint32_t*>(&p1);
        *reinterpret_cast<uint2*>(g_hh + i*128 + l*4) = u;
    }
}

/* -------- relu(concat(h0,h)) @ W_reg.T + b_reg, transposed out ------- */
__global__ void final_k(const float* __restrict__ Wreg, const float* __restrict__ breg,
                        float* __restrict__ out)
{
    __shared__ float sWrT[256*12];
    __shared__ float sbr[12];
    int tid = threadIdx.x;
    for (int t=tid; t<3072; t+=256){ int to=t>>8, j=t&255; sWrT[j*12+to] = Wreg[t]; }
    if (tid<12) sbr[tid] = breg[tid];
    __syncthreads();

    int w = tid>>5, l = tid&31;
    int i = blockIdx.x*8 + w;
    int b = i / NN;
    int n = i - b*NN;
    size_t hb = (size_t)i*128;

    float acc[12];
    #pragma unroll
    for (int t=0;t<12;t++) acc[t]=0.f;

    #pragma unroll
    for (int c=0;c<8;c++){
        int j = c*32 + l;
        float vIn = (j < 128) ? g_h0[hb + j]
                              : __half2float(g_hh[hb + (j - 128)]);
        vIn = fmaxf(vIn, 0.f);
        #pragma unroll
        for (int t=0;t<12;t++) acc[t] = fmaf(vIn, sWrT[j*12+t], acc[t]);
    }
    #pragma unroll
    for (int t=0;t<12;t++) acc[t] = warpSum(acc[t]);
    if (l < 12) out[((size_t)b*12 + l)*NN + n] = acc[l] + sbr[l];
}

/* ------------------------------ launch ------------------------------- */
extern "C" void kernel_launch(void* const* d_in, const int* in_sizes, int n_in,
                              void* d_out, int out_size)
{
    const float* x        = (const float*)d_in[0];
    const float* node_emb = (const float*)d_in[1];
    const float* time_emb = (const float*)d_in[2];
    const float* week_emb = (const float*)d_in[3];
    const float* Win      = (const float*)d_in[4];
    const float* bin      = (const float*)d_in[5];
    const float* W1       = (const float*)d_in[6];
    const float* b1       = (const float*)d_in[7];
    const float* W2       = (const float*)d_in[8];
    const float* b2       = (const float*)d_in[9];
    const float* Wreg     = (const float*)d_in[10];
    const float* breg     = (const float*)d_in[11];
    const float* proj     = (const float*)d_in[12];

    cudaFuncSetAttribute(glu3_k, cudaFuncAttributeMaxDynamicSharedMemorySize, G3_TOT);

    float*  g_h0_ptr; cudaGetSymbolAddress((void**)&g_h0_ptr, g_h0);
    __half* g_hh_ptr; cudaGetSymbolAddress((void**)&g_hh_ptr, g_hh);

    initmx_k<<<1,32>>>();
    pre_small_k<<<37,256>>>(time_emb, week_emb, W1, b1, W2, b2, proj);
    pre_node_k<<<NN/8,256>>>(node_emb, W1, W2, proj);
    phase1_k<<<NT/32,256>>>(x, node_emb, time_emb, week_emb, Win, bin);
    computek2_k<<<dim3(CH,NB),256>>>();

    for (int layer=0; layer<2; layer++){
        const float* wi = (const float*)d_in[13 + layer*6 + 0];
        const float* bi = (const float*)d_in[13 + layer*6 + 1];
        const float* wo = (const float*)d_in[13 + layer*6 + 2];
        const float* bo = (const float*)d_in[13 + layer*6 + 3];
        const float* lg = (const float*)d_in[13 + layer*6 + 4];
        const float* lb = (const float*)d_in[13 + layer*6 + 5];

        const float*  hin   = (layer == 0) ? g_h0_ptr : (const float*)0;
        const __half* hin_h = (layer == 0) ? (const __half*)0 : g_hh_ptr;

        glu3_k<<<148,512,G3_TOT>>>(hin, hin_h, wi, bi, wo, bo);
        kvredmma_k<<<dim3(CH,NB),256>>>();
        vred2_k<<<136,256>>>();
        attn2_k<<<dim3((NN+63)/64,NB),256,AT_TOT>>>((layer==0)?0:1, g_h0_ptr, lg, lb);
    }

    final_k<<<NT/8,256>>>(Wreg, breg, (float*)d_out);
}

// round 17
// speedup vs baseline: 1.5392x; 1.0223x over previous
#include <cuda_runtime.h>
#include <cuda_bf16.h>
#include <cuda_fp16.h>
#include <math.h>
#include <stdint.h>

#define NB 4
#define NN 50000
#define NT (NB*NN)
#define H4 128
#define RF 64
#define CH 98
#define CHSZ 512

#define ALPHA 0.4204482076268573f   /* 32^-0.25 */
#define RATIO 0.125f                /* 1/sqrt(64) */
#define EPSRF 1e-6f
#define EPSLN 1e-5f

/* ------------------------------ scratch ------------------------------ */
__device__ __align__(16) __half g_h0h[(size_t)NT*H4];
__device__ __align__(16) __half g_hh[(size_t)NT*H4];
__device__ __align__(16) __half g_vh[(size_t)NT*H4];
__device__ __align__(16) __half g_qh[(size_t)NT*RF];
__device__ float  g_diag2[NT];
__device__ int    g_idx[NT];
__device__ __align__(16) __half g_kh[(size_t)NT*RF];
__device__ int    g_mx[NB];
__device__ float  g_part [(size_t)NB*CH*RF*H4];
__device__ float  g_kpart[(size_t)NB*CH*RF];
__device__ __align__(16) __half g_v2xh[(size_t)NB*136*RF];
/* precomputed LUTs */
__device__ float  g_a1n[(size_t)NN*32], g_a2n[(size_t)NN*32];
__device__ float  g_d1n[(size_t)NN*64], g_d2n[(size_t)NN*64];
__device__ float  g_a1t[288*32], g_a2t[288*32];
__device__ float  g_d1t[288*64], g_d2t[288*64];
__device__ float  g_a1w[7*32],  g_a2w[7*32];
__device__ float  g_d1w[7*64],  g_d2w[7*64];
__device__ float  g_a1b[32],    g_a2b[32];
__device__ float  g_d1b[64],    g_d2b[64];

/* ------------------------------ helpers ------------------------------ */
__device__ __forceinline__ float warpSum(float v){
    #pragma unroll
    for (int o=16;o;o>>=1) v += __shfl_xor_sync(0xffffffffu, v, o);
    return v;
}
__device__ __forceinline__ float warpMax(float v){
    #pragma unroll
    for (int o=16;o;o>>=1) v = fmaxf(v, __shfl_xor_sync(0xffffffffu, v, o));
    return v;
}
__device__ __forceinline__ int f2ord(float f){
    int i = __float_as_int(f);
    return (i >= 0) ? i : (i ^ 0x7FFFFFFF);
}
__device__ __forceinline__ float ord2f(int i){
    return __int_as_float((i >= 0) ? i : (i ^ 0x7FFFFFFF));
}

/* --------------------- mma.sync helpers ------------------------------ */
__device__ __forceinline__ uint32_t smem_u32(const void* p){
    uint32_t a;
    asm("{ .reg .u64 t; cvta.to.shared.u64 t, %1; cvt.u32.u64 %0, t; }"
        : "=r"(a) : "l"(p));
    return a;
}
__device__ __forceinline__ void ldsm_x4(uint32_t* r, uint32_t addr){
    asm volatile("ldmatrix.sync.aligned.m8n8.x4.shared.b16 {%0,%1,%2,%3}, [%4];"
        : "=r"(r[0]), "=r"(r[1]), "=r"(r[2]), "=r"(r[3]) : "r"(addr));
}
__device__ __forceinline__ uint32_t movm(uint32_t s){
    uint32_t d;
    asm volatile("movmatrix.sync.aligned.m8n8.trans.b16 %0, %1;" : "=r"(d) : "r"(s));
    return d;
}
__device__ __forceinline__ void mma16816h(float* d, const uint32_t* a, const uint32_t* b){
    asm volatile("mma.sync.aligned.m16n8k16.row.col.f32.f16.f16.f32 "
        "{%0,%1,%2,%3}, {%4,%5,%6,%7}, {%8,%9}, {%0,%1,%2,%3};"
        : "+f"(d[0]), "+f"(d[1]), "+f"(d[2]), "+f"(d[3])
        : "r"(a[0]), "r"(a[1]), "r"(a[2]), "r"(a[3]), "r"(b[0]), "r"(b[1]));
}
__device__ __forceinline__ uint4 pack8_f16(const float* src){
    float4 a = ((const float4*)src)[0];
    float4 b = ((const float4*)src)[1];
    __half2 p0 = __floats2half2_rn(a.x, a.y);
    __half2 p1 = __floats2half2_rn(a.z, a.w);
    __half2 p2 = __floats2half2_rn(b.x, b.y);
    __half2 p3 = __floats2half2_rn(b.z, b.w);
    uint4 w;
    w.x = *reinterpret_cast<uint32_t*>(&p0);
    w.y = *reinterpret_cast<uint32_t*>(&p1);
    w.z = *reinterpret_cast<uint32_t*>(&p2);
    w.w = *reinterpret_cast<uint32_t*>(&p3);
    return w;
}

/* ------------------------------ init --------------------------------- */
__global__ void initmx_k(){
    if (threadIdx.x < NB) g_mx[threadIdx.x] = (int)0x80000000;
}

/* ------------- LUT precompute: time/week/bias (296 entries) ---------- */
__global__ void pre_small_k(const float* __restrict__ time_emb,
                            const float* __restrict__ week_emb,
                            const float* __restrict__ W1, const float* __restrict__ b1,
                            const float* __restrict__ W2, const float* __restrict__ b2,
                            const float* __restrict__ proj)
{
    __shared__ float sT1[32*32], sU1[32*32], sT2[32*32], sU2[32*32];
    __shared__ float sprojT[32*64];
    __shared__ float sv[8][32], snv[8][32];
    int tid = threadIdx.x;
    for (int t=tid; t<1024; t+=256){
        int h=t>>5, d=t&31;
        sT1[d*32+h] = W1[h*96 + 32 + d];
        sU1[d*32+h] = W1[h*96 + 64 + d];
        sT2[d*32+h] = W2[h*96 + 32 + d];
        sU2[d*32+h] = W2[h*96 + 64 + d];
    }
    for (int t=tid; t<2048; t+=256){ int m=t>>5, d=t&31; sprojT[d*64+m] = proj[m*32+d]; }
    __syncthreads();

    int w = tid>>5, l = tid&31;
    int e = blockIdx.x*8 + w;
    if (e >= 296) return;

    float a1, a2;
    float *A1, *A2, *D1, *D2;
    if (e < 288){
        sv[w][l] = time_emb[e*32 + l]; __syncwarp();
        a1 = 0.f; a2 = 0.f;
        #pragma unroll
        for (int d=0; d<32; d++){
            float v = sv[w][d];
            a1 = fmaf(sT1[d*32+l], v, a1);
            a2 = fmaf(sT2[d*32+l], v, a2);
        }
        A1 = g_a1t + e*32; A2 = g_a2t + e*32;
        D1 = g_d1t + e*64; D2 = g_d2t + e*64;
    } else if (e < 295){
        int k = e - 288;
        sv[w][l] = week_emb[k*32 + l]; __syncwarp();
        a1 = 0.f; a2 = 0.f;
        #pragma unroll
        for (int d=0; d<32; d++){
            float v = sv[w][d];
            a1 = fmaf(sU1[d*32+l], v, a1);
            a2 = fmaf(sU2[d*32+l], v, a2);
        }
        A1 = g_a1w + k*32; A2 = g_a2w + k*32;
        D1 = g_d1w + k*64; D2 = g_d2w + k*64;
    } else {
        a1 = b1[l]; a2 = b2[l];
        A1 = g_a1b; A2 = g_a2b; D1 = g_d1b; D2 = g_d2b;
    }
    a1 *= ALPHA; a2 *= ALPHA;
    A1[l] = a1; A2[l] = a2;

    snv[w][l] = a1; __syncwarp();
    float d0=0.f, d1=0.f;
    #pragma unroll
    for (int dd=0; dd<32; dd++){
        float f = snv[w][dd];
        d0 = fmaf(f, sprojT[dd*64+l],    d0);
        d1 = fmaf(f, sprojT[dd*64+32+l], d1);
    }
    D1[l] = d0; D1[32+l] = d1;
    __syncwarp();
    snv[w][l] = a2; __syncwarp();
    d0=0.f; d1=0.f;
    #pragma unroll
    for (int dd=0; dd<32; dd++){
        float f = snv[w][dd];
        d0 = fmaf(f, sprojT[dd*64+l],    d0);
        d1 = fmaf(f, sprojT[dd*64+32+l], d1);
    }
    D2[l] = d0; D2[32+l] = d1;
}

/* ------------- LUT precompute: per-node (50000 entries) -------------- */
__global__ void pre_node_k(const float* __restrict__ node_emb,
                           const float* __restrict__ W1, const float* __restrict__ W2,
                           const float* __restrict__ proj)
{
    __shared__ float sW1T[32*32], sW2T[32*32];
    __shared__ float sprojT[32*64];
    __shared__ float sne[8][32], snv[8][32];
    int tid = threadIdx.x;
    for (int t=tid; t<1024; t+=256){
        int h=t>>5, d=t&31;
        sW1T[d*32+h] = W1[h*96 + d];
        sW2T[d*32+h] = W2[h*96 + d];
    }
    for (int t=tid; t<2048; t+=256){ int m=t>>5, d=t&31; sprojT[d*64+m] = proj[m*32+d]; }
    __syncthreads();

    int w = tid>>5, l = tid&31;
    int n = blockIdx.x*8 + w;

    sne[w][l] = node_emb[n*32 + l]; __syncwarp();
    float a1 = 0.f, a2 = 0.f;
    #pragma unroll
    for (int d=0; d<32; d++){
        float v = sne[w][d];
        a1 = fmaf(sW1T[d*32+l], v, a1);
        a2 = fmaf(sW2T[d*32+l], v, a2);
    }
    a1 *= ALPHA; a2 *= ALPHA;
    g_a1n[(size_t)n*32 + l] = a1;
    g_a2n[(size_t)n*32 + l] = a2;

    snv[w][l] = a1; __syncwarp();
    float d0=0.f, d1=0.f;
    #pragma unroll
    for (int dd=0; dd<32; dd++){
        float f = snv[w][dd];
        d0 = fmaf(f, sprojT[dd*64+l],    d0);
        d1 = fmaf(f, sprojT[dd*64+32+l], d1);
    }
    g_d1n[(size_t)n*64 + l] = d0;
    g_d1n[(size_t)n*64 + 32 + l] = d1;
    __syncwarp();
    snv[w][l] = a2; __syncwarp();
    d0=0.f; d1=0.f;
    #pragma unroll
    for (int dd=0; dd<32; dd++){
        float f = snv[w][dd];
        d0 = fmaf(f, sprojT[dd*64+l],    d0);
        d1 = fmaf(f, sprojT[dd*64+32+l], d1);
    }
    g_d2n[(size_t)n*64 + l] = d0;
    g_d2n[(size_t)n*64 + 32 + l] = d1;
}

/* --------------------------- phase 1 (LUT, 4 nodes/warp) ------------- */
__global__ void phase1_k(const float* __restrict__ x,
                         const float* __restrict__ node_emb,
                         const float* __restrict__ time_emb,
                         const float* __restrict__ week_emb,
                         const float* __restrict__ Win, const float* __restrict__ bin)
{
    __shared__ float sW4[9*128];
    __shared__ float sbin[32];
    __shared__ float sxv[8][160];
    __shared__ int   sbmax[NB];

    int tid = threadIdx.x;
    for (int t=tid; t<1152; t+=256){
        int h=t/36, j=t%36;
        sW4[(j>>2)*128 + h*4 + (j&3)] = Win[t];
    }
    if (tid<32) sbin[tid]=bin[tid];
    if (tid<NB) sbmax[tid] = (int)0x80000000;
    __syncthreads();

    int w = tid>>5, l = tid&31;
    int i0 = (blockIdx.x*8 + w)*4;
    int b = i0 / NN;

    const float* xr = x + (size_t)i0*36;
    for (int idx=l; idx<144; idx+=32){
        int nd = idx/36, j = idx - nd*36;
        sxv[w][nd*40 + j] = xr[idx];
    }
    __syncwarp();

    float inp[4];
    #pragma unroll
    for (int nd=0; nd<4; nd++) inp[nd] = sbin[l];
    #pragma unroll
    for (int j4=0; j4<9; j4++){
        float4 w4 = ((float4*)sW4)[j4*32 + l];
        #pragma unroll
        for (int nd=0; nd<4; nd++){
            float4 x4 = *reinterpret_cast<float4*>(&sxv[w][nd*40 + j4*4]);
            inp[nd] = fmaf(w4.x, x4.x,
                      fmaf(w4.y, x4.y,
                      fmaf(w4.z, x4.z,
                      fmaf(w4.w, x4.w, inp[nd]))));
        }
    }

    float wmax = -1e30f;
    #pragma unroll 1
    for (int nd=0; nd<4; nd++){
        int i = i0 + nd;
        int n = i - b*NN;
        int ti = (int)(sxv[w][nd*40+34]*288.0f); ti = min(max(ti,0),287);
        int wk = (int)(sxv[w][nd*40+35]);        wk = min(max(wk,0),6);

        float ne = node_emb[n*32+l];
        float te = time_emb[ti*32+l];
        float we = week_emb[wk*32+l];
        size_t hb = (size_t)i*128;
        g_h0h[hb+l]      = __float2half(inp[nd]);
        g_h0h[hb+32+l]   = __float2half(ne);
        g_h0h[hb+64+l]   = __float2half(te);
        g_h0h[hb+96+l]   = __float2half(we);

        float a1 = g_a1n[(size_t)n*32+l] + g_a1t[ti*32+l] + g_a1w[wk*32+l] + g_a1b[l];
        float diag1 = 0.5f * warpSum(a1*a1);
        float d0 = g_d1n[(size_t)n*64+l]    + g_d1t[ti*64+l]    + g_d1w[wk*64+l]    + g_d1b[l];
        float d1 = g_d1n[(size_t)n*64+32+l] + g_d1t[ti*64+32+l] + g_d1w[wk*64+32+l] + g_d1b[32+l];
        float mx1 = warpMax(fmaxf(d0,d1));
        g_qh[(size_t)i*64 + l]      = __float2half(RATIO*(__expf(d0 - diag1 - mx1) + EPSRF));
        g_qh[(size_t)i*64 + 32 + l] = __float2half(RATIO*(__expf(d1 - diag1 - mx1) + EPSRF));

        float a2 = g_a2n[(size_t)n*32+l] + g_a2t[ti*32+l] + g_a2w[wk*32+l] + g_a2b[l];
        float diag2 = 0.5f * warpSum(a2*a2);
        d0 = g_d2n[(size_t)n*64+l]    + g_d2t[ti*64+l]    + g_d2w[wk*64+l]    + g_d2b[l];
        d1 = g_d2n[(size_t)n*64+32+l] + g_d2t[ti*64+32+l] + g_d2w[wk*64+32+l] + g_d2b[32+l];
        if (l==0){
            g_diag2[i] = diag2;
            g_idx[i]   = ti*8 + wk;
        }
        wmax = fmaxf(wmax, fmaxf(d0,d1));
    }

    float m = warpMax(wmax);
    if (l==0) atomicMax(&sbmax[b], f2ord(m));

    __syncthreads();
    if (tid < NB && sbmax[tid] != (int)0x80000000)
        atomicMax(&g_mx[tid], sbmax[tid]);
}

/* ---------- fused k features + ksum partials (LUT recompute) --------- */
__global__ void __launch_bounds__(256,1)
computek2_k(){
    __shared__ float sd2b[64];
    __shared__ int   sidx[CHSZ];
    __shared__ float sdiag[CHSZ];
    __shared__ float red[4][64];

    int b = blockIdx.y, ch = blockIdx.x;
    int tid = threadIdx.x;
    int m = tid & 63, part = tid >> 6;
    int nb0 = ch*CHSZ;

    if (tid < 64) sd2b[tid] = g_d2b[tid];
    for (int t=tid; t<CHSZ; t+=256){
        int n = nb0 + t;
        if (n < NN){
            sidx[t]  = g_idx[b*NN + n];
            sdiag[t] = g_diag2[b*NN + n];
        } else { sidx[t] = 0; sdiag[t] = 0.f; }
    }
    __syncthreads();

    float mx = ord2f(g_mx[b]);
    float s = 0.f;
    int tb = part*128;
    #pragma unroll 2
    for (int nn=0; nn<128; nn++){
        int t = tb + nn;
        int n = nb0 + t;
        if (n < NN){
            int iv = sidx[t];
            int ti = iv >> 3, wk = iv & 7;
            float dv = g_d2n[(size_t)n*64 + m] + g_d2t[ti*64 + m]
                     + g_d2w[wk*64 + m] + sd2b[m];
            float val = RATIO*(__expf(dv - sdiag[t] - mx) + EPSRF);
            g_kh[((size_t)(b*NN+n))*64 + m] = __float2half(val);
            s += val;
        }
    }
    red[part][m] = s;
    __syncthreads();
    if (part == 0){
        float t = red[0][m] + red[1][m] + red[2][m] + red[3][m];
        g_kpart[(size_t)(b*CH+ch)*64 + m] = t;
    }
}

/* ------------------------- GLU via mma.sync (fp16) ------------------- */
#define GT_TILES ((NT + 255)/256)
#define G3_SA   0
#define G3_SB   65536
#define G3_SBI  131072
#define G3_SBO  131584
#define G3_TOT  132096

extern __shared__ char gsm2[];

__global__ void __launch_bounds__(512,1)
glu3_k(const __half* __restrict__ hin_h,
       const float* __restrict__ wi, const float* __restrict__ bi,
       const float* __restrict__ wo, const float* __restrict__ bo)
{
    char* SA = gsm2 + G3_SA;
    char* SB = gsm2 + G3_SB;
    float* sbi = (float*)(gsm2 + G3_SBI);
    float* sbo = (float*)(gsm2 + G3_SBO);
    int tid = threadIdx.x;

    for (int c = tid; c < 4096; c += 512){
        int n = c >> 4, ch = c & 15;
        const float* src = (n < 128) ? (wi + (size_t)n*128 + ch*8)
                                     : (wo + (size_t)(n-128)*128 + ch*8);
        *reinterpret_cast<uint4*>(SB + n*256 + ((ch ^ (n&7))<<4)) = pack8_f16(src);
    }
    if (tid < 128){ sbi[tid] = bi[tid]; sbo[tid] = bo[tid]; }

    int w = tid>>5, l = tid&31;
    uint32_t saB = smem_u32(SA);
    uint32_t sbB = smem_u32(SB);

    int a_row = (w<<4) + (l & 15);
    int er    = (w<<4) + (l>>2);

    for (int tile = blockIdx.x; tile < GT_TILES; tile += gridDim.x){
        int base = tile << 8;

        for (int c = tid; c < 4096; c += 512){
            int r = c >> 4, ch = c & 15;
            uint4 pw = make_uint4(0,0,0,0);
            if (base + r < NT)
                pw = *reinterpret_cast<const uint4*>(hin_h + (size_t)(base + r)*128 + ch*8);
            *reinterpret_cast<uint4*>(SA + r*256 + ((ch ^ (r&7))<<4)) = pw;
        }
        __syncthreads();

        uint32_t Af[8][4];
        #pragma unroll
        for (int ks=0; ks<8; ks++){
            int kc = (ks<<1) + (l>>4);
            ldsm_x4(Af[ks], saB + a_row*256 + ((kc ^ (a_row&7))<<4));
        }

        #pragma unroll 1
        for (int nb=0; nb<16; nb++){
            int nrI = (nb<<3) + (l&7);
            int nrO = nrI + 128;
            uint32_t BI[16], BO[16];
            #pragma unroll
            for (int j=0;j<4;j++){
                int kc = (j<<2) + (l>>3);
                ldsm_x4(&BI[j<<2], sbB + nrI*256 + ((kc ^ (nrI&7))<<4));
                ldsm_x4(&BO[j<<2], sbB + nrO*256 + ((kc ^ (nrO&7))<<4));
            }
            float dI[4] = {0.f,0.f,0.f,0.f};
            float dO[4] = {0.f,0.f,0.f,0.f};
            #pragma unroll
            for (int ks=0; ks<8; ks++){
                mma16816h(dI, Af[ks], &BI[ks<<1]);
                mma16816h(dO, Af[ks], &BO[ks<<1]);
            }

            int c0 = (nb<<3) + ((l&3)<<1);
            float bi0 = sbi[c0], bi1 = sbi[c0+1];
            float bo0 = sbo[c0], bo1 = sbo[c0+1];
            int n0 = base + er;
            int n1 = n0 + 8;
            if (n0 < NT){
                float aI0 = dI[0] + bi0, aI1 = dI[1] + bi1;
                float ox = (dO[0] + bo0) / (1.f + __expf(-aI0));
                float oy = (dO[1] + bo1) / (1.f + __expf(-aI1));
                *reinterpret_cast<__half2*>(g_vh + (size_t)n0*128 + c0) = __floats2half2_rn(ox, oy);
            }
            if (n1 < NT){
                float aI2 = dI[2] + bi0, aI3 = dI[3] + bi1;
                float ox = (dO[2] + bo0) / (1.f + __expf(-aI2));
                float oy = (dO[3] + bo1) / (1.f + __expf(-aI3));
                *reinterpret_cast<__half2*>(g_vh + (size_t)n1*128 + c0) = __floats2half2_rn(ox, oy);
            }
        }
        __syncthreads();
    }
}

/* --------- K^T V partials via mma.sync + movmatrix (deterministic) --- */
__global__ void __launch_bounds__(256,1)
kvredmma_k(){
    __shared__ __align__(16) __half SKrow[32*64];
    __shared__ __align__(16) __half SVrow[32*128];
    int b = blockIdx.y, ch = blockIdx.x;
    int tid = threadIdx.x, w = tid>>5, l = tid&31;
    uint32_t skB = smem_u32(SKrow), svB = smem_u32(SVrow);

    float acc[4][2][4];
    #pragma unroll
    for (int mt=0;mt<4;mt++)
        #pragma unroll
        for (int nb=0;nb<2;nb++)
            #pragma unroll
            for (int r=0;r<4;r++) acc[mt][nb][r] = 0.f;

    int nb0 = ch*CHSZ;
    #pragma unroll 1
    for (int c0=0; c0<CHSZ; c0+=32){
        int nbase = nb0 + c0;
        {
            int node = tid >> 3, chk = tid & 7;
            int n = nbase + node;
            uint4 v = make_uint4(0,0,0,0);
            if (n < NN)
                v = *reinterpret_cast<const uint4*>(g_kh + ((size_t)(b*NN+n))*64 + chk*8);
            *reinterpret_cast<uint4*>((char*)SKrow + node*128 + ((chk ^ (node&7))<<4)) = v;
        }
        for (int c = tid; c < 512; c += 256){
            int node = c >> 4, chk = c & 15;
            int n = nbase + node;
            uint4 v = make_uint4(0,0,0,0);
            if (n < NN)
                v = *reinterpret_cast<const uint4*>(g_vh + ((size_t)(b*NN+n))*128 + chk*8);
            *reinterpret_cast<uint4*>((char*)SVrow + node*256 + ((chk ^ (node&7))<<4)) = v;
        }
        __syncthreads();

        #pragma unroll
        for (int ks=0; ks<2; ks++){
            int row = ks*16 + (l&15);
            uint32_t Mv[4];
            {
                int kc = w*2 + (l>>4);
                ldsm_x4(Mv, svB + row*256 + ((kc ^ (row&7))<<4));
            }
            uint32_t B0[2], B1[2];
            B0[0] = movm(Mv[0]); B0[1] = movm(Mv[1]);
            B1[0] = movm(Mv[2]); B1[1] = movm(Mv[3]);

            #pragma unroll
            for (int mt=0; mt<4; mt++){
                uint32_t Mk[4], Afr[4];
                int kc = mt*2 + (l>>4);
                ldsm_x4(Mk, skB + row*128 + ((kc ^ (row&7))<<4));
                Afr[0] = movm(Mk[0]); Afr[1] = movm(Mk[2]);
                Afr[2] = movm(Mk[1]); Afr[3] = movm(Mk[3]);
                mma16816h(acc[mt][0], Afr, B0);
                mma16816h(acc[mt][1], Afr, B1);
            }
        }
        __syncthreads();
    }

    size_t pb = (size_t)(b*CH+ch);
    #pragma unroll
    for (int mt=0;mt<4;mt++){
        #pragma unroll
        for (int nb=0;nb<2;nb++){
            int rf0 = mt*16 + (l>>2);
            int hd = w*16 + nb*8 + 2*(l&3);
            float2 v0 = make_float2(acc[mt][nb][0], acc[mt][nb][1]);
            float2 v1 = make_float2(acc[mt][nb][2], acc[mt][nb][3]);
            *reinterpret_cast<float2*>(&g_part[(pb*64 + rf0    )*128 + hd]) = v0;
            *reinterpret_cast<float2*>(&g_part[(pb*64 + rf0 + 8)*128 + hd]) = v1;
        }
    }
}

/* ---- vred: reduce partials -> transposed fp16 v2xT (x1/16) + ksum --- */
__global__ void vred2_k(){
    int idx = blockIdx.x*256 + threadIdx.x;
    if (idx >= NB*64*136) return;
    int b = idx / (64*136);
    int rem = idx - b*64*136;
    int m = rem / 136;
    int d = rem - m*136;
    float s = 0.f;
    if (d < 128){
        for (int ch=0; ch<CH; ch++)
            s += g_part[((size_t)(b*CH+ch)*64 + m)*128 + d];
    } else if (d == 128){
        for (int ch=0; ch<CH; ch++)
            s += g_kpart[(size_t)(b*CH+ch)*64 + m];
    }
    g_v2xh[((size_t)b*136 + d)*64 + m] = __float2half(s * 0.0625f);
}

/* ---------- attention out via mma + residual + layernorm ------------- */
#define AT_TOT (36864 + 1024)
extern __shared__ char gsm3[];

__global__ void __launch_bounds__(256,1)
attn2_k(const __half* __restrict__ res_h,
        const float* __restrict__ lg, const float* __restrict__ lb)
{
    char* SQ = gsm3;
    char* SV = gsm3 + 8192;
    float* sD = (float*)gsm3;
    float* sg = (float*)(gsm3 + 36864);
    float* sb = sg + 128;

    int b = blockIdx.y;
    int tid = threadIdx.x, w = tid>>5, l = tid&31;
    int nb0 = blockIdx.x*64;

    if (tid < 128) sg[tid] = lg[tid];
    else           sb[tid-128] = lb[tid-128];

    for (int c = tid; c < 512; c += 256){
        int nd = c>>3, ch = c&7;
        int n = nb0 + nd;
        uint4 v = make_uint4(0,0,0,0);
        if (n < NN)
            v = *reinterpret_cast<const uint4*>(g_qh + ((size_t)(b*NN+n))*64 + ch*8);
        *reinterpret_cast<uint4*>(SQ + nd*128 + ((ch ^ (nd&7))<<4)) = v;
    }
    for (int c = tid; c < 1088; c += 256){
        int row = c>>3, ch = c&7;
        uint4 v = *reinterpret_cast<const uint4*>(
            g_v2xh + ((size_t)b*136 + row)*64 + ch*8);
        *reinterpret_cast<uint4*>(SV + row*128 + ((ch ^ (row&7))<<4)) = v;
    }
    __syncthreads();

    uint32_t sqB = smem_u32(SQ), svB = smem_u32(SV);
    int mt = w & 3, nh = w >> 2;
    int nblocks = nh ? 9 : 8;

    uint32_t Af[4][4];
    #pragma unroll
    for (int ks=0; ks<4; ks++){
        int ar = mt*16 + (l&15);
        int kc = ks*2 + (l>>4);
        ldsm_x4(Af[ks], sqB + ar*128 + ((kc ^ (ar&7))<<4));
    }

    float d[9][4];
    #pragma unroll
    for (int nb=0;nb<9;nb++){ d[nb][0]=0.f; d[nb][1]=0.f; d[nb][2]=0.f; d[nb][3]=0.f; }

    #pragma unroll 1
    for (int nb=0; nb<nblocks; nb++){
        int br = nh*64 + nb*8 + (l&7);
        uint32_t Bv[2][4];
        #pragma unroll
        for (int h=0; h<2; h++){
            int kc = h*4 + (l>>3);
            ldsm_x4(Bv[h], svB + br*128 + ((kc ^ (br&7))<<4));
        }
        #pragma unroll
        for (int ks=0; ks<4; ks++)
            mma16816h(d[nb], Af[ks], &Bv[ks>>1][(ks&1)<<1]);
    }
    __syncthreads();

    #pragma unroll 1
    for (int nb=0; nb<nblocks; nb++){
        int col = nh*64 + nb*8 + 2*(l&3);
        int row0 = mt*16 + (l>>2);
        *reinterpret_cast<float2*>(&sD[row0*144 + col])     = make_float2(d[nb][0], d[nb][1]);
        *reinterpret_cast<float2*>(&sD[(row0+8)*144 + col]) = make_float2(d[nb][2], d[nb][3]);
    }
    __syncthreads();

    float4 g4 = ((float4*)sg)[l];
    float4 b4 = ((float4*)sb)[l];
    #pragma unroll 1
    for (int nd=0; nd<8; nd++){
        int ln = w*8 + nd;
        int n = nb0 + ln;
        if (n >= NN) continue;
        size_t i = (size_t)b*NN + n;
        float inv = 1.f / sD[ln*144 + 128];
        float4 acc = *reinterpret_cast<float4*>(&sD[ln*144 + l*4]);
        float4 res;
        {
            uint2 u = *reinterpret_cast<const uint2*>(res_h + i*128 + l*4);
            __half2 p0 = *reinterpret_cast<__half2*>(&u.x);
            __half2 p1 = *reinterpret_cast<__half2*>(&u.y);
            res.x = __low2float(p0); res.y = __high2float(p0);
            res.z = __low2float(p1); res.w = __high2float(p1);
        }
        float4 t;
        t.x = fmaf(acc.x, inv, res.x);
        t.y = fmaf(acc.y, inv, res.y);
        t.z = fmaf(acc.z, inv, res.z);
        t.w = fmaf(acc.w, inv, res.w);
        float mu = warpSum(t.x+t.y+t.z+t.w) * (1.f/128.f);
        float dx=t.x-mu, dy=t.y-mu, dz=t.z-mu, dw=t.w-mu;
        float var = warpSum(dx*dx+dy*dy+dz*dz+dw*dw) * (1.f/128.f);
        float rs = rsqrtf(var + EPSLN);
        float ox = dx*rs*g4.x + b4.x;
        float oy = dy*rs*g4.y + b4.y;
        float oz = dz*rs*g4.z + b4.z;
        float ow = dw*rs*g4.w + b4.w;
        __half2 p0 = __floats2half2_rn(ox, oy);
        __half2 p1 = __floats2half2_rn(oz, ow);
        uint2 u;
        u.x = *reinterpret_cast<uint32_t*>(&p0);
        u.y = *reinterpret_cast<uint32_t*>(&p1);
        *reinterpret_cast<uint2*>(g_hh + i*128 + l*4) = u;
    }
}

/* -------- relu(concat(h0,h)) @ W_reg.T + b_reg, transposed out ------- */
__global__ void final_k(const float* __restrict__ Wreg, const float* __restrict__ breg,
                        float* __restrict__ out)
{
    __shared__ float sWrT[256*12];
    __shared__ float sbr[12];
    int tid = threadIdx.x;
    for (int t=tid; t<3072; t+=256){ int to=t>>8, j=t&255; sWrT[j*12+to] = Wreg[t]; }
    if (tid<12) sbr[tid] = breg[tid];
    __syncthreads();

    int w = tid>>5, l = tid&31;
    int i = blockIdx.x*8 + w;
    int b = i / NN;
    int n = i - b*NN;
    size_t hb = (size_t)i*128;

    float acc[12];
    #pragma unroll
    for (int t=0;t<12;t++) acc[t]=0.f;

    #pragma unroll
    for (int c=0;c<8;c++){
        int j = c*32 + l;
        float vIn = (j < 128) ? __half2float(g_h0h[hb + j])
                              : __half2float(g_hh[hb + (j - 128)]);
        vIn = fmaxf(vIn, 0.f);
        #pragma unroll
        for (int t=0;t<12;t++) acc[t] = fmaf(vIn, sWrT[j*12+t], acc[t]);
    }
    #pragma unroll
    for (int t=0;t<12;t++) acc[t] = warpSum(acc[t]);
    if (l < 12) out[((size_t)b*12 + l)*NN + n] = acc[l] + sbr[l];
}

/* ------------------------------ launch ------------------------------- */
extern "C" void kernel_launch(void* const* d_in, const int* in_sizes, int n_in,
                              void* d_out, int out_size)
{
    const float* x        = (const float*)d_in[0];
    const float* node_emb = (const float*)d_in[1];
    const float* time_emb = (const float*)d_in[2];
    const float* week_emb = (const float*)d_in[3];
    const float* Win      = (const float*)d_in[4];
    const float* bin      = (const float*)d_in[5];
    const float* W1       = (const float*)d_in[6];
    const float* b1       = (const float*)d_in[7];
    const float* W2       = (const float*)d_in[8];
    const float* b2       = (const float*)d_in[9];
    const float* Wreg     = (const float*)d_in[10];
    const float* breg     = (const float*)d_in[11];
    const float* proj     = (const float*)d_in[12];

    cudaFuncSetAttribute(glu3_k, cudaFuncAttributeMaxDynamicSharedMemorySize, G3_TOT);

    __half* g_h0h_ptr; cudaGetSymbolAddress((void**)&g_h0h_ptr, g_h0h);
    __half* g_hh_ptr;  cudaGetSymbolAddress((void**)&g_hh_ptr,  g_hh);

    initmx_k<<<1,32>>>();
    pre_small_k<<<37,256>>>(time_emb, week_emb, W1, b1, W2, b2, proj);
    pre_node_k<<<NN/8,256>>>(node_emb, W1, W2, proj);
    phase1_k<<<NT/32,256>>>(x, node_emb, time_emb, week_emb, Win, bin);
    computek2_k<<<dim3(CH,NB),256>>>();

    for (int layer=0; layer<2; layer++){
        const float* wi = (const float*)d_in[13 + layer*6 + 0];
        const float* bi = (const float*)d_in[13 + layer*6 + 1];
        const float* wo = (const float*)d_in[13 + layer*6 + 2];
        const float* bo = (const float*)d_in[13 + layer*6 + 3];
        const float* lg = (const float*)d_in[13 + layer*6 + 4];
        const float* lb = (const float*)d_in[13 + layer*6 + 5];

        const __half* hin_h = (layer == 0) ? g_h0h_ptr : g_hh_ptr;
        const __half* res_h = (layer == 0) ? g_h0h_ptr : g_hh_ptr;

        glu3_k<<<148,512,G3_TOT>>>(hin_h, wi, bi, wo, bo);
        kvredmma_k<<<dim3(CH,NB),256>>>();
        vred2_k<<<136,256>>>();
        attn2_k<<<dim3((NN+63)/64,NB),256,AT_TOT>>>(res_h, lg, lb);
    }

    final_k<<<NT/8,256>>>(Wreg, breg, (float*)d_out);
}